// round 10
// baseline (speedup 1.0000x reference)
#include <cuda_runtime.h>
#include <cuda_bf16.h>
#include <cuda_fp16.h>
#include <cstdint>

#define PLEN 2048
#define BATCH 2
#define NH 8
#define DH 64
#define DM 512
#define KSPLIT 4

static const size_t PSTRIDE = (size_t)BATCH * PLEN * DM;  // one pv partial buffer

// ---------------------------------------------------------------------------
// Scratch (allocation-free: __device__ globals)
// ---------------------------------------------------------------------------
__device__ __nv_bfloat16 g_qh[BATCH * PLEN * DM];
__device__ __nv_bfloat16 g_ql[BATCH * PLEN * DM];
__device__ __nv_bfloat16 g_kh[BATCH * PLEN * DM];
__device__ __nv_bfloat16 g_kl[BATCH * PLEN * DM];
__device__ float g_v[BATCH * PLEN * DM];
__device__ float g_ohp[KSPLIT * BATCH * PLEN * DM];   // pv split-K partials
__device__ __half g_vth[BATCH * DM * PLEN];           // V^T fp16 hi
__device__ __half g_vtl[BATCH * DM * PLEN];           // V^T fp16 lo
__device__ __nv_bfloat16 g_wqth[DM * DM], g_wqtl[DM * DM];
__device__ __nv_bfloat16 g_wkth[DM * DM], g_wktl[DM * DM];
__device__ __nv_bfloat16 g_wvth[DM * DM], g_wvtl[DM * DM];
__device__ __nv_bfloat16 g_wpth[DM * DM], g_wptl[DM * DM];
__device__ __half g_S[(size_t)BATCH * NH * PLEN * PLEN];      // 134 MB fp16 raw logits
__device__ __half g_Sh[(size_t)BATCH * NH * PLEN * PLEN];     // 134 MB fp16 post-mix attn

// ---------------------------------------------------------------------------
// Warp MMA helpers (plain sm_80+ PTX: assembles for compute_103 non-'a')
// ---------------------------------------------------------------------------
__device__ __forceinline__ uint32_t smem_u32(const void* p) {
    uint32_t a;
    asm("{ .reg .u64 t; cvta.to.shared.u64 t, %1; cvt.u32.u64 %0, t; }" : "=r"(a) : "l"(p));
    return a;
}

#define LDSM4(r, addr)                                                         \
    asm volatile("ldmatrix.sync.aligned.m8n8.x4.shared.b16 {%0,%1,%2,%3}, [%4];" \
                 : "=r"((r)[0]), "=r"((r)[1]), "=r"((r)[2]), "=r"((r)[3])      \
                 : "r"(addr))

#define MMA16816(d, a, b)                                                      \
    asm volatile("mma.sync.aligned.m16n8k16.row.col.f32.bf16.bf16.f32 "        \
                 "{%0,%1,%2,%3}, {%4,%5,%6,%7}, {%8,%9}, {%0,%1,%2,%3};"       \
                 : "+f"((d)[0]), "+f"((d)[1]), "+f"((d)[2]), "+f"((d)[3])      \
                 : "r"((a)[0]), "r"((a)[1]), "r"((a)[2]), "r"((a)[3]),         \
                   "r"((b)[0]), "r"((b)[1]))

#define MMA16816H(d, a, b)                                                     \
    asm volatile("mma.sync.aligned.m16n8k16.row.col.f32.f16.f16.f32 "          \
                 "{%0,%1,%2,%3}, {%4,%5,%6,%7}, {%8,%9}, {%0,%1,%2,%3};"       \
                 : "+f"((d)[0]), "+f"((d)[1]), "+f"((d)[2]), "+f"((d)[3])      \
                 : "r"((a)[0]), "r"((a)[1]), "r"((a)[2]), "r"((a)[3]),         \
                   "r"((b)[0]), "r"((b)[1]))

__device__ __forceinline__ void split_store(float4 v, __nv_bfloat16* hi,
                                            __nv_bfloat16* lo, int off)
{
    __nv_bfloat16 hx = __float2bfloat16_rn(v.x), hy = __float2bfloat16_rn(v.y);
    __nv_bfloat16 hz = __float2bfloat16_rn(v.z), hw = __float2bfloat16_rn(v.w);
    __nv_bfloat162 h01; h01.x = hx; h01.y = hy;
    __nv_bfloat162 h23; h23.x = hz; h23.y = hw;
    __nv_bfloat162 l01, l23;
    l01.x = __float2bfloat16_rn(v.x - __bfloat162float(hx));
    l01.y = __float2bfloat16_rn(v.y - __bfloat162float(hy));
    l23.x = __float2bfloat16_rn(v.z - __bfloat162float(hz));
    l23.y = __float2bfloat16_rn(v.w - __bfloat162float(hw));
    *(__nv_bfloat162*)(hi + off)     = h01;
    *(__nv_bfloat162*)(hi + off + 2) = h23;
    *(__nv_bfloat162*)(lo + off)     = l01;
    *(__nv_bfloat162*)(lo + off + 2) = l23;
}

// ---------------------------------------------------------------------------
// Double-buffered HMMA bf16-split NT GEMM:
//   C[M,N] = alpha * A[M,K] * B[N,K]^T
// APS/BPS: operand comes pre-split as bf16 hi/lo arrays (copy-only smem fill).
// COUT: 0 = fp32 out, 1 = fp16 out, 2 = bf16 hi/lo split out (Cv=hi, Cl2=lo).
// ASUM=4: fp32 A is the elementwise sum of 4 partial buffers (stride apstride).
// ---------------------------------------------------------------------------
#define KC 32
#define SRS 40  // smem row stride in bf16 elements (80 B)

template <int NT, int ASUM, int COUT, int APS, int BPS>
__device__ void hmma_gemm(const float* __restrict__ A,
                          const __nv_bfloat16* __restrict__ Ahg,
                          const __nv_bfloat16* __restrict__ Alg,
                          size_t apstride, int lda,
                          const float* __restrict__ B,
                          const __nv_bfloat16* __restrict__ Bhg,
                          const __nv_bfloat16* __restrict__ Blg,
                          int ldb,
                          void* __restrict__ Cv, void* __restrict__ Cl2, int ldc,
                          int K, float alpha, int m0, int n0)
{
    constexpr int WN = (NT == 128) ? 4 : 2;
    constexpr int WM = 8 / WN;
    constexpr int MT = 128 / WM;
    constexpr int MF = MT / 16;
    constexpr int PB = NT / 32;
    constexpr int AEL = 128 * SRS;
    constexpr int BEL = NT * SRS;
    constexpr int BUFEL = 2 * AEL + 2 * BEL;

    extern __shared__ __nv_bfloat16 sm[];

    const int tid = threadIdx.x;
    const int wid = tid >> 5, lane = tid & 31;
    const int wm = wid / WN, wn = wid % WN;
    const uint32_t ubase = smem_u32(sm);

    const uint32_t aOff = (uint32_t)(wm * MT + (lane & 15)) * (SRS * 2)
                        + (uint32_t)(lane >> 4) * 16;
    const uint32_t bOff = (uint32_t)(wn * 32 + ((lane >> 4) << 3) + (lane & 7)) * (SRS * 2)
                        + (uint32_t)((lane >> 3) & 1) * 16;

    float acc[MF][4][4];
#pragma unroll
    for (int i = 0; i < MF; i++)
#pragma unroll
        for (int j = 0; j < 4; j++)
#pragma unroll
            for (int t = 0; t < 4; t++) acc[i][j][t] = 0.f;

    float4 pa[4], pb[PB];
    uint2 pah[4], pal[4], pbh[PB], pbl[PB];

#define LOAD_AB(k0_)                                                            \
    {                                                                           \
        _Pragma("unroll")                                                       \
        for (int u = 0; u < 4; u++) {                                           \
            int i_ = tid + u * 256;                                             \
            int r_ = i_ >> 3, c4_ = (i_ & 7) << 2;                              \
            size_t idx_ = (size_t)(m0 + r_) * lda + (k0_) + c4_;                \
            if (APS) {                                                          \
                pah[u] = *(const uint2*)(Ahg + idx_);                           \
                pal[u] = *(const uint2*)(Alg + idx_);                           \
            } else {                                                            \
                float4 v_ = *(const float4*)(A + idx_);                         \
                if (ASUM == 4) {                                                \
                    float4 v1_ = *(const float4*)(A + idx_ + apstride);         \
                    float4 v2_ = *(const float4*)(A + idx_ + 2 * apstride);     \
                    float4 v3_ = *(const float4*)(A + idx_ + 3 * apstride);     \
                    v_.x += v1_.x + v2_.x + v3_.x;                              \
                    v_.y += v1_.y + v2_.y + v3_.y;                              \
                    v_.z += v1_.z + v2_.z + v3_.z;                              \
                    v_.w += v1_.w + v2_.w + v3_.w;                              \
                }                                                               \
                pa[u] = v_;                                                     \
            }                                                                   \
        }                                                                       \
        _Pragma("unroll")                                                       \
        for (int u = 0; u < PB; u++) {                                          \
            int i_ = tid + u * 256;                                             \
            int r_ = i_ >> 3, c4_ = (i_ & 7) << 2;                              \
            size_t idx_ = (size_t)(n0 + r_) * ldb + (k0_) + c4_;                \
            if (BPS) {                                                          \
                pbh[u] = *(const uint2*)(Bhg + idx_);                           \
                pbl[u] = *(const uint2*)(Blg + idx_);                           \
            } else {                                                            \
                pb[u] = *(const float4*)(B + idx_);                             \
            }                                                                   \
        }                                                                       \
    }

#define STORE_BUF(bi_)                                                          \
    {                                                                           \
        __nv_bfloat16* Ah_ = sm + (bi_) * BUFEL;                                \
        __nv_bfloat16* Bh_ = Ah_ + AEL;                                         \
        __nv_bfloat16* Al_ = Bh_ + BEL;                                         \
        __nv_bfloat16* Bl_ = Al_ + AEL;                                         \
        _Pragma("unroll")                                                       \
        for (int u = 0; u < 4; u++) {                                           \
            int i_ = tid + u * 256;                                             \
            int r_ = i_ >> 3, c4_ = (i_ & 7) << 2;                              \
            if (APS) {                                                          \
                *(uint2*)(Ah_ + r_ * SRS + c4_) = pah[u];                       \
                *(uint2*)(Al_ + r_ * SRS + c4_) = pal[u];                       \
            } else {                                                            \
                split_store(pa[u], Ah_, Al_, r_ * SRS + c4_);                   \
            }                                                                   \
        }                                                                       \
        _Pragma("unroll")                                                       \
        for (int u = 0; u < PB; u++) {                                          \
            int i_ = tid + u * 256;                                             \
            int r_ = i_ >> 3, c4_ = (i_ & 7) << 2;                              \
            if (BPS) {                                                          \
                *(uint2*)(Bh_ + r_ * SRS + c4_) = pbh[u];                       \
                *(uint2*)(Bl_ + r_ * SRS + c4_) = pbl[u];                       \
            } else {                                                            \
                split_store(pb[u], Bh_, Bl_, r_ * SRS + c4_);                   \
            }                                                                   \
        }                                                                       \
    }

    LOAD_AB(0);
    STORE_BUF(0);
    __syncthreads();

    const int nch = K / KC;
    for (int ch = 0; ch < nch; ch++) {
        if (ch + 1 < nch) LOAD_AB((ch + 1) * KC);

        const uint32_t bb = (uint32_t)((ch & 1) * BUFEL * 2);
        const uint32_t uAh = ubase + bb;
        const uint32_t uBh = uAh + AEL * 2;
        const uint32_t uAl = uBh + BEL * 2;
        const uint32_t uBl = uAl + AEL * 2;

#pragma unroll
        for (int ks = 0; ks < 2; ks++) {
            const uint32_t kb = (uint32_t)(ks * 32);
            uint32_t ah[MF][4], al[MF][4], bh[4][2], bl[4][2];
#pragma unroll
            for (int mf = 0; mf < MF; mf++) {
                uint32_t off = aOff + (uint32_t)(mf * 16) * (SRS * 2) + kb;
                LDSM4(ah[mf], uAh + off);
                LDSM4(al[mf], uAl + off);
            }
#pragma unroll
            for (int g = 0; g < 2; g++) {
                uint32_t off = bOff + (uint32_t)(g * 16) * (SRS * 2) + kb;
                uint32_t th[4], tl[4];
                LDSM4(th, uBh + off);
                LDSM4(tl, uBl + off);
                bh[2 * g][0] = th[0]; bh[2 * g][1] = th[1];
                bh[2 * g + 1][0] = th[2]; bh[2 * g + 1][1] = th[3];
                bl[2 * g][0] = tl[0]; bl[2 * g][1] = tl[1];
                bl[2 * g + 1][0] = tl[2]; bl[2 * g + 1][1] = tl[3];
            }
#pragma unroll
            for (int mf = 0; mf < MF; mf++)
#pragma unroll
                for (int nf = 0; nf < 4; nf++) {
                    MMA16816(acc[mf][nf], ah[mf], bh[nf]);
                    MMA16816(acc[mf][nf], ah[mf], bl[nf]);
                    MMA16816(acc[mf][nf], al[mf], bh[nf]);
                }
        }

        if (ch + 1 < nch) {
            STORE_BUF((ch + 1) & 1);
            __syncthreads();
        }
    }

    // ---- epilogue ----
    const int rbase = m0 + wm * MT + (lane >> 2);
    const int cbase = n0 + wn * 32 + ((lane & 3) << 1);
#pragma unroll
    for (int mf = 0; mf < MF; mf++)
#pragma unroll
        for (int nf = 0; nf < 4; nf++) {
            int r0 = rbase + mf * 16;
            int c = cbase + nf * 8;
            float v0x = acc[mf][nf][0] * alpha, v0y = acc[mf][nf][1] * alpha;
            float v1x = acc[mf][nf][2] * alpha, v1y = acc[mf][nf][3] * alpha;
            if (COUT == 1) {
                __half* Ch = (__half*)Cv;
                __half2 p0, p1;
                p0.x = __float2half_rn(v0x); p0.y = __float2half_rn(v0y);
                p1.x = __float2half_rn(v1x); p1.y = __float2half_rn(v1y);
                *(__half2*)(Ch + (size_t)r0 * ldc + c) = p0;
                *(__half2*)(Ch + (size_t)(r0 + 8) * ldc + c) = p1;
            } else if (COUT == 2) {
                __nv_bfloat16* Ch = (__nv_bfloat16*)Cv;
                __nv_bfloat16* Cl = (__nv_bfloat16*)Cl2;
                __nv_bfloat162 h0, h1, l0, l1;
                h0.x = __float2bfloat16_rn(v0x); h0.y = __float2bfloat16_rn(v0y);
                h1.x = __float2bfloat16_rn(v1x); h1.y = __float2bfloat16_rn(v1y);
                l0.x = __float2bfloat16_rn(v0x - __bfloat162float(h0.x));
                l0.y = __float2bfloat16_rn(v0y - __bfloat162float(h0.y));
                l1.x = __float2bfloat16_rn(v1x - __bfloat162float(h1.x));
                l1.y = __float2bfloat16_rn(v1y - __bfloat162float(h1.y));
                *(__nv_bfloat162*)(Ch + (size_t)r0 * ldc + c) = h0;
                *(__nv_bfloat162*)(Ch + (size_t)(r0 + 8) * ldc + c) = h1;
                *(__nv_bfloat162*)(Cl + (size_t)r0 * ldc + c) = l0;
                *(__nv_bfloat162*)(Cl + (size_t)(r0 + 8) * ldc + c) = l1;
            } else {
                float* C = (float*)Cv;
                float2 w0 = {v0x, v0y};
                float2 w1 = {v1x, v1y};
                *(float2*)(C + (size_t)r0 * ldc + c) = w0;
                *(float2*)(C + (size_t)(r0 + 8) * ldc + c) = w1;
            }
        }
#undef LOAD_AB
#undef STORE_BUF
}

#define SMEM_G128 (2 * (2 * 128 * SRS + 2 * 128 * SRS) * 2)  // 81920 B

// ---------------------------------------------------------------------------
// pv GEMM: A fp16 (direct copy), B fp16 pre-split hi/lo. NT=64, 2-term MMA.
//   C[M,64] = A[M,K](f16) * B[64,K]^T
// ---------------------------------------------------------------------------
__device__ void hmma_gemm_hA(const __half* __restrict__ A, int lda,
                             const __half* __restrict__ Bh_g,
                             const __half* __restrict__ Bl_g, int ldb,
                             float* __restrict__ C, int ldc,
                             int K, int m0)
{
    constexpr int NT = 64, WN = 2, MT = 32, MF = 2;
    constexpr int AEL = 128 * SRS;
    constexpr int BEL = NT * SRS;
    constexpr int BUFEL = AEL + 2 * BEL;

    extern __shared__ __nv_bfloat16 smb[];
    __half* sm = (__half*)smb;

    const int tid = threadIdx.x;
    const int wid = tid >> 5, lane = tid & 31;
    const int wm = wid / WN, wn = wid % WN;
    const uint32_t ubase = smem_u32(sm);

    const uint32_t aOff = (uint32_t)(wm * MT + (lane & 15)) * (SRS * 2)
                        + (uint32_t)(lane >> 4) * 16;
    const uint32_t bOff = (uint32_t)(wn * 32 + ((lane >> 4) << 3) + (lane & 7)) * (SRS * 2)
                        + (uint32_t)((lane >> 3) & 1) * 16;

    float acc[MF][4][4];
#pragma unroll
    for (int i = 0; i < MF; i++)
#pragma unroll
        for (int j = 0; j < 4; j++)
#pragma unroll
            for (int t = 0; t < 4; t++) acc[i][j][t] = 0.f;

    uint2 pa[4], pbh[2], pbl[2];

#define LOAD_AB2(k0_)                                                           \
    {                                                                           \
        _Pragma("unroll")                                                       \
        for (int u = 0; u < 4; u++) {                                           \
            int i_ = tid + u * 256;                                             \
            int r_ = i_ >> 3, c4_ = (i_ & 7) << 2;                              \
            pa[u] = *(const uint2*)(A + (size_t)(m0 + r_) * lda + (k0_) + c4_); \
        }                                                                       \
        _Pragma("unroll")                                                       \
        for (int u = 0; u < 2; u++) {                                           \
            int i_ = tid + u * 256;                                             \
            int r_ = i_ >> 3, c4_ = (i_ & 7) << 2;                              \
            size_t idx_ = (size_t)r_ * ldb + (k0_) + c4_;                       \
            pbh[u] = *(const uint2*)(Bh_g + idx_);                              \
            pbl[u] = *(const uint2*)(Bl_g + idx_);                              \
        }                                                                       \
    }

#define STORE_BUF2(bi_)                                                         \
    {                                                                           \
        __half* Ah_ = sm + (bi_) * BUFEL;                                       \
        __half* Bh_ = Ah_ + AEL;                                                \
        __half* Bl_ = Bh_ + BEL;                                                \
        _Pragma("unroll")                                                       \
        for (int u = 0; u < 4; u++) {                                           \
            int i_ = tid + u * 256;                                             \
            int r_ = i_ >> 3, c4_ = (i_ & 7) << 2;                              \
            *(uint2*)(Ah_ + r_ * SRS + c4_) = pa[u];                            \
        }                                                                       \
        _Pragma("unroll")                                                       \
        for (int u = 0; u < 2; u++) {                                           \
            int i_ = tid + u * 256;                                             \
            int r_ = i_ >> 3, c4_ = (i_ & 7) << 2;                              \
            *(uint2*)(Bh_ + r_ * SRS + c4_) = pbh[u];                           \
            *(uint2*)(Bl_ + r_ * SRS + c4_) = pbl[u];                           \
        }                                                                       \
    }

    LOAD_AB2(0);
    STORE_BUF2(0);
    __syncthreads();

    const int nch = K / KC;
    for (int ch = 0; ch < nch; ch++) {
        if (ch + 1 < nch) LOAD_AB2((ch + 1) * KC);

        const uint32_t bb = (uint32_t)((ch & 1) * BUFEL * 2);
        const uint32_t uAh = ubase + bb;
        const uint32_t uBh = uAh + AEL * 2;
        const uint32_t uBl = uBh + BEL * 2;

#pragma unroll
        for (int ks = 0; ks < 2; ks++) {
            const uint32_t kb = (uint32_t)(ks * 32);
            uint32_t ah[MF][4], bh[4][2], bl[4][2];
#pragma unroll
            for (int mf = 0; mf < MF; mf++) {
                uint32_t off = aOff + (uint32_t)(mf * 16) * (SRS * 2) + kb;
                LDSM4(ah[mf], uAh + off);
            }
#pragma unroll
            for (int g = 0; g < 2; g++) {
                uint32_t off = bOff + (uint32_t)(g * 16) * (SRS * 2) + kb;
                uint32_t th[4], tl[4];
                LDSM4(th, uBh + off);
                LDSM4(tl, uBl + off);
                bh[2 * g][0] = th[0]; bh[2 * g][1] = th[1];
                bh[2 * g + 1][0] = th[2]; bh[2 * g + 1][1] = th[3];
                bl[2 * g][0] = tl[0]; bl[2 * g][1] = tl[1];
                bl[2 * g + 1][0] = tl[2]; bl[2 * g + 1][1] = tl[3];
            }
#pragma unroll
            for (int mf = 0; mf < MF; mf++)
#pragma unroll
                for (int nf = 0; nf < 4; nf++) {
                    MMA16816H(acc[mf][nf], ah[mf], bh[nf]);
                    MMA16816H(acc[mf][nf], ah[mf], bl[nf]);
                }
        }

        if (ch + 1 < nch) {
            STORE_BUF2((ch + 1) & 1);
            __syncthreads();
        }
    }

    const int rbase = m0 + wm * MT + (lane >> 2);
    const int cbase = wn * 32 + ((lane & 3) << 1);
#pragma unroll
    for (int mf = 0; mf < MF; mf++)
#pragma unroll
        for (int nf = 0; nf < 4; nf++) {
            int r0 = rbase + mf * 16;
            int c = cbase + nf * 8;
            float2 v0 = {acc[mf][nf][0], acc[mf][nf][1]};
            float2 v1 = {acc[mf][nf][2], acc[mf][nf][3]};
            *(float2*)(C + (size_t)r0 * ldc + c) = v0;
            *(float2*)(C + (size_t)(r0 + 8) * ldc + c) = v1;
        }
#undef LOAD_AB2
#undef STORE_BUF2
}

#define SMEM_PV (2 * (128 * SRS + 2 * 64 * SRS) * 2)  // 40960 B

// ---------------------------------------------------------------------------
// Transpose + split: dst{h,l}[c, r] = split(src[r, c])
// ---------------------------------------------------------------------------
__global__ __launch_bounds__(256) void k_transpose_split_bf(
    const float* __restrict__ src, __nv_bfloat16* __restrict__ dh,
    __nv_bfloat16* __restrict__ dl, int R, int C)
{
    __shared__ float t[32][33];
    const float* s = src + (size_t)blockIdx.z * R * C;
    __nv_bfloat16* dhp = dh + (size_t)blockIdx.z * R * C;
    __nv_bfloat16* dlp = dl + (size_t)blockIdx.z * R * C;
    int c0 = blockIdx.x * 32, r0 = blockIdx.y * 32;
    for (int dy = threadIdx.y; dy < 32; dy += 8)
        t[dy][threadIdx.x] = s[(size_t)(r0 + dy) * C + c0 + threadIdx.x];
    __syncthreads();
    for (int dy = threadIdx.y; dy < 32; dy += 8) {
        float v = t[threadIdx.x][dy];
        __nv_bfloat16 h = __float2bfloat16_rn(v);
        size_t o = (size_t)(c0 + dy) * R + r0 + threadIdx.x;
        dhp[o] = h;
        dlp[o] = __float2bfloat16_rn(v - __bfloat162float(h));
    }
}

__global__ __launch_bounds__(256) void k_transpose_split_h(
    const float* __restrict__ src, __half* __restrict__ dh,
    __half* __restrict__ dl, int R, int C)
{
    __shared__ float t[32][33];
    const float* s = src + (size_t)blockIdx.z * R * C;
    __half* dhp = dh + (size_t)blockIdx.z * R * C;
    __half* dlp = dl + (size_t)blockIdx.z * R * C;
    int c0 = blockIdx.x * 32, r0 = blockIdx.y * 32;
    for (int dy = threadIdx.y; dy < 32; dy += 8)
        t[dy][threadIdx.x] = s[(size_t)(r0 + dy) * C + c0 + threadIdx.x];
    __syncthreads();
    for (int dy = threadIdx.y; dy < 32; dy += 8) {
        float v = t[threadIdx.x][dy];
        __half h = __float2half_rn(v);
        size_t o = (size_t)(c0 + dy) * R + r0 + threadIdx.x;
        dhp[o] = h;
        dlp[o] = __float2half_rn(v - __half2float(h));
    }
}

// ---------------------------------------------------------------------------
// Stage kernels
// ---------------------------------------------------------------------------
__global__ __launch_bounds__(256) void k_qkv_mma(const float* __restrict__ x)
{
    int which = blockIdx.z;
    int m0 = blockIdx.y * 128, n0 = blockIdx.x * 128;
    if (which == 0) {
        hmma_gemm<128, 1, 2, 0, 1>(x, nullptr, nullptr, 0, DM,
                                   nullptr, g_wqth, g_wqtl, DM,
                                   g_qh, g_ql, DM, DM, 0.125f, m0, n0);
    } else if (which == 1) {
        hmma_gemm<128, 1, 2, 0, 1>(x, nullptr, nullptr, 0, DM,
                                   nullptr, g_wkth, g_wktl, DM,
                                   g_kh, g_kl, DM, DM, 1.0f, m0, n0);
    } else {
        hmma_gemm<128, 1, 0, 0, 1>(x, nullptr, nullptr, 0, DM,
                                   nullptr, g_wvth, g_wvtl, DM,
                                   g_v, nullptr, DM, DM, 1.0f, m0, n0);
    }
}

__global__ __launch_bounds__(256) void k_scores_mma()
{
    int z = blockIdx.z, b = z >> 3, h = z & 7;
    size_t off = (size_t)b * PLEN * DM + h * DH;
    __half* C = g_S + (size_t)z * PLEN * PLEN;
    hmma_gemm<128, 1, 1, 1, 1>(nullptr, g_qh + off, g_ql + off, 0, DM,
                               nullptr, g_kh + off, g_kl + off, DM,
                               C, nullptr, PLEN, DH, 1.0f,
                               blockIdx.y * 128, blockIdx.x * 128);
}

__global__ __launch_bounds__(256) void k_pv_mma()
{
    int kidx = blockIdx.x;
    int z = blockIdx.z, b = z >> 3, g = z & 7;
    const __half* A = g_Sh + (size_t)z * PLEN * PLEN + kidx * (PLEN / KSPLIT);
    size_t boff = (size_t)b * DM * PLEN + (size_t)g * DH * PLEN
                + kidx * (PLEN / KSPLIT);
    float* C = g_ohp + (size_t)kidx * PSTRIDE + (size_t)b * PLEN * DM + g * DH;
    hmma_gemm_hA(A, PLEN, g_vth + boff, g_vtl + boff, PLEN, C, DM,
                 PLEN / KSPLIT, blockIdx.y * 128);
}

__global__ __launch_bounds__(256) void k_proj_mma(float* __restrict__ out)
{
    hmma_gemm<128, 4, 0, 0, 1>(g_ohp, nullptr, nullptr, PSTRIDE, DM,
                               nullptr, g_wpth, g_wptl, DM,
                               out, nullptr, DM, DM, 1.0f,
                               blockIdx.y * 128, blockIdx.x * 128);
}

// ---------------------------------------------------------------------------
// Stage 3: head-mix (W1) -> softmax -> head-mix (W2, /l folded).
// Reads fp16 g_S, writes fp16 g_Sh. 512 thr, 2 warps per head.
// ---------------------------------------------------------------------------
__device__ __forceinline__ float4 ld4h(const __half* p) {
    uint2 u = *(const uint2*)p;
    __half2 a = *(__half2*)&u.x;
    __half2 b = *(__half2*)&u.y;
    float4 r;
    r.x = __half2float(a.x); r.y = __half2float(a.y);
    r.z = __half2float(b.x); r.w = __half2float(b.y);
    return r;
}
__device__ __forceinline__ void st4h(__half* p, float4 v) {
    __half2 a, b;
    a.x = __float2half_rn(v.x); a.y = __float2half_rn(v.y);
    b.x = __float2half_rn(v.z); b.y = __float2half_rn(v.w);
    uint2 u;
    u.x = *(uint32_t*)&a; u.y = *(uint32_t*)&b;
    *(uint2*)p = u;
}

__global__ __launch_bounds__(512) void k_mix_softmax(
    const float* __restrict__ W1, const float* __restrict__ W2)
{
    extern __shared__ float smix[];  // [8][2048]
    __shared__ float w1s[64], w2l[64], redm[16], reds[16];

    const int tid = threadIdx.x;
    const int i = blockIdx.x, b = blockIdx.y;

    if (tid < 64) w1s[tid] = W1[tid];
    __syncthreads();

    const __half* Srow = g_S + (size_t)b * NH * PLEN * PLEN + (size_t)i * PLEN;
    __half* Orow = g_Sh + (size_t)b * NH * PLEN * PLEN + (size_t)i * PLEN;
    const int j4 = tid << 2;

    // ---- mix1 ----
    float4 r[8];
#pragma unroll
    for (int h = 0; h < 8; h++)
        r[h] = ld4h(Srow + (size_t)h * PLEN * PLEN + j4);
#pragma unroll
    for (int g = 0; g < 8; g++) {
        float4 a = {0.f, 0.f, 0.f, 0.f};
#pragma unroll
        for (int h = 0; h < 8; h++) {
            float w = w1s[h * 8 + g];
            a.x += w * r[h].x; a.y += w * r[h].y;
            a.z += w * r[h].z; a.w += w * r[h].w;
        }
        *(float4*)(smix + g * PLEN + j4) = a;
    }
    __syncthreads();

    // ---- softmax: 2 warps per head ----
    const int wid = tid >> 5, lane = tid & 31;
    const int g = wid >> 1;
    const int t64 = ((wid & 1) << 5) + lane;
    float* sg = smix + g * PLEN;

    float m = -1e30f;
#pragma unroll
    for (int k2 = 0; k2 < 32; k2++) m = fmaxf(m, sg[t64 + (k2 << 6)]);
#pragma unroll
    for (int o = 16; o; o >>= 1) m = fmaxf(m, __shfl_xor_sync(0xffffffffu, m, o));
    if (lane == 0) redm[wid] = m;
    __syncthreads();
    m = fmaxf(redm[g << 1], redm[(g << 1) + 1]);

    float l = 0.f;
#pragma unroll
    for (int k2 = 0; k2 < 32; k2++) {
        int idx = t64 + (k2 << 6);
        float e = __expf(sg[idx] - m);
        sg[idx] = e;
        l += e;
    }
#pragma unroll
    for (int o = 16; o; o >>= 1) l += __shfl_xor_sync(0xffffffffu, l, o);
    if (lane == 0) reds[wid] = l;
    __syncthreads();

    if (tid < 64) {
        int h = tid >> 3;
        w2l[tid] = W2[tid] / (reds[h << 1] + reds[(h << 1) + 1]);
    }
    __syncthreads();

    // ---- mix2 -> fp16 out ----
#pragma unroll
    for (int h = 0; h < 8; h++) r[h] = *(const float4*)(smix + h * PLEN + j4);
#pragma unroll
    for (int gp = 0; gp < 8; gp++) {
        float4 a = {0.f, 0.f, 0.f, 0.f};
#pragma unroll
        for (int h = 0; h < 8; h++) {
            float w = w2l[h * 8 + gp];
            a.x += w * r[h].x; a.y += w * r[h].y;
            a.z += w * r[h].z; a.w += w * r[h].w;
        }
        st4h(Orow + (size_t)gp * PLEN * PLEN + j4, a);
    }
}

// ---------------------------------------------------------------------------
extern "C" void kernel_launch(void* const* d_in, const int* in_sizes, int n_in,
                              void* d_out, int out_size)
{
    const float* x     = (const float*)d_in[0];
    const float* Wq    = (const float*)d_in[1];
    const float* Wk    = (const float*)d_in[2];
    const float* Wv    = (const float*)d_in[3];
    const float* W1    = (const float*)d_in[4];
    const float* W2    = (const float*)d_in[5];
    const float* Wproj = (const float*)d_in[6];
    float* out = (float*)d_out;

    cudaFuncSetAttribute(k_mix_softmax, cudaFuncAttributeMaxDynamicSharedMemorySize, 65536);
    cudaFuncSetAttribute(k_qkv_mma,    cudaFuncAttributeMaxDynamicSharedMemorySize, SMEM_G128);
    cudaFuncSetAttribute(k_scores_mma, cudaFuncAttributeMaxDynamicSharedMemorySize, SMEM_G128);
    cudaFuncSetAttribute(k_pv_mma,     cudaFuncAttributeMaxDynamicSharedMemorySize, SMEM_PV);
    cudaFuncSetAttribute(k_proj_mma,   cudaFuncAttributeMaxDynamicSharedMemorySize, SMEM_G128);

    __nv_bfloat16 *wqth, *wqtl, *wkth, *wktl, *wvth, *wvtl, *wpth, *wptl;
    cudaGetSymbolAddress((void**)&wqth, g_wqth); cudaGetSymbolAddress((void**)&wqtl, g_wqtl);
    cudaGetSymbolAddress((void**)&wkth, g_wkth); cudaGetSymbolAddress((void**)&wktl, g_wktl);
    cudaGetSymbolAddress((void**)&wvth, g_wvth); cudaGetSymbolAddress((void**)&wvtl, g_wvtl);
    cudaGetSymbolAddress((void**)&wpth, g_wpth); cudaGetSymbolAddress((void**)&wptl, g_wptl);
    float* vp = nullptr;  cudaGetSymbolAddress((void**)&vp,  g_v);
    __half *vth, *vtl;
    cudaGetSymbolAddress((void**)&vth, g_vth); cudaGetSymbolAddress((void**)&vtl, g_vtl);

    k_transpose_split_bf<<<dim3(16, 16, 1), dim3(32, 8)>>>(Wq, wqth, wqtl, DM, DM);
    k_transpose_split_bf<<<dim3(16, 16, 1), dim3(32, 8)>>>(Wk, wkth, wktl, DM, DM);
    k_transpose_split_bf<<<dim3(16, 16, 1), dim3(32, 8)>>>(Wv, wvth, wvtl, DM, DM);
    k_transpose_split_bf<<<dim3(16, 16, 1), dim3(32, 8)>>>(Wproj, wpth, wptl, DM, DM);

    k_qkv_mma<<<dim3(4, 32, 3), 256, SMEM_G128>>>(x);
    k_transpose_split_h<<<dim3(16, 64, 2), dim3(32, 8)>>>(vp, vth, vtl, PLEN, DM);
    k_scores_mma<<<dim3(16, 16, 16), 256, SMEM_G128>>>();
    k_mix_softmax<<<dim3(2048, 2, 1), 512, 65536>>>(W1, W2);
    k_pv_mma<<<dim3(KSPLIT, 16, 16), 256, SMEM_PV>>>();
    k_proj_mma<<<dim3(4, 32, 1), 256, SMEM_G128>>>(out);
}

// round 11
// speedup vs baseline: 1.0143x; 1.0143x over previous
#include <cuda_runtime.h>
#include <cuda_bf16.h>
#include <cuda_fp16.h>
#include <cstdint>

#define PLEN 2048
#define BATCH 2
#define NH 8
#define DH 64
#define DM 512
#define KSPLIT 4

static const size_t PSTRIDE = (size_t)BATCH * PLEN * DM;  // one pv partial buffer

// ---------------------------------------------------------------------------
// Scratch (allocation-free: __device__ globals)
// ---------------------------------------------------------------------------
__device__ __nv_bfloat16 g_qh[BATCH * PLEN * DM];
__device__ __nv_bfloat16 g_ql[BATCH * PLEN * DM];
__device__ __nv_bfloat16 g_kh[BATCH * PLEN * DM];
__device__ __nv_bfloat16 g_kl[BATCH * PLEN * DM];
__device__ float g_v[BATCH * PLEN * DM];
__device__ float g_ohp[KSPLIT * BATCH * PLEN * DM];   // pv split-K partials
__device__ __half g_vth[BATCH * DM * PLEN];           // V^T fp16 hi
__device__ __half g_vtl[BATCH * DM * PLEN];           // V^T fp16 lo
__device__ __nv_bfloat16 g_wqth[DM * DM], g_wqtl[DM * DM];
__device__ __nv_bfloat16 g_wkth[DM * DM], g_wktl[DM * DM];
__device__ __nv_bfloat16 g_wvth[DM * DM], g_wvtl[DM * DM];
__device__ __nv_bfloat16 g_wpth[DM * DM], g_wptl[DM * DM];
__device__ __half g_S[(size_t)BATCH * NH * PLEN * PLEN];      // 134 MB fp16 raw logits
__device__ __half g_Sh[(size_t)BATCH * NH * PLEN * PLEN];     // 134 MB fp16 post-mix attn

// ---------------------------------------------------------------------------
// Warp MMA helpers (plain sm_80+ PTX: assembles for compute_103 non-'a')
// ---------------------------------------------------------------------------
__device__ __forceinline__ uint32_t smem_u32(const void* p) {
    uint32_t a;
    asm("{ .reg .u64 t; cvta.to.shared.u64 t, %1; cvt.u32.u64 %0, t; }" : "=r"(a) : "l"(p));
    return a;
}

#define LDSM4(r, addr)                                                         \
    asm volatile("ldmatrix.sync.aligned.m8n8.x4.shared.b16 {%0,%1,%2,%3}, [%4];" \
                 : "=r"((r)[0]), "=r"((r)[1]), "=r"((r)[2]), "=r"((r)[3])      \
                 : "r"(addr))

#define MMA16816(d, a, b)                                                      \
    asm volatile("mma.sync.aligned.m16n8k16.row.col.f32.bf16.bf16.f32 "        \
                 "{%0,%1,%2,%3}, {%4,%5,%6,%7}, {%8,%9}, {%0,%1,%2,%3};"       \
                 : "+f"((d)[0]), "+f"((d)[1]), "+f"((d)[2]), "+f"((d)[3])      \
                 : "r"((a)[0]), "r"((a)[1]), "r"((a)[2]), "r"((a)[3]),         \
                   "r"((b)[0]), "r"((b)[1]))

#define MMA16816H(d, a, b)                                                     \
    asm volatile("mma.sync.aligned.m16n8k16.row.col.f32.f16.f16.f32 "          \
                 "{%0,%1,%2,%3}, {%4,%5,%6,%7}, {%8,%9}, {%0,%1,%2,%3};"       \
                 : "+f"((d)[0]), "+f"((d)[1]), "+f"((d)[2]), "+f"((d)[3])      \
                 : "r"((a)[0]), "r"((a)[1]), "r"((a)[2]), "r"((a)[3]),         \
                   "r"((b)[0]), "r"((b)[1]))

__device__ __forceinline__ void split_store(float4 v, __nv_bfloat16* hi,
                                            __nv_bfloat16* lo, int off)
{
    __nv_bfloat16 hx = __float2bfloat16_rn(v.x), hy = __float2bfloat16_rn(v.y);
    __nv_bfloat16 hz = __float2bfloat16_rn(v.z), hw = __float2bfloat16_rn(v.w);
    __nv_bfloat162 h01; h01.x = hx; h01.y = hy;
    __nv_bfloat162 h23; h23.x = hz; h23.y = hw;
    __nv_bfloat162 l01, l23;
    l01.x = __float2bfloat16_rn(v.x - __bfloat162float(hx));
    l01.y = __float2bfloat16_rn(v.y - __bfloat162float(hy));
    l23.x = __float2bfloat16_rn(v.z - __bfloat162float(hz));
    l23.y = __float2bfloat16_rn(v.w - __bfloat162float(hw));
    *(__nv_bfloat162*)(hi + off)     = h01;
    *(__nv_bfloat162*)(hi + off + 2) = h23;
    *(__nv_bfloat162*)(lo + off)     = l01;
    *(__nv_bfloat162*)(lo + off + 2) = l23;
}

// ---------------------------------------------------------------------------
// Double-buffered HMMA bf16-split NT GEMM:
//   C[M,N] = alpha * A[M,K] * B[N,K]^T
// APS/BPS: operand comes pre-split as bf16 hi/lo arrays (copy-only smem fill).
// COUT: 0 = fp32 out, 1 = fp16 out, 2 = bf16 hi/lo split out (Cv=hi, Cl2=lo).
// ASUM=4: fp32 A is the elementwise sum of 4 partial buffers (stride apstride).
// ---------------------------------------------------------------------------
#define KC 32
#define SRS 40  // smem row stride in bf16 elements (80 B)

template <int NT, int ASUM, int COUT, int APS, int BPS>
__device__ void hmma_gemm(const float* __restrict__ A,
                          const __nv_bfloat16* __restrict__ Ahg,
                          const __nv_bfloat16* __restrict__ Alg,
                          size_t apstride, int lda,
                          const float* __restrict__ B,
                          const __nv_bfloat16* __restrict__ Bhg,
                          const __nv_bfloat16* __restrict__ Blg,
                          int ldb,
                          void* __restrict__ Cv, void* __restrict__ Cl2, int ldc,
                          int K, float alpha, int m0, int n0)
{
    constexpr int WN = (NT == 128) ? 4 : 2;
    constexpr int WM = 8 / WN;
    constexpr int MT = 128 / WM;
    constexpr int MF = MT / 16;
    constexpr int PB = NT / 32;
    constexpr int AEL = 128 * SRS;
    constexpr int BEL = NT * SRS;
    constexpr int BUFEL = 2 * AEL + 2 * BEL;

    extern __shared__ __nv_bfloat16 sm[];

    const int tid = threadIdx.x;
    const int wid = tid >> 5, lane = tid & 31;
    const int wm = wid / WN, wn = wid % WN;
    const uint32_t ubase = smem_u32(sm);

    const uint32_t aOff = (uint32_t)(wm * MT + (lane & 15)) * (SRS * 2)
                        + (uint32_t)(lane >> 4) * 16;
    const uint32_t bOff = (uint32_t)(wn * 32 + ((lane >> 4) << 3) + (lane & 7)) * (SRS * 2)
                        + (uint32_t)((lane >> 3) & 1) * 16;

    float acc[MF][4][4];
#pragma unroll
    for (int i = 0; i < MF; i++)
#pragma unroll
        for (int j = 0; j < 4; j++)
#pragma unroll
            for (int t = 0; t < 4; t++) acc[i][j][t] = 0.f;

    float4 pa[4], pb[PB];
    uint2 pah[4], pal[4], pbh[PB], pbl[PB];

#define LOAD_AB(k0_)                                                            \
    {                                                                           \
        _Pragma("unroll")                                                       \
        for (int u = 0; u < 4; u++) {                                           \
            int i_ = tid + u * 256;                                             \
            int r_ = i_ >> 3, c4_ = (i_ & 7) << 2;                              \
            size_t idx_ = (size_t)(m0 + r_) * lda + (k0_) + c4_;                \
            if (APS) {                                                          \
                pah[u] = *(const uint2*)(Ahg + idx_);                           \
                pal[u] = *(const uint2*)(Alg + idx_);                           \
            } else {                                                            \
                float4 v_ = *(const float4*)(A + idx_);                         \
                if (ASUM == 4) {                                                \
                    float4 v1_ = *(const float4*)(A + idx_ + apstride);         \
                    float4 v2_ = *(const float4*)(A + idx_ + 2 * apstride);     \
                    float4 v3_ = *(const float4*)(A + idx_ + 3 * apstride);     \
                    v_.x += v1_.x + v2_.x + v3_.x;                              \
                    v_.y += v1_.y + v2_.y + v3_.y;                              \
                    v_.z += v1_.z + v2_.z + v3_.z;                              \
                    v_.w += v1_.w + v2_.w + v3_.w;                              \
                }                                                               \
                pa[u] = v_;                                                     \
            }                                                                   \
        }                                                                       \
        _Pragma("unroll")                                                       \
        for (int u = 0; u < PB; u++) {                                          \
            int i_ = tid + u * 256;                                             \
            int r_ = i_ >> 3, c4_ = (i_ & 7) << 2;                              \
            size_t idx_ = (size_t)(n0 + r_) * ldb + (k0_) + c4_;                \
            if (BPS) {                                                          \
                pbh[u] = *(const uint2*)(Bhg + idx_);                           \
                pbl[u] = *(const uint2*)(Blg + idx_);                           \
            } else {                                                            \
                pb[u] = *(const float4*)(B + idx_);                             \
            }                                                                   \
        }                                                                       \
    }

#define STORE_BUF(bi_)                                                          \
    {                                                                           \
        __nv_bfloat16* Ah_ = sm + (bi_) * BUFEL;                                \
        __nv_bfloat16* Bh_ = Ah_ + AEL;                                         \
        __nv_bfloat16* Al_ = Bh_ + BEL;                                         \
        __nv_bfloat16* Bl_ = Al_ + AEL;                                         \
        _Pragma("unroll")                                                       \
        for (int u = 0; u < 4; u++) {                                           \
            int i_ = tid + u * 256;                                             \
            int r_ = i_ >> 3, c4_ = (i_ & 7) << 2;                              \
            if (APS) {                                                          \
                *(uint2*)(Ah_ + r_ * SRS + c4_) = pah[u];                       \
                *(uint2*)(Al_ + r_ * SRS + c4_) = pal[u];                       \
            } else {                                                            \
                split_store(pa[u], Ah_, Al_, r_ * SRS + c4_);                   \
            }                                                                   \
        }                                                                       \
        _Pragma("unroll")                                                       \
        for (int u = 0; u < PB; u++) {                                          \
            int i_ = tid + u * 256;                                             \
            int r_ = i_ >> 3, c4_ = (i_ & 7) << 2;                              \
            if (BPS) {                                                          \
                *(uint2*)(Bh_ + r_ * SRS + c4_) = pbh[u];                       \
                *(uint2*)(Bl_ + r_ * SRS + c4_) = pbl[u];                       \
            } else {                                                            \
                split_store(pb[u], Bh_, Bl_, r_ * SRS + c4_);                   \
            }                                                                   \
        }                                                                       \
    }

    LOAD_AB(0);
    STORE_BUF(0);
    __syncthreads();

    const int nch = K / KC;
    for (int ch = 0; ch < nch; ch++) {
        if (ch + 1 < nch) LOAD_AB((ch + 1) * KC);

        const uint32_t bb = (uint32_t)((ch & 1) * BUFEL * 2);
        const uint32_t uAh = ubase + bb;
        const uint32_t uBh = uAh + AEL * 2;
        const uint32_t uAl = uBh + BEL * 2;
        const uint32_t uBl = uAl + AEL * 2;

#pragma unroll
        for (int ks = 0; ks < 2; ks++) {
            const uint32_t kb = (uint32_t)(ks * 32);
            uint32_t ah[MF][4], al[MF][4], bh[4][2], bl[4][2];
#pragma unroll
            for (int mf = 0; mf < MF; mf++) {
                uint32_t off = aOff + (uint32_t)(mf * 16) * (SRS * 2) + kb;
                LDSM4(ah[mf], uAh + off);
                LDSM4(al[mf], uAl + off);
            }
#pragma unroll
            for (int g = 0; g < 2; g++) {
                uint32_t off = bOff + (uint32_t)(g * 16) * (SRS * 2) + kb;
                uint32_t th[4], tl[4];
                LDSM4(th, uBh + off);
                LDSM4(tl, uBl + off);
                bh[2 * g][0] = th[0]; bh[2 * g][1] = th[1];
                bh[2 * g + 1][0] = th[2]; bh[2 * g + 1][1] = th[3];
                bl[2 * g][0] = tl[0]; bl[2 * g][1] = tl[1];
                bl[2 * g + 1][0] = tl[2]; bl[2 * g + 1][1] = tl[3];
            }
#pragma unroll
            for (int mf = 0; mf < MF; mf++)
#pragma unroll
                for (int nf = 0; nf < 4; nf++) {
                    MMA16816(acc[mf][nf], ah[mf], bh[nf]);
                    MMA16816(acc[mf][nf], ah[mf], bl[nf]);
                    MMA16816(acc[mf][nf], al[mf], bh[nf]);
                }
        }

        if (ch + 1 < nch) {
            STORE_BUF((ch + 1) & 1);
            __syncthreads();
        }
    }

    // ---- epilogue ----
    const int rbase = m0 + wm * MT + (lane >> 2);
    const int cbase = n0 + wn * 32 + ((lane & 3) << 1);
#pragma unroll
    for (int mf = 0; mf < MF; mf++)
#pragma unroll
        for (int nf = 0; nf < 4; nf++) {
            int r0 = rbase + mf * 16;
            int c = cbase + nf * 8;
            float v0x = acc[mf][nf][0] * alpha, v0y = acc[mf][nf][1] * alpha;
            float v1x = acc[mf][nf][2] * alpha, v1y = acc[mf][nf][3] * alpha;
            if (COUT == 1) {
                __half* Ch = (__half*)Cv;
                __half2 p0, p1;
                p0.x = __float2half_rn(v0x); p0.y = __float2half_rn(v0y);
                p1.x = __float2half_rn(v1x); p1.y = __float2half_rn(v1y);
                *(__half2*)(Ch + (size_t)r0 * ldc + c) = p0;
                *(__half2*)(Ch + (size_t)(r0 + 8) * ldc + c) = p1;
            } else if (COUT == 2) {
                __nv_bfloat16* Ch = (__nv_bfloat16*)Cv;
                __nv_bfloat16* Cl = (__nv_bfloat16*)Cl2;
                __nv_bfloat162 h0, h1, l0, l1;
                h0.x = __float2bfloat16_rn(v0x); h0.y = __float2bfloat16_rn(v0y);
                h1.x = __float2bfloat16_rn(v1x); h1.y = __float2bfloat16_rn(v1y);
                l0.x = __float2bfloat16_rn(v0x - __bfloat162float(h0.x));
                l0.y = __float2bfloat16_rn(v0y - __bfloat162float(h0.y));
                l1.x = __float2bfloat16_rn(v1x - __bfloat162float(h1.x));
                l1.y = __float2bfloat16_rn(v1y - __bfloat162float(h1.y));
                *(__nv_bfloat162*)(Ch + (size_t)r0 * ldc + c) = h0;
                *(__nv_bfloat162*)(Ch + (size_t)(r0 + 8) * ldc + c) = h1;
                *(__nv_bfloat162*)(Cl + (size_t)r0 * ldc + c) = l0;
                *(__nv_bfloat162*)(Cl + (size_t)(r0 + 8) * ldc + c) = l1;
            } else {
                float* C = (float*)Cv;
                float2 w0 = {v0x, v0y};
                float2 w1 = {v1x, v1y};
                *(float2*)(C + (size_t)r0 * ldc + c) = w0;
                *(float2*)(C + (size_t)(r0 + 8) * ldc + c) = w1;
            }
        }
#undef LOAD_AB
#undef STORE_BUF
}

#define SMEM_G128 (2 * (2 * 128 * SRS + 2 * 128 * SRS) * 2)  // 81920 B

// ---------------------------------------------------------------------------
// pv GEMM: A fp16 (direct copy), B fp16 pre-split hi/lo. NT=64, 2-term MMA.
//   C[M,64] = A[M,K](f16) * B[64,K]^T
// ---------------------------------------------------------------------------
__device__ void hmma_gemm_hA(const __half* __restrict__ A, int lda,
                             const __half* __restrict__ Bh_g,
                             const __half* __restrict__ Bl_g, int ldb,
                             float* __restrict__ C, int ldc,
                             int K, int m0)
{
    constexpr int NT = 64, WN = 2, MT = 32, MF = 2;
    constexpr int AEL = 128 * SRS;
    constexpr int BEL = NT * SRS;
    constexpr int BUFEL = AEL + 2 * BEL;

    extern __shared__ __nv_bfloat16 smb[];
    __half* sm = (__half*)smb;

    const int tid = threadIdx.x;
    const int wid = tid >> 5, lane = tid & 31;
    const int wm = wid / WN, wn = wid % WN;
    const uint32_t ubase = smem_u32(sm);

    const uint32_t aOff = (uint32_t)(wm * MT + (lane & 15)) * (SRS * 2)
                        + (uint32_t)(lane >> 4) * 16;
    const uint32_t bOff = (uint32_t)(wn * 32 + ((lane >> 4) << 3) + (lane & 7)) * (SRS * 2)
                        + (uint32_t)((lane >> 3) & 1) * 16;

    float acc[MF][4][4];
#pragma unroll
    for (int i = 0; i < MF; i++)
#pragma unroll
        for (int j = 0; j < 4; j++)
#pragma unroll
            for (int t = 0; t < 4; t++) acc[i][j][t] = 0.f;

    uint2 pa[4], pbh[2], pbl[2];

#define LOAD_AB2(k0_)                                                           \
    {                                                                           \
        _Pragma("unroll")                                                       \
        for (int u = 0; u < 4; u++) {                                           \
            int i_ = tid + u * 256;                                             \
            int r_ = i_ >> 3, c4_ = (i_ & 7) << 2;                              \
            pa[u] = *(const uint2*)(A + (size_t)(m0 + r_) * lda + (k0_) + c4_); \
        }                                                                       \
        _Pragma("unroll")                                                       \
        for (int u = 0; u < 2; u++) {                                           \
            int i_ = tid + u * 256;                                             \
            int r_ = i_ >> 3, c4_ = (i_ & 7) << 2;                              \
            size_t idx_ = (size_t)r_ * ldb + (k0_) + c4_;                       \
            pbh[u] = *(const uint2*)(Bh_g + idx_);                              \
            pbl[u] = *(const uint2*)(Bl_g + idx_);                              \
        }                                                                       \
    }

#define STORE_BUF2(bi_)                                                         \
    {                                                                           \
        __half* Ah_ = sm + (bi_) * BUFEL;                                       \
        __half* Bh_ = Ah_ + AEL;                                                \
        __half* Bl_ = Bh_ + BEL;                                                \
        _Pragma("unroll")                                                       \
        for (int u = 0; u < 4; u++) {                                           \
            int i_ = tid + u * 256;                                             \
            int r_ = i_ >> 3, c4_ = (i_ & 7) << 2;                              \
            *(uint2*)(Ah_ + r_ * SRS + c4_) = pa[u];                            \
        }                                                                       \
        _Pragma("unroll")                                                       \
        for (int u = 0; u < 2; u++) {                                           \
            int i_ = tid + u * 256;                                             \
            int r_ = i_ >> 3, c4_ = (i_ & 7) << 2;                              \
            *(uint2*)(Bh_ + r_ * SRS + c4_) = pbh[u];                           \
            *(uint2*)(Bl_ + r_ * SRS + c4_) = pbl[u];                           \
        }                                                                       \
    }

    LOAD_AB2(0);
    STORE_BUF2(0);
    __syncthreads();

    const int nch = K / KC;
    for (int ch = 0; ch < nch; ch++) {
        if (ch + 1 < nch) LOAD_AB2((ch + 1) * KC);

        const uint32_t bb = (uint32_t)((ch & 1) * BUFEL * 2);
        const uint32_t uAh = ubase + bb;
        const uint32_t uBh = uAh + AEL * 2;
        const uint32_t uBl = uBh + BEL * 2;

#pragma unroll
        for (int ks = 0; ks < 2; ks++) {
            const uint32_t kb = (uint32_t)(ks * 32);
            uint32_t ah[MF][4], bh[4][2], bl[4][2];
#pragma unroll
            for (int mf = 0; mf < MF; mf++) {
                uint32_t off = aOff + (uint32_t)(mf * 16) * (SRS * 2) + kb;
                LDSM4(ah[mf], uAh + off);
            }
#pragma unroll
            for (int g = 0; g < 2; g++) {
                uint32_t off = bOff + (uint32_t)(g * 16) * (SRS * 2) + kb;
                uint32_t th[4], tl[4];
                LDSM4(th, uBh + off);
                LDSM4(tl, uBl + off);
                bh[2 * g][0] = th[0]; bh[2 * g][1] = th[1];
                bh[2 * g + 1][0] = th[2]; bh[2 * g + 1][1] = th[3];
                bl[2 * g][0] = tl[0]; bl[2 * g][1] = tl[1];
                bl[2 * g + 1][0] = tl[2]; bl[2 * g + 1][1] = tl[3];
            }
#pragma unroll
            for (int mf = 0; mf < MF; mf++)
#pragma unroll
                for (int nf = 0; nf < 4; nf++) {
                    MMA16816H(acc[mf][nf], ah[mf], bh[nf]);
                    MMA16816H(acc[mf][nf], ah[mf], bl[nf]);
                }
        }

        if (ch + 1 < nch) {
            STORE_BUF2((ch + 1) & 1);
            __syncthreads();
        }
    }

    const int rbase = m0 + wm * MT + (lane >> 2);
    const int cbase = wn * 32 + ((lane & 3) << 1);
#pragma unroll
    for (int mf = 0; mf < MF; mf++)
#pragma unroll
        for (int nf = 0; nf < 4; nf++) {
            int r0 = rbase + mf * 16;
            int c = cbase + nf * 8;
            float2 v0 = {acc[mf][nf][0], acc[mf][nf][1]};
            float2 v1 = {acc[mf][nf][2], acc[mf][nf][3]};
            *(float2*)(C + (size_t)r0 * ldc + c) = v0;
            *(float2*)(C + (size_t)(r0 + 8) * ldc + c) = v1;
        }
#undef LOAD_AB2
#undef STORE_BUF2
}

#define SMEM_PV (2 * (128 * SRS + 2 * 64 * SRS) * 2)  // 40960 B

// ---------------------------------------------------------------------------
// Transpose + split: dst{h,l}[c, r] = split(src[r, c])
// ---------------------------------------------------------------------------
__global__ __launch_bounds__(256) void k_transpose_split_bf(
    const float* __restrict__ src, __nv_bfloat16* __restrict__ dh,
    __nv_bfloat16* __restrict__ dl, int R, int C)
{
    __shared__ float t[32][33];
    const float* s = src + (size_t)blockIdx.z * R * C;
    __nv_bfloat16* dhp = dh + (size_t)blockIdx.z * R * C;
    __nv_bfloat16* dlp = dl + (size_t)blockIdx.z * R * C;
    int c0 = blockIdx.x * 32, r0 = blockIdx.y * 32;
    for (int dy = threadIdx.y; dy < 32; dy += 8)
        t[dy][threadIdx.x] = s[(size_t)(r0 + dy) * C + c0 + threadIdx.x];
    __syncthreads();
    for (int dy = threadIdx.y; dy < 32; dy += 8) {
        float v = t[threadIdx.x][dy];
        __nv_bfloat16 h = __float2bfloat16_rn(v);
        size_t o = (size_t)(c0 + dy) * R + r0 + threadIdx.x;
        dhp[o] = h;
        dlp[o] = __float2bfloat16_rn(v - __bfloat162float(h));
    }
}

__global__ __launch_bounds__(256) void k_transpose_split_h(
    const float* __restrict__ src, __half* __restrict__ dh,
    __half* __restrict__ dl, int R, int C)
{
    __shared__ float t[32][33];
    const float* s = src + (size_t)blockIdx.z * R * C;
    __half* dhp = dh + (size_t)blockIdx.z * R * C;
    __half* dlp = dl + (size_t)blockIdx.z * R * C;
    int c0 = blockIdx.x * 32, r0 = blockIdx.y * 32;
    for (int dy = threadIdx.y; dy < 32; dy += 8)
        t[dy][threadIdx.x] = s[(size_t)(r0 + dy) * C + c0 + threadIdx.x];
    __syncthreads();
    for (int dy = threadIdx.y; dy < 32; dy += 8) {
        float v = t[threadIdx.x][dy];
        __half h = __float2half_rn(v);
        size_t o = (size_t)(c0 + dy) * R + r0 + threadIdx.x;
        dhp[o] = h;
        dlp[o] = __float2half_rn(v - __half2float(h));
    }
}

// ---------------------------------------------------------------------------
// Stage kernels
// ---------------------------------------------------------------------------
__global__ __launch_bounds__(256) void k_qkv_mma(const float* __restrict__ x)
{
    int which = blockIdx.z;
    int m0 = blockIdx.y * 128, n0 = blockIdx.x * 128;
    if (which == 0) {
        hmma_gemm<128, 1, 2, 0, 1>(x, nullptr, nullptr, 0, DM,
                                   nullptr, g_wqth, g_wqtl, DM,
                                   g_qh, g_ql, DM, DM, 0.125f, m0, n0);
    } else if (which == 1) {
        hmma_gemm<128, 1, 2, 0, 1>(x, nullptr, nullptr, 0, DM,
                                   nullptr, g_wkth, g_wktl, DM,
                                   g_kh, g_kl, DM, DM, 1.0f, m0, n0);
    } else {
        hmma_gemm<128, 1, 0, 0, 1>(x, nullptr, nullptr, 0, DM,
                                   nullptr, g_wvth, g_wvtl, DM,
                                   g_v, nullptr, DM, DM, 1.0f, m0, n0);
    }
}

__global__ __launch_bounds__(256) void k_scores_mma()
{
    int z = blockIdx.z, b = z >> 3, h = z & 7;
    size_t off = (size_t)b * PLEN * DM + h * DH;
    __half* C = g_S + (size_t)z * PLEN * PLEN;
    hmma_gemm<128, 1, 1, 1, 1>(nullptr, g_qh + off, g_ql + off, 0, DM,
                               nullptr, g_kh + off, g_kl + off, DM,
                               C, nullptr, PLEN, DH, 1.0f,
                               blockIdx.y * 128, blockIdx.x * 128);
}

__global__ __launch_bounds__(256) void k_pv_mma()
{
    int kidx = blockIdx.x;
    int z = blockIdx.z, b = z >> 3, g = z & 7;
    const __half* A = g_Sh + (size_t)z * PLEN * PLEN + kidx * (PLEN / KSPLIT);
    size_t boff = (size_t)b * DM * PLEN + (size_t)g * DH * PLEN
                + kidx * (PLEN / KSPLIT);
    float* C = g_ohp + (size_t)kidx * PSTRIDE + (size_t)b * PLEN * DM + g * DH;
    hmma_gemm_hA(A, PLEN, g_vth + boff, g_vtl + boff, PLEN, C, DM,
                 PLEN / KSPLIT, blockIdx.y * 128);
}

__global__ __launch_bounds__(256) void k_proj_mma(float* __restrict__ out)
{
    hmma_gemm<128, 4, 0, 0, 1>(g_ohp, nullptr, nullptr, PSTRIDE, DM,
                               nullptr, g_wpth, g_wptl, DM,
                               out, nullptr, DM, DM, 1.0f,
                               blockIdx.y * 128, blockIdx.x * 128);
}

// ---------------------------------------------------------------------------
// Stage 3: head-mix (W1) -> softmax -> head-mix (W2, /l folded).
// Fully register-resident: each of 512 threads owns 4 columns x 8 heads.
// No data smem; only tiny reduction scratch. Reads fp16 g_S, writes fp16 g_Sh.
// ---------------------------------------------------------------------------
__device__ __forceinline__ float4 ld4h(const __half* p) {
    uint2 u = *(const uint2*)p;
    __half2 a = *(__half2*)&u.x;
    __half2 b = *(__half2*)&u.y;
    float4 r;
    r.x = __half2float(a.x); r.y = __half2float(a.y);
    r.z = __half2float(b.x); r.w = __half2float(b.y);
    return r;
}
__device__ __forceinline__ void st4h(__half* p, float4 v) {
    __half2 a, b;
    a.x = __float2half_rn(v.x); a.y = __float2half_rn(v.y);
    b.x = __float2half_rn(v.z); b.y = __float2half_rn(v.w);
    uint2 u;
    u.x = *(uint32_t*)&a; u.y = *(uint32_t*)&b;
    *(uint2*)p = u;
}

__global__ __launch_bounds__(512) void k_mix_softmax(
    const float* __restrict__ W1, const float* __restrict__ W2)
{
    __shared__ float w1s[64], w2l[64];
    __shared__ float red[16][8];
    __shared__ float finm[8], finl[8];

    const int tid = threadIdx.x;
    const int wid = tid >> 5, lane = tid & 31;
    const int i = blockIdx.x, b = blockIdx.y;

    if (tid < 64) w1s[tid] = W1[tid];
    __syncthreads();

    const __half* Srow = g_S + (size_t)b * NH * PLEN * PLEN + (size_t)i * PLEN;
    __half* Orow = g_Sh + (size_t)b * NH * PLEN * PLEN + (size_t)i * PLEN;
    const int j4 = tid << 2;

    // ---- mix1 into registers ----
    float4 v[8];
    {
        float4 r[8];
#pragma unroll
        for (int h = 0; h < 8; h++)
            r[h] = ld4h(Srow + (size_t)h * PLEN * PLEN + j4);
#pragma unroll
        for (int g = 0; g < 8; g++) {
            float4 a = {0.f, 0.f, 0.f, 0.f};
#pragma unroll
            for (int h = 0; h < 8; h++) {
                float w = w1s[h * 8 + g];
                a.x += w * r[h].x; a.y += w * r[h].y;
                a.z += w * r[h].z; a.w += w * r[h].w;
            }
            v[g] = a;
        }
    }

    // ---- per-head max: thread-local -> warp shuffle -> 16x8 tile -> final ----
#pragma unroll
    for (int g = 0; g < 8; g++) {
        float m = fmaxf(fmaxf(v[g].x, v[g].y), fmaxf(v[g].z, v[g].w));
#pragma unroll
        for (int o = 16; o; o >>= 1) m = fmaxf(m, __shfl_xor_sync(0xffffffffu, m, o));
        if (lane == 0) red[wid][g] = m;
    }
    __syncthreads();
    if (tid < 8) {
        float m = -1e30f;
#pragma unroll
        for (int w = 0; w < 16; w++) m = fmaxf(m, red[w][tid]);
        finm[tid] = m;
    }
    __syncthreads();

    // ---- exp in registers + per-head sum ----
#pragma unroll
    for (int g = 0; g < 8; g++) {
        float m = finm[g];
        v[g].x = __expf(v[g].x - m);
        v[g].y = __expf(v[g].y - m);
        v[g].z = __expf(v[g].z - m);
        v[g].w = __expf(v[g].w - m);
        float s = (v[g].x + v[g].y) + (v[g].z + v[g].w);
#pragma unroll
        for (int o = 16; o; o >>= 1) s += __shfl_xor_sync(0xffffffffu, s, o);
        if (lane == 0) red[wid][g] = s;  // safe: all reads of red (max) done before this sync path
    }
    __syncthreads();
    if (tid < 8) {
        float s = 0.f;
#pragma unroll
        for (int w = 0; w < 16; w++) s += red[w][tid];
        finl[tid] = s;
    }
    __syncthreads();

    if (tid < 64) w2l[tid] = W2[tid] / finl[tid >> 3];
    __syncthreads();

    // ---- mix2 from registers -> fp16 out ----
#pragma unroll
    for (int gp = 0; gp < 8; gp++) {
        float4 a = {0.f, 0.f, 0.f, 0.f};
#pragma unroll
        for (int h = 0; h < 8; h++) {
            float w = w2l[h * 8 + gp];
            a.x += w * v[h].x; a.y += w * v[h].y;
            a.z += w * v[h].z; a.w += w * v[h].w;
        }
        st4h(Orow + (size_t)gp * PLEN * PLEN + j4, a);
    }
}

// ---------------------------------------------------------------------------
extern "C" void kernel_launch(void* const* d_in, const int* in_sizes, int n_in,
                              void* d_out, int out_size)
{
    const float* x     = (const float*)d_in[0];
    const float* Wq    = (const float*)d_in[1];
    const float* Wk    = (const float*)d_in[2];
    const float* Wv    = (const float*)d_in[3];
    const float* W1    = (const float*)d_in[4];
    const float* W2    = (const float*)d_in[5];
    const float* Wproj = (const float*)d_in[6];
    float* out = (float*)d_out;

    cudaFuncSetAttribute(k_qkv_mma,    cudaFuncAttributeMaxDynamicSharedMemorySize, SMEM_G128);
    cudaFuncSetAttribute(k_scores_mma, cudaFuncAttributeMaxDynamicSharedMemorySize, SMEM_G128);
    cudaFuncSetAttribute(k_pv_mma,     cudaFuncAttributeMaxDynamicSharedMemorySize, SMEM_PV);
    cudaFuncSetAttribute(k_proj_mma,   cudaFuncAttributeMaxDynamicSharedMemorySize, SMEM_G128);

    __nv_bfloat16 *wqth, *wqtl, *wkth, *wktl, *wvth, *wvtl, *wpth, *wptl;
    cudaGetSymbolAddress((void**)&wqth, g_wqth); cudaGetSymbolAddress((void**)&wqtl, g_wqtl);
    cudaGetSymbolAddress((void**)&wkth, g_wkth); cudaGetSymbolAddress((void**)&wktl, g_wktl);
    cudaGetSymbolAddress((void**)&wvth, g_wvth); cudaGetSymbolAddress((void**)&wvtl, g_wvtl);
    cudaGetSymbolAddress((void**)&wpth, g_wpth); cudaGetSymbolAddress((void**)&wptl, g_wptl);
    float* vp = nullptr;  cudaGetSymbolAddress((void**)&vp,  g_v);
    __half *vth, *vtl;
    cudaGetSymbolAddress((void**)&vth, g_vth); cudaGetSymbolAddress((void**)&vtl, g_vtl);

    k_transpose_split_bf<<<dim3(16, 16, 1), dim3(32, 8)>>>(Wq, wqth, wqtl, DM, DM);
    k_transpose_split_bf<<<dim3(16, 16, 1), dim3(32, 8)>>>(Wk, wkth, wktl, DM, DM);
    k_transpose_split_bf<<<dim3(16, 16, 1), dim3(32, 8)>>>(Wv, wvth, wvtl, DM, DM);
    k_transpose_split_bf<<<dim3(16, 16, 1), dim3(32, 8)>>>(Wproj, wpth, wptl, DM, DM);

    k_qkv_mma<<<dim3(4, 32, 3), 256, SMEM_G128>>>(x);
    k_transpose_split_h<<<dim3(16, 64, 2), dim3(32, 8)>>>(vp, vth, vtl, PLEN, DM);
    k_scores_mma<<<dim3(16, 16, 16), 256, SMEM_G128>>>();
    k_mix_softmax<<<dim3(2048, 2, 1), 512>>>(W1, W2);
    k_pv_mma<<<dim3(KSPLIT, 16, 16), 256, SMEM_PV>>>();
    k_proj_mma<<<dim3(4, 32, 1), 256, SMEM_G128>>>(out);
}

// round 12
// speedup vs baseline: 1.0900x; 1.0746x over previous
#include <cuda_runtime.h>
#include <cuda_fp16.h>
#include <cstdint>

#define PLEN 2048
#define BATCH 2
#define NH 8
#define DH 64
#define DM 512
#define KSPLIT 4

static const size_t PSTRIDE = (size_t)BATCH * PLEN * DM;  // one pv partial buffer

// ---------------------------------------------------------------------------
// Scratch (allocation-free: __device__ globals)
// ---------------------------------------------------------------------------
__device__ __half g_qf[BATCH * PLEN * DM];                 // Q fp16 (pre-scaled)
__device__ __half g_kfh[BATCH * PLEN * DM];                // K fp16 hi
__device__ __half g_kfl[BATCH * PLEN * DM];                // K fp16 lo
__device__ float  g_v[BATCH * PLEN * DM];
__device__ float  g_ohp[KSPLIT * BATCH * PLEN * DM];       // pv split-K partials
__device__ __half g_vth[BATCH * DM * PLEN];                // V^T fp16 hi
__device__ __half g_vtl[BATCH * DM * PLEN];                // V^T fp16 lo
__device__ __half g_wqth[DM * DM], g_wqtl[DM * DM];
__device__ __half g_wkth[DM * DM], g_wktl[DM * DM];
__device__ __half g_wvth[DM * DM], g_wvtl[DM * DM];
__device__ __half g_wpth[DM * DM], g_wptl[DM * DM];
__device__ __half g_S[(size_t)BATCH * NH * PLEN * PLEN];   // fp16 raw logits
__device__ __half g_Sh[(size_t)BATCH * NH * PLEN * PLEN];  // fp16 post-mix attn

// ---------------------------------------------------------------------------
// Warp MMA helpers (plain sm_80+ PTX)
// ---------------------------------------------------------------------------
__device__ __forceinline__ uint32_t smem_u32(const void* p) {
    uint32_t a;
    asm("{ .reg .u64 t; cvta.to.shared.u64 t, %1; cvt.u32.u64 %0, t; }" : "=r"(a) : "l"(p));
    return a;
}

#define LDSM4(r, addr)                                                         \
    asm volatile("ldmatrix.sync.aligned.m8n8.x4.shared.b16 {%0,%1,%2,%3}, [%4];" \
                 : "=r"((r)[0]), "=r"((r)[1]), "=r"((r)[2]), "=r"((r)[3])      \
                 : "r"(addr))

#define MMA16816H(d, a, b)                                                     \
    asm volatile("mma.sync.aligned.m16n8k16.row.col.f32.f16.f16.f32 "          \
                 "{%0,%1,%2,%3}, {%4,%5,%6,%7}, {%8,%9}, {%0,%1,%2,%3};"       \
                 : "+f"((d)[0]), "+f"((d)[1]), "+f"((d)[2]), "+f"((d)[3])      \
                 : "r"((a)[0]), "r"((a)[1]), "r"((a)[2]), "r"((a)[3]),         \
                   "r"((b)[0]), "r"((b)[1]))

__device__ __forceinline__ uint2 f4_to_h4(float4 v) {
    __half2 a, b;
    a.x = __float2half_rn(v.x); a.y = __float2half_rn(v.y);
    b.x = __float2half_rn(v.z); b.y = __float2half_rn(v.w);
    uint2 u;
    u.x = *(uint32_t*)&a; u.y = *(uint32_t*)&b;
    return u;
}

// ---------------------------------------------------------------------------
// Unified double-buffered fp16 2-term NT GEMM:
//   C[M,N] = alpha * A[M,K] * B[N,K]^T,   D = Af*Bh + Af*Bl  (fp32 accum)
// A-source (ASRC): 0 = fp32 -> fp16 convert; 1 = fp16 copy;
//                  2 = sum of 4 fp32 partials (stride apstride) -> fp16.
// B: fp16 pre-split hi/lo arrays (copy-only smem fill).
// COUT: 0 = fp32 out, 1 = fp16 out, 3 = fp16 hi/lo split out (Cv=hi, Cl2=lo).
// CTA tile 128 x NT, K-chunk 32, 256 threads (8 warps), 2-stage pipeline.
// ---------------------------------------------------------------------------
#define KC 32
#define SRS 40  // smem row stride in halves (80 B)

template <int NT, int ASRC, int COUT>
__device__ void gemm_f16(const void* __restrict__ Asrc, size_t apstride, int lda,
                         const __half* __restrict__ Bh_g,
                         const __half* __restrict__ Bl_g, int ldb,
                         void* __restrict__ Cv, void* __restrict__ Cl2, int ldc,
                         int K, float alpha, int m0, int n0)
{
    constexpr int WN = (NT == 128) ? 4 : 2;
    constexpr int WM = 8 / WN;
    constexpr int MT = 128 / WM;
    constexpr int MF = MT / 16;
    constexpr int PB = NT / 32;
    constexpr int AEL = 128 * SRS;   // halves
    constexpr int BEL = NT * SRS;
    constexpr int BUFEL = AEL + 2 * BEL;

    extern __shared__ __half sm[];

    const int tid = threadIdx.x;
    const int wid = tid >> 5, lane = tid & 31;
    const int wm = wid / WN, wn = wid % WN;
    const uint32_t ubase = smem_u32(sm);

    const uint32_t aOff = (uint32_t)(wm * MT + (lane & 15)) * (SRS * 2)
                        + (uint32_t)(lane >> 4) * 16;
    const uint32_t bOff = (uint32_t)(wn * 32 + ((lane >> 4) << 3) + (lane & 7)) * (SRS * 2)
                        + (uint32_t)((lane >> 3) & 1) * 16;

    float acc[MF][4][4];
#pragma unroll
    for (int i = 0; i < MF; i++)
#pragma unroll
        for (int j = 0; j < 4; j++)
#pragma unroll
            for (int t = 0; t < 4; t++) acc[i][j][t] = 0.f;

    const float* Af = (const float*)Asrc;
    const __half* Ah16 = (const __half*)Asrc;

    uint2 pa[4], pbh[PB], pbl[PB];

#define LOAD_AB(k0_)                                                            \
    {                                                                           \
        _Pragma("unroll")                                                       \
        for (int u = 0; u < 4; u++) {                                           \
            int i_ = tid + u * 256;                                             \
            int r_ = i_ >> 3, c4_ = (i_ & 7) << 2;                              \
            size_t idx_ = (size_t)(m0 + r_) * lda + (k0_) + c4_;                \
            if (ASRC == 1) {                                                    \
                pa[u] = *(const uint2*)(Ah16 + idx_);                           \
            } else {                                                            \
                float4 v_ = *(const float4*)(Af + idx_);                        \
                if (ASRC == 2) {                                                \
                    float4 v1_ = *(const float4*)(Af + idx_ + apstride);        \
                    float4 v2_ = *(const float4*)(Af + idx_ + 2 * apstride);    \
                    float4 v3_ = *(const float4*)(Af + idx_ + 3 * apstride);    \
                    v_.x += v1_.x + v2_.x + v3_.x;                              \
                    v_.y += v1_.y + v2_.y + v3_.y;                              \
                    v_.z += v1_.z + v2_.z + v3_.z;                              \
                    v_.w += v1_.w + v2_.w + v3_.w;                              \
                }                                                               \
                pa[u] = f4_to_h4(v_);                                           \
            }                                                                   \
        }                                                                       \
        _Pragma("unroll")                                                       \
        for (int u = 0; u < PB; u++) {                                          \
            int i_ = tid + u * 256;                                             \
            int r_ = i_ >> 3, c4_ = (i_ & 7) << 2;                              \
            size_t idx_ = (size_t)(n0 + r_) * ldb + (k0_) + c4_;                \
            pbh[u] = *(const uint2*)(Bh_g + idx_);                              \
            pbl[u] = *(const uint2*)(Bl_g + idx_);                              \
        }                                                                       \
    }

#define STORE_BUF(bi_)                                                          \
    {                                                                           \
        __half* Af_ = sm + (bi_) * BUFEL;                                       \
        __half* Bh_ = Af_ + AEL;                                                \
        __half* Bl_ = Bh_ + BEL;                                                \
        _Pragma("unroll")                                                       \
        for (int u = 0; u < 4; u++) {                                           \
            int i_ = tid + u * 256;                                             \
            int r_ = i_ >> 3, c4_ = (i_ & 7) << 2;                              \
            *(uint2*)(Af_ + r_ * SRS + c4_) = pa[u];                            \
        }                                                                       \
        _Pragma("unroll")                                                       \
        for (int u = 0; u < PB; u++) {                                          \
            int i_ = tid + u * 256;                                             \
            int r_ = i_ >> 3, c4_ = (i_ & 7) << 2;                              \
            *(uint2*)(Bh_ + r_ * SRS + c4_) = pbh[u];                           \
            *(uint2*)(Bl_ + r_ * SRS + c4_) = pbl[u];                           \
        }                                                                       \
    }

    LOAD_AB(0);
    STORE_BUF(0);
    __syncthreads();

    const int nch = K / KC;
    for (int ch = 0; ch < nch; ch++) {
        if (ch + 1 < nch) LOAD_AB((ch + 1) * KC);

        const uint32_t bb = (uint32_t)((ch & 1) * BUFEL * 2);
        const uint32_t uAf = ubase + bb;
        const uint32_t uBh = uAf + AEL * 2;
        const uint32_t uBl = uBh + BEL * 2;

#pragma unroll
        for (int ks = 0; ks < 2; ks++) {
            const uint32_t kb = (uint32_t)(ks * 32);
            uint32_t ah[MF][4], bh[4][2], bl[4][2];
#pragma unroll
            for (int mf = 0; mf < MF; mf++) {
                uint32_t off = aOff + (uint32_t)(mf * 16) * (SRS * 2) + kb;
                LDSM4(ah[mf], uAf + off);
            }
#pragma unroll
            for (int g = 0; g < 2; g++) {
                uint32_t off = bOff + (uint32_t)(g * 16) * (SRS * 2) + kb;
                uint32_t th[4], tl[4];
                LDSM4(th, uBh + off);
                LDSM4(tl, uBl + off);
                bh[2 * g][0] = th[0]; bh[2 * g][1] = th[1];
                bh[2 * g + 1][0] = th[2]; bh[2 * g + 1][1] = th[3];
                bl[2 * g][0] = tl[0]; bl[2 * g][1] = tl[1];
                bl[2 * g + 1][0] = tl[2]; bl[2 * g + 1][1] = tl[3];
            }
#pragma unroll
            for (int mf = 0; mf < MF; mf++)
#pragma unroll
                for (int nf = 0; nf < 4; nf++) {
                    MMA16816H(acc[mf][nf], ah[mf], bh[nf]);
                    MMA16816H(acc[mf][nf], ah[mf], bl[nf]);
                }
        }

        if (ch + 1 < nch) {
            STORE_BUF((ch + 1) & 1);
            __syncthreads();
        }
    }

    // ---- epilogue ----
    const int rbase = m0 + wm * MT + (lane >> 2);
    const int cbase = n0 + wn * 32 + ((lane & 3) << 1);
#pragma unroll
    for (int mf = 0; mf < MF; mf++)
#pragma unroll
        for (int nf = 0; nf < 4; nf++) {
            int r0 = rbase + mf * 16;
            int c = cbase + nf * 8;
            float v0x = acc[mf][nf][0] * alpha, v0y = acc[mf][nf][1] * alpha;
            float v1x = acc[mf][nf][2] * alpha, v1y = acc[mf][nf][3] * alpha;
            if (COUT == 1) {
                __half* Ch = (__half*)Cv;
                __half2 p0, p1;
                p0.x = __float2half_rn(v0x); p0.y = __float2half_rn(v0y);
                p1.x = __float2half_rn(v1x); p1.y = __float2half_rn(v1y);
                *(__half2*)(Ch + (size_t)r0 * ldc + c) = p0;
                *(__half2*)(Ch + (size_t)(r0 + 8) * ldc + c) = p1;
            } else if (COUT == 3) {
                __half* Ch = (__half*)Cv;
                __half* Cl = (__half*)Cl2;
                __half2 h0, h1, l0, l1;
                h0.x = __float2half_rn(v0x); h0.y = __float2half_rn(v0y);
                h1.x = __float2half_rn(v1x); h1.y = __float2half_rn(v1y);
                l0.x = __float2half_rn(v0x - __half2float(h0.x));
                l0.y = __float2half_rn(v0y - __half2float(h0.y));
                l1.x = __float2half_rn(v1x - __half2float(h1.x));
                l1.y = __float2half_rn(v1y - __half2float(h1.y));
                *(__half2*)(Ch + (size_t)r0 * ldc + c) = h0;
                *(__half2*)(Ch + (size_t)(r0 + 8) * ldc + c) = h1;
                *(__half2*)(Cl + (size_t)r0 * ldc + c) = l0;
                *(__half2*)(Cl + (size_t)(r0 + 8) * ldc + c) = l1;
            } else {
                float* C = (float*)Cv;
                float2 w0 = {v0x, v0y};
                float2 w1 = {v1x, v1y};
                *(float2*)(C + (size_t)r0 * ldc + c) = w0;
                *(float2*)(C + (size_t)(r0 + 8) * ldc + c) = w1;
            }
        }
#undef LOAD_AB
#undef STORE_BUF
}

#define SMEM_F128 (2 * (128 * SRS + 2 * 128 * SRS) * 2)  // 61440 B
#define SMEM_F64  (2 * (128 * SRS + 2 * 64 * SRS) * 2)   // 40960 B

// ---------------------------------------------------------------------------
// Merged weight transpose + fp16 split: 4 x (512x512)
// ---------------------------------------------------------------------------
__global__ __launch_bounds__(256) void k_wtrans4(
    const float* __restrict__ Wq, const float* __restrict__ Wk,
    const float* __restrict__ Wv, const float* __restrict__ Wp,
    __half* qh, __half* ql, __half* kh, __half* kl,
    __half* vh, __half* vl, __half* ph, __half* pl)
{
    __shared__ float t[32][33];
    int z = blockIdx.z;
    const float* s = (z == 0) ? Wq : (z == 1) ? Wk : (z == 2) ? Wv : Wp;
    __half* dh = (z == 0) ? qh : (z == 1) ? kh : (z == 2) ? vh : ph;
    __half* dl = (z == 0) ? ql : (z == 1) ? kl : (z == 2) ? vl : pl;
    int c0 = blockIdx.x * 32, r0 = blockIdx.y * 32;
    for (int dy = threadIdx.y; dy < 32; dy += 8)
        t[dy][threadIdx.x] = s[(size_t)(r0 + dy) * DM + c0 + threadIdx.x];
    __syncthreads();
    for (int dy = threadIdx.y; dy < 32; dy += 8) {
        float v = t[threadIdx.x][dy];
        __half h = __float2half_rn(v);
        size_t o = (size_t)(c0 + dy) * DM + r0 + threadIdx.x;
        dh[o] = h;
        dl[o] = __float2half_rn(v - __half2float(h));
    }
}

// V transpose + fp16 split: [b, p, d] -> [b, d, p]
__global__ __launch_bounds__(256) void k_transpose_split_h(
    const float* __restrict__ src, __half* __restrict__ dh,
    __half* __restrict__ dl, int R, int C)
{
    __shared__ float t[32][33];
    const float* s = src + (size_t)blockIdx.z * R * C;
    __half* dhp = dh + (size_t)blockIdx.z * R * C;
    __half* dlp = dl + (size_t)blockIdx.z * R * C;
    int c0 = blockIdx.x * 32, r0 = blockIdx.y * 32;
    for (int dy = threadIdx.y; dy < 32; dy += 8)
        t[dy][threadIdx.x] = s[(size_t)(r0 + dy) * C + c0 + threadIdx.x];
    __syncthreads();
    for (int dy = threadIdx.y; dy < 32; dy += 8) {
        float v = t[threadIdx.x][dy];
        __half h = __float2half_rn(v);
        size_t o = (size_t)(c0 + dy) * R + r0 + threadIdx.x;
        dhp[o] = h;
        dlp[o] = __float2half_rn(v - __half2float(h));
    }
}

// ---------------------------------------------------------------------------
// Stage kernels
// ---------------------------------------------------------------------------
__global__ __launch_bounds__(256) void k_qkv_mma(const float* __restrict__ x)
{
    int which = blockIdx.z;
    int m0 = blockIdx.y * 128, n0 = blockIdx.x * 128;
    if (which == 0) {
        gemm_f16<128, 0, 1>(x, 0, DM, g_wqth, g_wqtl, DM,
                            g_qf, nullptr, DM, DM, 0.125f, m0, n0);
    } else if (which == 1) {
        gemm_f16<128, 0, 3>(x, 0, DM, g_wkth, g_wktl, DM,
                            g_kfh, g_kfl, DM, DM, 1.0f, m0, n0);
    } else {
        gemm_f16<128, 0, 0>(x, 0, DM, g_wvth, g_wvtl, DM,
                            g_v, nullptr, DM, DM, 1.0f, m0, n0);
    }
}

__global__ __launch_bounds__(256) void k_scores_mma()
{
    int z = blockIdx.z, b = z >> 3, h = z & 7;
    size_t off = (size_t)b * PLEN * DM + h * DH;
    __half* C = g_S + (size_t)z * PLEN * PLEN;
    gemm_f16<128, 1, 1>(g_qf + off, 0, DM, g_kfh + off, g_kfl + off, DM,
                        C, nullptr, PLEN, DH, 1.0f,
                        blockIdx.y * 128, blockIdx.x * 128);
}

__global__ __launch_bounds__(256) void k_pv_mma()
{
    int kidx = blockIdx.x;
    int z = blockIdx.z, b = z >> 3, g = z & 7;
    const __half* A = g_Sh + (size_t)z * PLEN * PLEN + kidx * (PLEN / KSPLIT);
    size_t boff = (size_t)b * DM * PLEN + (size_t)g * DH * PLEN
                + kidx * (PLEN / KSPLIT);
    float* C = g_ohp + (size_t)kidx * PSTRIDE + (size_t)b * PLEN * DM + g * DH;
    gemm_f16<64, 1, 0>(A, 0, PLEN, g_vth + boff, g_vtl + boff, PLEN,
                       C, nullptr, DM, PLEN / KSPLIT, 1.0f,
                       blockIdx.y * 128, 0);
}

__global__ __launch_bounds__(256) void k_proj_mma(float* __restrict__ out)
{
    gemm_f16<128, 2, 0>(g_ohp, PSTRIDE, DM, g_wpth, g_wptl, DM,
                        out, nullptr, DM, DM, 1.0f,
                        blockIdx.y * 128, blockIdx.x * 128);
}

// ---------------------------------------------------------------------------
// Stage 3: head-mix (W1) -> softmax -> head-mix (W2, /l folded).
// Register-resident. Reads fp16 g_S, writes fp16 g_Sh. 512 thr.
// ---------------------------------------------------------------------------
__device__ __forceinline__ float4 ld4h(const __half* p) {
    uint2 u = *(const uint2*)p;
    __half2 a = *(__half2*)&u.x;
    __half2 b = *(__half2*)&u.y;
    float4 r;
    r.x = __half2float(a.x); r.y = __half2float(a.y);
    r.z = __half2float(b.x); r.w = __half2float(b.y);
    return r;
}
__device__ __forceinline__ void st4h(__half* p, float4 v) {
    __half2 a, b;
    a.x = __float2half_rn(v.x); a.y = __float2half_rn(v.y);
    b.x = __float2half_rn(v.z); b.y = __float2half_rn(v.w);
    uint2 u;
    u.x = *(uint32_t*)&a; u.y = *(uint32_t*)&b;
    *(uint2*)p = u;
}

__global__ __launch_bounds__(512) void k_mix_softmax(
    const float* __restrict__ W1, const float* __restrict__ W2)
{
    __shared__ float w1s[64], w2l[64];
    __shared__ float red[16][8];
    __shared__ float finm[8], finl[8];

    const int tid = threadIdx.x;
    const int wid = tid >> 5, lane = tid & 31;
    const int i = blockIdx.x, b = blockIdx.y;

    if (tid < 64) w1s[tid] = W1[tid];
    __syncthreads();

    const __half* Srow = g_S + (size_t)b * NH * PLEN * PLEN + (size_t)i * PLEN;
    __half* Orow = g_Sh + (size_t)b * NH * PLEN * PLEN + (size_t)i * PLEN;
    const int j4 = tid << 2;

    float4 v[8];
    {
        float4 r[8];
#pragma unroll
        for (int h = 0; h < 8; h++)
            r[h] = ld4h(Srow + (size_t)h * PLEN * PLEN + j4);
#pragma unroll
        for (int g = 0; g < 8; g++) {
            float4 a = {0.f, 0.f, 0.f, 0.f};
#pragma unroll
            for (int h = 0; h < 8; h++) {
                float w = w1s[h * 8 + g];
                a.x += w * r[h].x; a.y += w * r[h].y;
                a.z += w * r[h].z; a.w += w * r[h].w;
            }
            v[g] = a;
        }
    }

#pragma unroll
    for (int g = 0; g < 8; g++) {
        float m = fmaxf(fmaxf(v[g].x, v[g].y), fmaxf(v[g].z, v[g].w));
#pragma unroll
        for (int o = 16; o; o >>= 1) m = fmaxf(m, __shfl_xor_sync(0xffffffffu, m, o));
        if (lane == 0) red[wid][g] = m;
    }
    __syncthreads();
    if (tid < 8) {
        float m = -1e30f;
#pragma unroll
        for (int w = 0; w < 16; w++) m = fmaxf(m, red[w][tid]);
        finm[tid] = m;
    }
    __syncthreads();

#pragma unroll
    for (int g = 0; g < 8; g++) {
        float m = finm[g];
        v[g].x = __expf(v[g].x - m);
        v[g].y = __expf(v[g].y - m);
        v[g].z = __expf(v[g].z - m);
        v[g].w = __expf(v[g].w - m);
        float s = (v[g].x + v[g].y) + (v[g].z + v[g].w);
#pragma unroll
        for (int o = 16; o; o >>= 1) s += __shfl_xor_sync(0xffffffffu, s, o);
        if (lane == 0) red[wid][g] = s;
    }
    __syncthreads();
    if (tid < 8) {
        float s = 0.f;
#pragma unroll
        for (int w = 0; w < 16; w++) s += red[w][tid];
        finl[tid] = s;
    }
    __syncthreads();

    if (tid < 64) w2l[tid] = W2[tid] / finl[tid >> 3];
    __syncthreads();

#pragma unroll
    for (int gp = 0; gp < 8; gp++) {
        float4 a = {0.f, 0.f, 0.f, 0.f};
#pragma unroll
        for (int h = 0; h < 8; h++) {
            float w = w2l[h * 8 + gp];
            a.x += w * v[h].x; a.y += w * v[h].y;
            a.z += w * v[h].z; a.w += w * v[h].w;
        }
        st4h(Orow + (size_t)gp * PLEN * PLEN + j4, a);
    }
}

// ---------------------------------------------------------------------------
extern "C" void kernel_launch(void* const* d_in, const int* in_sizes, int n_in,
                              void* d_out, int out_size)
{
    const float* x     = (const float*)d_in[0];
    const float* Wq    = (const float*)d_in[1];
    const float* Wk    = (const float*)d_in[2];
    const float* Wv    = (const float*)d_in[3];
    const float* W1    = (const float*)d_in[4];
    const float* W2    = (const float*)d_in[5];
    const float* Wproj = (const float*)d_in[6];
    float* out = (float*)d_out;

    cudaFuncSetAttribute(k_qkv_mma,    cudaFuncAttributeMaxDynamicSharedMemorySize, SMEM_F128);
    cudaFuncSetAttribute(k_scores_mma, cudaFuncAttributeMaxDynamicSharedMemorySize, SMEM_F128);
    cudaFuncSetAttribute(k_pv_mma,     cudaFuncAttributeMaxDynamicSharedMemorySize, SMEM_F64);
    cudaFuncSetAttribute(k_proj_mma,   cudaFuncAttributeMaxDynamicSharedMemorySize, SMEM_F128);

    __half *wqth, *wqtl, *wkth, *wktl, *wvth, *wvtl, *wpth, *wptl;
    cudaGetSymbolAddress((void**)&wqth, g_wqth); cudaGetSymbolAddress((void**)&wqtl, g_wqtl);
    cudaGetSymbolAddress((void**)&wkth, g_wkth); cudaGetSymbolAddress((void**)&wktl, g_wktl);
    cudaGetSymbolAddress((void**)&wvth, g_wvth); cudaGetSymbolAddress((void**)&wvtl, g_wvtl);
    cudaGetSymbolAddress((void**)&wpth, g_wpth); cudaGetSymbolAddress((void**)&wptl, g_wptl);
    float* vp = nullptr;  cudaGetSymbolAddress((void**)&vp,  g_v);
    __half *vth, *vtl;
    cudaGetSymbolAddress((void**)&vth, g_vth); cudaGetSymbolAddress((void**)&vtl, g_vtl);

    k_wtrans4<<<dim3(16, 16, 4), dim3(32, 8)>>>(Wq, Wk, Wv, Wproj,
                                                wqth, wqtl, wkth, wktl,
                                                wvth, wvtl, wpth, wptl);
    k_qkv_mma<<<dim3(4, 32, 3), 256, SMEM_F128>>>(x);
    k_transpose_split_h<<<dim3(16, 64, 2), dim3(32, 8)>>>(vp, vth, vtl, PLEN, DM);
    k_scores_mma<<<dim3(16, 16, 16), 256, SMEM_F128>>>();
    k_mix_softmax<<<dim3(2048, 2, 1), 512>>>(W1, W2);
    k_pv_mma<<<dim3(KSPLIT, 16, 16), 256, SMEM_F64>>>();
    k_proj_mma<<<dim3(4, 32, 1), 256, SMEM_F128>>>(out);
}

// round 13
// speedup vs baseline: 1.1682x; 1.0717x over previous
#include <cuda_runtime.h>
#include <cuda_fp16.h>
#include <cstdint>

#define PLEN 2048
#define BATCH 2
#define NH 8
#define DH 64
#define DM 512
#define KSPLIT 4

static const size_t PSTRIDE = (size_t)BATCH * PLEN * DM;  // one pv partial buffer

// ---------------------------------------------------------------------------
// Scratch (allocation-free: __device__ globals)
// ---------------------------------------------------------------------------
__device__ __half g_qf[BATCH * PLEN * DM];                 // Q fp16 (pre-scaled)
__device__ __half g_kfh[BATCH * PLEN * DM];                // K fp16 hi
__device__ __half g_kfl[BATCH * PLEN * DM];                // K fp16 lo
__device__ float  g_v[BATCH * PLEN * DM];
__device__ float  g_ohp[KSPLIT * BATCH * PLEN * DM];       // pv split-K partials
__device__ __half g_vth[BATCH * DM * PLEN];                // V^T fp16 hi
__device__ __half g_vtl[BATCH * DM * PLEN];                // V^T fp16 lo
__device__ __half g_wqth[DM * DM], g_wqtl[DM * DM];
__device__ __half g_wkth[DM * DM], g_wktl[DM * DM];
__device__ __half g_wvth[DM * DM], g_wvtl[DM * DM];
__device__ __half g_wpth[DM * DM], g_wptl[DM * DM];
__device__ __half g_S[(size_t)BATCH * NH * PLEN * PLEN];   // fp16 raw logits
__device__ __half g_Sh[(size_t)BATCH * NH * PLEN * PLEN];  // fp16 post-mix attn

// ---------------------------------------------------------------------------
// Warp MMA helpers (plain sm_80+ PTX)
// ---------------------------------------------------------------------------
__device__ __forceinline__ uint32_t smem_u32(const void* p) {
    uint32_t a;
    asm("{ .reg .u64 t; cvta.to.shared.u64 t, %1; cvt.u32.u64 %0, t; }" : "=r"(a) : "l"(p));
    return a;
}

#define LDSM4(r, addr)                                                         \
    asm volatile("ldmatrix.sync.aligned.m8n8.x4.shared.b16 {%0,%1,%2,%3}, [%4];" \
                 : "=r"((r)[0]), "=r"((r)[1]), "=r"((r)[2]), "=r"((r)[3])      \
                 : "r"(addr))

#define MMA16816H(d, a, b)                                                     \
    asm volatile("mma.sync.aligned.m16n8k16.row.col.f32.f16.f16.f32 "          \
                 "{%0,%1,%2,%3}, {%4,%5,%6,%7}, {%8,%9}, {%0,%1,%2,%3};"       \
                 : "+f"((d)[0]), "+f"((d)[1]), "+f"((d)[2]), "+f"((d)[3])      \
                 : "r"((a)[0]), "r"((a)[1]), "r"((a)[2]), "r"((a)[3]),         \
                   "r"((b)[0]), "r"((b)[1]))

__device__ __forceinline__ uint2 f4_to_h4(float4 v) {
    __half2 a, b;
    a.x = __float2half_rn(v.x); a.y = __float2half_rn(v.y);
    b.x = __float2half_rn(v.z); b.y = __float2half_rn(v.w);
    uint2 u;
    u.x = *(uint32_t*)&a; u.y = *(uint32_t*)&b;
    return u;
}

// ---------------------------------------------------------------------------
// Unified double-buffered fp16 2-term NT GEMM, CTA tile 128 x 64:
//   C[M,N] = alpha * A[M,K] * B[N,K]^T,   D = Af*Bh + Af*Bl  (fp32 accum)
// 8 warps as 4(m) x 2(n): warp tile 32 x 32, MF=2 -> acc 32 regs.
// A-source (ASRC): 0 = fp32 -> fp16 convert; 1 = fp16 copy;
//                  2 = sum of 4 fp32 partials (stride apstride) -> fp16.
// B: fp16 pre-split hi/lo arrays (copy-only smem fill).
// COUT: 0 = fp32 out, 1 = fp16 out, 3 = fp16 hi/lo split out (Cv=hi, Cl2=lo).
// ---------------------------------------------------------------------------
#define KC 32
#define SRS 40  // smem row stride in halves (80 B)
#define NT 64

template <int ASRC, int COUT>
__device__ void gemm_f16(const void* __restrict__ Asrc, size_t apstride, int lda,
                         const __half* __restrict__ Bh_g,
                         const __half* __restrict__ Bl_g, int ldb,
                         void* __restrict__ Cv, void* __restrict__ Cl2, int ldc,
                         int K, float alpha, int m0, int n0)
{
    constexpr int WN = 2, MT = 32, MF = 2;
    constexpr int PB = NT / 32;      // 2
    constexpr int AEL = 128 * SRS;   // halves
    constexpr int BEL = NT * SRS;
    constexpr int BUFEL = AEL + 2 * BEL;

    extern __shared__ __half sm[];

    const int tid = threadIdx.x;
    const int wid = tid >> 5, lane = tid & 31;
    const int wm = wid / WN, wn = wid % WN;
    const uint32_t ubase = smem_u32(sm);

    const uint32_t aOff = (uint32_t)(wm * MT + (lane & 15)) * (SRS * 2)
                        + (uint32_t)(lane >> 4) * 16;
    const uint32_t bOff = (uint32_t)(wn * 32 + ((lane >> 4) << 3) + (lane & 7)) * (SRS * 2)
                        + (uint32_t)((lane >> 3) & 1) * 16;

    float acc[MF][4][4];
#pragma unroll
    for (int i = 0; i < MF; i++)
#pragma unroll
        for (int j = 0; j < 4; j++)
#pragma unroll
            for (int t = 0; t < 4; t++) acc[i][j][t] = 0.f;

    const float* Af = (const float*)Asrc;
    const __half* Ah16 = (const __half*)Asrc;

    uint2 pa[4], pbh[PB], pbl[PB];

#define LOAD_AB(k0_)                                                            \
    {                                                                           \
        _Pragma("unroll")                                                       \
        for (int u = 0; u < 4; u++) {                                           \
            int i_ = tid + u * 256;                                             \
            int r_ = i_ >> 3, c4_ = (i_ & 7) << 2;                              \
            size_t idx_ = (size_t)(m0 + r_) * lda + (k0_) + c4_;                \
            if (ASRC == 1) {                                                    \
                pa[u] = *(const uint2*)(Ah16 + idx_);                           \
            } else {                                                            \
                float4 v_ = *(const float4*)(Af + idx_);                        \
                if (ASRC == 2) {                                                \
                    float4 v1_ = *(const float4*)(Af + idx_ + apstride);        \
                    float4 v2_ = *(const float4*)(Af + idx_ + 2 * apstride);    \
                    float4 v3_ = *(const float4*)(Af + idx_ + 3 * apstride);    \
                    v_.x += v1_.x + v2_.x + v3_.x;                              \
                    v_.y += v1_.y + v2_.y + v3_.y;                              \
                    v_.z += v1_.z + v2_.z + v3_.z;                              \
                    v_.w += v1_.w + v2_.w + v3_.w;                              \
                }                                                               \
                pa[u] = f4_to_h4(v_);                                           \
            }                                                                   \
        }                                                                       \
        _Pragma("unroll")                                                       \
        for (int u = 0; u < PB; u++) {                                          \
            int i_ = tid + u * 256;                                             \
            int r_ = i_ >> 3, c4_ = (i_ & 7) << 2;                              \
            size_t idx_ = (size_t)(n0 + r_) * ldb + (k0_) + c4_;                \
            pbh[u] = *(const uint2*)(Bh_g + idx_);                              \
            pbl[u] = *(const uint2*)(Bl_g + idx_);                              \
        }                                                                       \
    }

#define STORE_BUF(bi_)                                                          \
    {                                                                           \
        __half* Af_ = sm + (bi_) * BUFEL;                                       \
        __half* Bh_ = Af_ + AEL;                                                \
        __half* Bl_ = Bh_ + BEL;                                                \
        _Pragma("unroll")                                                       \
        for (int u = 0; u < 4; u++) {                                           \
            int i_ = tid + u * 256;                                             \
            int r_ = i_ >> 3, c4_ = (i_ & 7) << 2;                              \
            *(uint2*)(Af_ + r_ * SRS + c4_) = pa[u];                            \
        }                                                                       \
        _Pragma("unroll")                                                       \
        for (int u = 0; u < PB; u++) {                                          \
            int i_ = tid + u * 256;                                             \
            int r_ = i_ >> 3, c4_ = (i_ & 7) << 2;                              \
            *(uint2*)(Bh_ + r_ * SRS + c4_) = pbh[u];                           \
            *(uint2*)(Bl_ + r_ * SRS + c4_) = pbl[u];                           \
        }                                                                       \
    }

    LOAD_AB(0);
    STORE_BUF(0);
    __syncthreads();

    const int nch = K / KC;
    for (int ch = 0; ch < nch; ch++) {
        if (ch + 1 < nch) LOAD_AB((ch + 1) * KC);

        const uint32_t bb = (uint32_t)((ch & 1) * BUFEL * 2);
        const uint32_t uAf = ubase + bb;
        const uint32_t uBh = uAf + AEL * 2;
        const uint32_t uBl = uBh + BEL * 2;

#pragma unroll
        for (int ks = 0; ks < 2; ks++) {
            const uint32_t kb = (uint32_t)(ks * 32);
            uint32_t ah[MF][4], bh[4][2], bl[4][2];
#pragma unroll
            for (int mf = 0; mf < MF; mf++) {
                uint32_t off = aOff + (uint32_t)(mf * 16) * (SRS * 2) + kb;
                LDSM4(ah[mf], uAf + off);
            }
#pragma unroll
            for (int g = 0; g < 2; g++) {
                uint32_t off = bOff + (uint32_t)(g * 16) * (SRS * 2) + kb;
                uint32_t th[4], tl[4];
                LDSM4(th, uBh + off);
                LDSM4(tl, uBl + off);
                bh[2 * g][0] = th[0]; bh[2 * g][1] = th[1];
                bh[2 * g + 1][0] = th[2]; bh[2 * g + 1][1] = th[3];
                bl[2 * g][0] = tl[0]; bl[2 * g][1] = tl[1];
                bl[2 * g + 1][0] = tl[2]; bl[2 * g + 1][1] = tl[3];
            }
#pragma unroll
            for (int mf = 0; mf < MF; mf++)
#pragma unroll
                for (int nf = 0; nf < 4; nf++) {
                    MMA16816H(acc[mf][nf], ah[mf], bh[nf]);
                    MMA16816H(acc[mf][nf], ah[mf], bl[nf]);
                }
        }

        if (ch + 1 < nch) {
            STORE_BUF((ch + 1) & 1);
            __syncthreads();
        }
    }

    // ---- epilogue ----
    const int rbase = m0 + wm * MT + (lane >> 2);
    const int cbase = n0 + wn * 32 + ((lane & 3) << 1);
#pragma unroll
    for (int mf = 0; mf < MF; mf++)
#pragma unroll
        for (int nf = 0; nf < 4; nf++) {
            int r0 = rbase + mf * 16;
            int c = cbase + nf * 8;
            float v0x = acc[mf][nf][0] * alpha, v0y = acc[mf][nf][1] * alpha;
            float v1x = acc[mf][nf][2] * alpha, v1y = acc[mf][nf][3] * alpha;
            if (COUT == 1) {
                __half* Ch = (__half*)Cv;
                __half2 p0, p1;
                p0.x = __float2half_rn(v0x); p0.y = __float2half_rn(v0y);
                p1.x = __float2half_rn(v1x); p1.y = __float2half_rn(v1y);
                *(__half2*)(Ch + (size_t)r0 * ldc + c) = p0;
                *(__half2*)(Ch + (size_t)(r0 + 8) * ldc + c) = p1;
            } else if (COUT == 3) {
                __half* Ch = (__half*)Cv;
                __half* Cl = (__half*)Cl2;
                __half2 h0, h1, l0, l1;
                h0.x = __float2half_rn(v0x); h0.y = __float2half_rn(v0y);
                h1.x = __float2half_rn(v1x); h1.y = __float2half_rn(v1y);
                l0.x = __float2half_rn(v0x - __half2float(h0.x));
                l0.y = __float2half_rn(v0y - __half2float(h0.y));
                l1.x = __float2half_rn(v1x - __half2float(h1.x));
                l1.y = __float2half_rn(v1y - __half2float(h1.y));
                *(__half2*)(Ch + (size_t)r0 * ldc + c) = h0;
                *(__half2*)(Ch + (size_t)(r0 + 8) * ldc + c) = h1;
                *(__half2*)(Cl + (size_t)r0 * ldc + c) = l0;
                *(__half2*)(Cl + (size_t)(r0 + 8) * ldc + c) = l1;
            } else {
                float* C = (float*)Cv;
                float2 w0 = {v0x, v0y};
                float2 w1 = {v1x, v1y};
                *(float2*)(C + (size_t)r0 * ldc + c) = w0;
                *(float2*)(C + (size_t)(r0 + 8) * ldc + c) = w1;
            }
        }
#undef LOAD_AB
#undef STORE_BUF
}

#define SMEM_F64 (2 * (128 * SRS + 2 * 64 * SRS) * 2)   // 40960 B

// ---------------------------------------------------------------------------
// Merged weight transpose + fp16 split: 4 x (512x512)
// ---------------------------------------------------------------------------
__global__ __launch_bounds__(256) void k_wtrans4(
    const float* __restrict__ Wq, const float* __restrict__ Wk,
    const float* __restrict__ Wv, const float* __restrict__ Wp,
    __half* qh, __half* ql, __half* kh, __half* kl,
    __half* vh, __half* vl, __half* ph, __half* pl)
{
    __shared__ float t[32][33];
    int z = blockIdx.z;
    const float* s = (z == 0) ? Wq : (z == 1) ? Wk : (z == 2) ? Wv : Wp;
    __half* dh = (z == 0) ? qh : (z == 1) ? kh : (z == 2) ? vh : ph;
    __half* dl = (z == 0) ? ql : (z == 1) ? kl : (z == 2) ? vl : pl;
    int c0 = blockIdx.x * 32, r0 = blockIdx.y * 32;
    for (int dy = threadIdx.y; dy < 32; dy += 8)
        t[dy][threadIdx.x] = s[(size_t)(r0 + dy) * DM + c0 + threadIdx.x];
    __syncthreads();
    for (int dy = threadIdx.y; dy < 32; dy += 8) {
        float v = t[threadIdx.x][dy];
        __half h = __float2half_rn(v);
        size_t o = (size_t)(c0 + dy) * DM + r0 + threadIdx.x;
        dh[o] = h;
        dl[o] = __float2half_rn(v - __half2float(h));
    }
}

// V transpose + fp16 split: [b, p, d] -> [b, d, p]
__global__ __launch_bounds__(256) void k_transpose_split_h(
    const float* __restrict__ src, __half* __restrict__ dh,
    __half* __restrict__ dl, int R, int C)
{
    __shared__ float t[32][33];
    const float* s = src + (size_t)blockIdx.z * R * C;
    __half* dhp = dh + (size_t)blockIdx.z * R * C;
    __half* dlp = dl + (size_t)blockIdx.z * R * C;
    int c0 = blockIdx.x * 32, r0 = blockIdx.y * 32;
    for (int dy = threadIdx.y; dy < 32; dy += 8)
        t[dy][threadIdx.x] = s[(size_t)(r0 + dy) * C + c0 + threadIdx.x];
    __syncthreads();
    for (int dy = threadIdx.y; dy < 32; dy += 8) {
        float v = t[threadIdx.x][dy];
        __half h = __float2half_rn(v);
        size_t o = (size_t)(c0 + dy) * R + r0 + threadIdx.x;
        dhp[o] = h;
        dlp[o] = __float2half_rn(v - __half2float(h));
    }
}

// ---------------------------------------------------------------------------
// Stage kernels (all 128x64 tiles, >=2 CTAs/SM)
// ---------------------------------------------------------------------------
__global__ __launch_bounds__(256, 2) void k_qkv_mma(const float* __restrict__ x)
{
    int which = blockIdx.z;
    int m0 = blockIdx.y * 128, n0 = blockIdx.x * NT;
    if (which == 0) {
        gemm_f16<0, 1>(x, 0, DM, g_wqth, g_wqtl, DM,
                       g_qf, nullptr, DM, DM, 0.125f, m0, n0);
    } else if (which == 1) {
        gemm_f16<0, 3>(x, 0, DM, g_wkth, g_wktl, DM,
                       g_kfh, g_kfl, DM, DM, 1.0f, m0, n0);
    } else {
        gemm_f16<0, 0>(x, 0, DM, g_wvth, g_wvtl, DM,
                       g_v, nullptr, DM, DM, 1.0f, m0, n0);
    }
}

__global__ __launch_bounds__(256, 2) void k_scores_mma()
{
    int z = blockIdx.z, b = z >> 3, h = z & 7;
    size_t off = (size_t)b * PLEN * DM + h * DH;
    __half* C = g_S + (size_t)z * PLEN * PLEN;
    gemm_f16<1, 1>(g_qf + off, 0, DM, g_kfh + off, g_kfl + off, DM,
                   C, nullptr, PLEN, DH, 1.0f,
                   blockIdx.y * 128, blockIdx.x * NT);
}

__global__ __launch_bounds__(256, 2) void k_pv_mma()
{
    int kidx = blockIdx.x;
    int z = blockIdx.z, b = z >> 3, g = z & 7;
    const __half* A = g_Sh + (size_t)z * PLEN * PLEN + kidx * (PLEN / KSPLIT);
    size_t boff = (size_t)b * DM * PLEN + (size_t)g * DH * PLEN
                + kidx * (PLEN / KSPLIT);
    float* C = g_ohp + (size_t)kidx * PSTRIDE + (size_t)b * PLEN * DM + g * DH;
    gemm_f16<1, 0>(A, 0, PLEN, g_vth + boff, g_vtl + boff, PLEN,
                   C, nullptr, DM, PLEN / KSPLIT, 1.0f,
                   blockIdx.y * 128, 0);
}

__global__ __launch_bounds__(256, 2) void k_proj_mma(float* __restrict__ out)
{
    gemm_f16<2, 0>(g_ohp, PSTRIDE, DM, g_wpth, g_wptl, DM,
                   out, nullptr, DM, DM, 1.0f,
                   blockIdx.y * 128, blockIdx.x * NT);
}

// ---------------------------------------------------------------------------
// Stage 3: head-mix (W1) -> softmax -> head-mix (W2, /l folded).
// Register-resident. Reads fp16 g_S, writes fp16 g_Sh. 512 thr.
// ---------------------------------------------------------------------------
__device__ __forceinline__ float4 ld4h(const __half* p) {
    uint2 u = *(const uint2*)p;
    __half2 a = *(__half2*)&u.x;
    __half2 b = *(__half2*)&u.y;
    float4 r;
    r.x = __half2float(a.x); r.y = __half2float(a.y);
    r.z = __half2float(b.x); r.w = __half2float(b.y);
    return r;
}
__device__ __forceinline__ void st4h(__half* p, float4 v) {
    __half2 a, b;
    a.x = __float2half_rn(v.x); a.y = __float2half_rn(v.y);
    b.x = __float2half_rn(v.z); b.y = __float2half_rn(v.w);
    uint2 u;
    u.x = *(uint32_t*)&a; u.y = *(uint32_t*)&b;
    *(uint2*)p = u;
}

__global__ __launch_bounds__(512) void k_mix_softmax(
    const float* __restrict__ W1, const float* __restrict__ W2)
{
    __shared__ float w1s[64], w2l[64];
    __shared__ float red[16][8];
    __shared__ float finm[8], finl[8];

    const int tid = threadIdx.x;
    const int wid = tid >> 5, lane = tid & 31;
    const int i = blockIdx.x, b = blockIdx.y;

    if (tid < 64) w1s[tid] = W1[tid];
    __syncthreads();

    const __half* Srow = g_S + (size_t)b * NH * PLEN * PLEN + (size_t)i * PLEN;
    __half* Orow = g_Sh + (size_t)b * NH * PLEN * PLEN + (size_t)i * PLEN;
    const int j4 = tid << 2;

    float4 v[8];
    {
        float4 r[8];
#pragma unroll
        for (int h = 0; h < 8; h++)
            r[h] = ld4h(Srow + (size_t)h * PLEN * PLEN + j4);
#pragma unroll
        for (int g = 0; g < 8; g++) {
            float4 a = {0.f, 0.f, 0.f, 0.f};
#pragma unroll
            for (int h = 0; h < 8; h++) {
                float w = w1s[h * 8 + g];
                a.x += w * r[h].x; a.y += w * r[h].y;
                a.z += w * r[h].z; a.w += w * r[h].w;
            }
            v[g] = a;
        }
    }

#pragma unroll
    for (int g = 0; g < 8; g++) {
        float m = fmaxf(fmaxf(v[g].x, v[g].y), fmaxf(v[g].z, v[g].w));
#pragma unroll
        for (int o = 16; o; o >>= 1) m = fmaxf(m, __shfl_xor_sync(0xffffffffu, m, o));
        if (lane == 0) red[wid][g] = m;
    }
    __syncthreads();
    if (tid < 8) {
        float m = -1e30f;
#pragma unroll
        for (int w = 0; w < 16; w++) m = fmaxf(m, red[w][tid]);
        finm[tid] = m;
    }
    __syncthreads();

#pragma unroll
    for (int g = 0; g < 8; g++) {
        float m = finm[g];
        v[g].x = __expf(v[g].x - m);
        v[g].y = __expf(v[g].y - m);
        v[g].z = __expf(v[g].z - m);
        v[g].w = __expf(v[g].w - m);
        float s = (v[g].x + v[g].y) + (v[g].z + v[g].w);
#pragma unroll
        for (int o = 16; o; o >>= 1) s += __shfl_xor_sync(0xffffffffu, s, o);
        if (lane == 0) red[wid][g] = s;
    }
    __syncthreads();
    if (tid < 8) {
        float s = 0.f;
#pragma unroll
        for (int w = 0; w < 16; w++) s += red[w][tid];
        finl[tid] = s;
    }
    __syncthreads();

    if (tid < 64) w2l[tid] = W2[tid] / finl[tid >> 3];
    __syncthreads();

#pragma unroll
    for (int gp = 0; gp < 8; gp++) {
        float4 a = {0.f, 0.f, 0.f, 0.f};
#pragma unroll
        for (int h = 0; h < 8; h++) {
            float w = w2l[h * 8 + gp];
            a.x += w * v[h].x; a.y += w * v[h].y;
            a.z += w * v[h].z; a.w += w * v[h].w;
        }
        st4h(Orow + (size_t)gp * PLEN * PLEN + j4, a);
    }
}

// ---------------------------------------------------------------------------
extern "C" void kernel_launch(void* const* d_in, const int* in_sizes, int n_in,
                              void* d_out, int out_size)
{
    const float* x     = (const float*)d_in[0];
    const float* Wq    = (const float*)d_in[1];
    const float* Wk    = (const float*)d_in[2];
    const float* Wv    = (const float*)d_in[3];
    const float* W1    = (const float*)d_in[4];
    const float* W2    = (const float*)d_in[5];
    const float* Wproj = (const float*)d_in[6];
    float* out = (float*)d_out;

    cudaFuncSetAttribute(k_qkv_mma,    cudaFuncAttributeMaxDynamicSharedMemorySize, SMEM_F64);
    cudaFuncSetAttribute(k_scores_mma, cudaFuncAttributeMaxDynamicSharedMemorySize, SMEM_F64);
    cudaFuncSetAttribute(k_pv_mma,     cudaFuncAttributeMaxDynamicSharedMemorySize, SMEM_F64);
    cudaFuncSetAttribute(k_proj_mma,   cudaFuncAttributeMaxDynamicSharedMemorySize, SMEM_F64);

    __half *wqth, *wqtl, *wkth, *wktl, *wvth, *wvtl, *wpth, *wptl;
    cudaGetSymbolAddress((void**)&wqth, g_wqth); cudaGetSymbolAddress((void**)&wqtl, g_wqtl);
    cudaGetSymbolAddress((void**)&wkth, g_wkth); cudaGetSymbolAddress((void**)&wktl, g_wktl);
    cudaGetSymbolAddress((void**)&wvth, g_wvth); cudaGetSymbolAddress((void**)&wvtl, g_wvtl);
    cudaGetSymbolAddress((void**)&wpth, g_wpth); cudaGetSymbolAddress((void**)&wptl, g_wptl);
    float* vp = nullptr;  cudaGetSymbolAddress((void**)&vp,  g_v);
    __half *vth, *vtl;
    cudaGetSymbolAddress((void**)&vth, g_vth); cudaGetSymbolAddress((void**)&vtl, g_vtl);

    k_wtrans4<<<dim3(16, 16, 4), dim3(32, 8)>>>(Wq, Wk, Wv, Wproj,
                                                wqth, wqtl, wkth, wktl,
                                                wvth, wvtl, wpth, wptl);
    k_qkv_mma<<<dim3(8, 32, 3), 256, SMEM_F64>>>(x);
    k_transpose_split_h<<<dim3(16, 64, 2), dim3(32, 8)>>>(vp, vth, vtl, PLEN, DM);
    k_scores_mma<<<dim3(32, 16, 16), 256, SMEM_F64>>>();
    k_mix_softmax<<<dim3(2048, 2, 1), 512>>>(W1, W2);
    k_pv_mma<<<dim3(KSPLIT, 16, 16), 256, SMEM_F64>>>();
    k_proj_mma<<<dim3(8, 32, 1), 256, SMEM_F64>>>(out);
}

// round 14
// speedup vs baseline: 1.2704x; 1.0875x over previous
#include <cuda_runtime.h>
#include <cuda_fp16.h>
#include <cstdint>

#define PLEN 2048
#define BATCH 2
#define NH 8
#define DH 64
#define DM 512
#define KSPLIT 4

static const size_t PSTRIDE = (size_t)BATCH * PLEN * DM;  // one pv partial buffer

// ---------------------------------------------------------------------------
// Scratch (allocation-free: __device__ globals)
// ---------------------------------------------------------------------------
__device__ __half g_qf[BATCH * PLEN * DM];                 // Q fp16 (pre-scaled)
__device__ __half g_kf[BATCH * PLEN * DM];                 // K fp16 (single)
__device__ float  g_v[BATCH * PLEN * DM];
__device__ float  g_ohp[KSPLIT * BATCH * PLEN * DM];       // pv split-K partials
__device__ __half g_vt[BATCH * DM * PLEN];                 // V^T fp16 (single)
__device__ __half g_wqth[DM * DM], g_wqtl[DM * DM];
__device__ __half g_wkth[DM * DM], g_wktl[DM * DM];
__device__ __half g_wvth[DM * DM], g_wvtl[DM * DM];
__device__ __half g_wpth[DM * DM], g_wptl[DM * DM];
__device__ __half g_S[(size_t)BATCH * NH * PLEN * PLEN];   // fp16 raw logits
__device__ __half g_Sh[(size_t)BATCH * NH * PLEN * PLEN];  // fp16 post-mix attn

// ---------------------------------------------------------------------------
// Warp MMA helpers (plain sm_80+ PTX)
// ---------------------------------------------------------------------------
__device__ __forceinline__ uint32_t smem_u32(const void* p) {
    uint32_t a;
    asm("{ .reg .u64 t; cvta.to.shared.u64 t, %1; cvt.u32.u64 %0, t; }" : "=r"(a) : "l"(p));
    return a;
}

#define LDSM4(r, addr)                                                         \
    asm volatile("ldmatrix.sync.aligned.m8n8.x4.shared.b16 {%0,%1,%2,%3}, [%4];" \
                 : "=r"((r)[0]), "=r"((r)[1]), "=r"((r)[2]), "=r"((r)[3])      \
                 : "r"(addr))

#define MMA16816H(d, a, b)                                                     \
    asm volatile("mma.sync.aligned.m16n8k16.row.col.f32.f16.f16.f32 "          \
                 "{%0,%1,%2,%3}, {%4,%5,%6,%7}, {%8,%9}, {%0,%1,%2,%3};"       \
                 : "+f"((d)[0]), "+f"((d)[1]), "+f"((d)[2]), "+f"((d)[3])      \
                 : "r"((a)[0]), "r"((a)[1]), "r"((a)[2]), "r"((a)[3]),         \
                   "r"((b)[0]), "r"((b)[1]))

__device__ __forceinline__ uint2 f4_to_h4(float4 v) {
    __half2 a, b;
    a.x = __float2half_rn(v.x); a.y = __float2half_rn(v.y);
    b.x = __float2half_rn(v.z); b.y = __float2half_rn(v.w);
    uint2 u;
    u.x = *(uint32_t*)&a; u.y = *(uint32_t*)&b;
    return u;
}

// ---------------------------------------------------------------------------
// Unified double-buffered fp16 NT GEMM, CTA tile 128 x 64:
//   C[M,N] = alpha * A[M,K] * B[N,K]^T   (fp32 accum)
// BT = B terms: 2 -> D = Af*Bh + Af*Bl (hi/lo split); 1 -> D = Af*Bh only.
// A-source (ASRC): 0 = fp32 -> fp16 convert; 1 = fp16 copy;
//                  2 = sum of 4 fp32 partials (stride apstride) -> fp16.
// COUT: 0 = fp32 out, 1 = fp16 out.
// 8 warps as 4(m) x 2(n): warp tile 32 x 32.
// ---------------------------------------------------------------------------
#define KC 32
#define SRS 40  // smem row stride in halves (80 B)
#define NT 64

template <int ASRC, int COUT, int BT>
__device__ void gemm_f16(const void* __restrict__ Asrc, size_t apstride, int lda,
                         const __half* __restrict__ Bh_g,
                         const __half* __restrict__ Bl_g, int ldb,
                         void* __restrict__ Cv, int ldc,
                         int K, float alpha, int m0, int n0)
{
    constexpr int WN = 2, MT = 32, MF = 2;
    constexpr int PB = NT / 32;      // 2
    constexpr int AEL = 128 * SRS;   // halves
    constexpr int BEL = NT * SRS;
    constexpr int BUFEL = AEL + BT * BEL;

    extern __shared__ __half sm[];

    const int tid = threadIdx.x;
    const int wid = tid >> 5, lane = tid & 31;
    const int wm = wid / WN, wn = wid % WN;
    const uint32_t ubase = smem_u32(sm);

    const uint32_t aOff = (uint32_t)(wm * MT + (lane & 15)) * (SRS * 2)
                        + (uint32_t)(lane >> 4) * 16;
    const uint32_t bOff = (uint32_t)(wn * 32 + ((lane >> 4) << 3) + (lane & 7)) * (SRS * 2)
                        + (uint32_t)((lane >> 3) & 1) * 16;

    float acc[MF][4][4];
#pragma unroll
    for (int i = 0; i < MF; i++)
#pragma unroll
        for (int j = 0; j < 4; j++)
#pragma unroll
            for (int t = 0; t < 4; t++) acc[i][j][t] = 0.f;

    const float* Af = (const float*)Asrc;
    const __half* Ah16 = (const __half*)Asrc;

    uint2 pa[4], pbh[PB], pbl[PB];

#define LOAD_AB(k0_)                                                            \
    {                                                                           \
        _Pragma("unroll")                                                       \
        for (int u = 0; u < 4; u++) {                                           \
            int i_ = tid + u * 256;                                             \
            int r_ = i_ >> 3, c4_ = (i_ & 7) << 2;                              \
            size_t idx_ = (size_t)(m0 + r_) * lda + (k0_) + c4_;                \
            if (ASRC == 1) {                                                    \
                pa[u] = *(const uint2*)(Ah16 + idx_);                           \
            } else {                                                            \
                float4 v_ = *(const float4*)(Af + idx_);                        \
                if (ASRC == 2) {                                                \
                    float4 v1_ = *(const float4*)(Af + idx_ + apstride);        \
                    float4 v2_ = *(const float4*)(Af + idx_ + 2 * apstride);    \
                    float4 v3_ = *(const float4*)(Af + idx_ + 3 * apstride);    \
                    v_.x += v1_.x + v2_.x + v3_.x;                              \
                    v_.y += v1_.y + v2_.y + v3_.y;                              \
                    v_.z += v1_.z + v2_.z + v3_.z;                              \
                    v_.w += v1_.w + v2_.w + v3_.w;                              \
                }                                                               \
                pa[u] = f4_to_h4(v_);                                           \
            }                                                                   \
        }                                                                       \
        _Pragma("unroll")                                                       \
        for (int u = 0; u < PB; u++) {                                          \
            int i_ = tid + u * 256;                                             \
            int r_ = i_ >> 3, c4_ = (i_ & 7) << 2;                              \
            size_t idx_ = (size_t)(n0 + r_) * ldb + (k0_) + c4_;                \
            pbh[u] = *(const uint2*)(Bh_g + idx_);                              \
            if (BT == 2) pbl[u] = *(const uint2*)(Bl_g + idx_);                 \
        }                                                                       \
    }

#define STORE_BUF(bi_)                                                          \
    {                                                                           \
        __half* Af_ = sm + (bi_) * BUFEL;                                       \
        __half* Bh_ = Af_ + AEL;                                                \
        __half* Bl_ = Bh_ + BEL;                                                \
        _Pragma("unroll")                                                       \
        for (int u = 0; u < 4; u++) {                                           \
            int i_ = tid + u * 256;                                             \
            int r_ = i_ >> 3, c4_ = (i_ & 7) << 2;                              \
            *(uint2*)(Af_ + r_ * SRS + c4_) = pa[u];                            \
        }                                                                       \
        _Pragma("unroll")                                                       \
        for (int u = 0; u < PB; u++) {                                          \
            int i_ = tid + u * 256;                                             \
            int r_ = i_ >> 3, c4_ = (i_ & 7) << 2;                              \
            *(uint2*)(Bh_ + r_ * SRS + c4_) = pbh[u];                           \
            if (BT == 2) *(uint2*)(Bl_ + r_ * SRS + c4_) = pbl[u];              \
        }                                                                       \
    }

    LOAD_AB(0);
    STORE_BUF(0);
    __syncthreads();

    const int nch = K / KC;
    for (int ch = 0; ch < nch; ch++) {
        if (ch + 1 < nch) LOAD_AB((ch + 1) * KC);

        const uint32_t bb = (uint32_t)((ch & 1) * BUFEL * 2);
        const uint32_t uAf = ubase + bb;
        const uint32_t uBh = uAf + AEL * 2;
        const uint32_t uBl = uBh + BEL * 2;

#pragma unroll
        for (int ks = 0; ks < 2; ks++) {
            const uint32_t kb = (uint32_t)(ks * 32);
            uint32_t ah[MF][4], bh[4][2], bl[4][2];
#pragma unroll
            for (int mf = 0; mf < MF; mf++) {
                uint32_t off = aOff + (uint32_t)(mf * 16) * (SRS * 2) + kb;
                LDSM4(ah[mf], uAf + off);
            }
#pragma unroll
            for (int g = 0; g < 2; g++) {
                uint32_t off = bOff + (uint32_t)(g * 16) * (SRS * 2) + kb;
                uint32_t th[4], tl[4];
                LDSM4(th, uBh + off);
                bh[2 * g][0] = th[0]; bh[2 * g][1] = th[1];
                bh[2 * g + 1][0] = th[2]; bh[2 * g + 1][1] = th[3];
                if (BT == 2) {
                    LDSM4(tl, uBl + off);
                    bl[2 * g][0] = tl[0]; bl[2 * g][1] = tl[1];
                    bl[2 * g + 1][0] = tl[2]; bl[2 * g + 1][1] = tl[3];
                }
            }
#pragma unroll
            for (int mf = 0; mf < MF; mf++)
#pragma unroll
                for (int nf = 0; nf < 4; nf++) {
                    MMA16816H(acc[mf][nf], ah[mf], bh[nf]);
                    if (BT == 2) MMA16816H(acc[mf][nf], ah[mf], bl[nf]);
                }
        }

        if (ch + 1 < nch) {
            STORE_BUF((ch + 1) & 1);
            __syncthreads();
        }
    }

    // ---- epilogue ----
    const int rbase = m0 + wm * MT + (lane >> 2);
    const int cbase = n0 + wn * 32 + ((lane & 3) << 1);
#pragma unroll
    for (int mf = 0; mf < MF; mf++)
#pragma unroll
        for (int nf = 0; nf < 4; nf++) {
            int r0 = rbase + mf * 16;
            int c = cbase + nf * 8;
            float v0x = acc[mf][nf][0] * alpha, v0y = acc[mf][nf][1] * alpha;
            float v1x = acc[mf][nf][2] * alpha, v1y = acc[mf][nf][3] * alpha;
            if (COUT == 1) {
                __half* Ch = (__half*)Cv;
                __half2 p0, p1;
                p0.x = __float2half_rn(v0x); p0.y = __float2half_rn(v0y);
                p1.x = __float2half_rn(v1x); p1.y = __float2half_rn(v1y);
                *(__half2*)(Ch + (size_t)r0 * ldc + c) = p0;
                *(__half2*)(Ch + (size_t)(r0 + 8) * ldc + c) = p1;
            } else {
                float* C = (float*)Cv;
                float2 w0 = {v0x, v0y};
                float2 w1 = {v1x, v1y};
                *(float2*)(C + (size_t)r0 * ldc + c) = w0;
                *(float2*)(C + (size_t)(r0 + 8) * ldc + c) = w1;
            }
        }
#undef LOAD_AB
#undef STORE_BUF
}

#define SMEM_BT2 (2 * (128 * SRS + 2 * 64 * SRS) * 2)   // 40960 B
#define SMEM_BT1 (2 * (128 * SRS + 1 * 64 * SRS) * 2)   // 30720 B

// ---------------------------------------------------------------------------
// Merged weight transpose + fp16 split: 4 x (512x512)
// ---------------------------------------------------------------------------
__global__ __launch_bounds__(256) void k_wtrans4(
    const float* __restrict__ Wq, const float* __restrict__ Wk,
    const float* __restrict__ Wv, const float* __restrict__ Wp,
    __half* qh, __half* ql, __half* kh, __half* kl,
    __half* vh, __half* vl, __half* ph, __half* pl)
{
    __shared__ float t[32][33];
    int z = blockIdx.z;
    const float* s = (z == 0) ? Wq : (z == 1) ? Wk : (z == 2) ? Wv : Wp;
    __half* dh = (z == 0) ? qh : (z == 1) ? kh : (z == 2) ? vh : ph;
    __half* dl = (z == 0) ? ql : (z == 1) ? kl : (z == 2) ? vl : pl;
    int c0 = blockIdx.x * 32, r0 = blockIdx.y * 32;
    for (int dy = threadIdx.y; dy < 32; dy += 8)
        t[dy][threadIdx.x] = s[(size_t)(r0 + dy) * DM + c0 + threadIdx.x];
    __syncthreads();
    for (int dy = threadIdx.y; dy < 32; dy += 8) {
        float v = t[threadIdx.x][dy];
        __half h = __float2half_rn(v);
        size_t o = (size_t)(c0 + dy) * DM + r0 + threadIdx.x;
        dh[o] = h;
        dl[o] = __float2half_rn(v - __half2float(h));
    }
}

// V transpose (single fp16): [b, p, d] -> [b, d, p]
__global__ __launch_bounds__(256) void k_transpose_h(
    const float* __restrict__ src, __half* __restrict__ dst, int R, int C)
{
    __shared__ float t[32][33];
    const float* s = src + (size_t)blockIdx.z * R * C;
    __half* d = dst + (size_t)blockIdx.z * R * C;
    int c0 = blockIdx.x * 32, r0 = blockIdx.y * 32;
    for (int dy = threadIdx.y; dy < 32; dy += 8)
        t[dy][threadIdx.x] = s[(size_t)(r0 + dy) * C + c0 + threadIdx.x];
    __syncthreads();
    for (int dy = threadIdx.y; dy < 32; dy += 8)
        d[(size_t)(c0 + dy) * R + r0 + threadIdx.x] =
            __float2half_rn(t[threadIdx.x][dy]);
}

// ---------------------------------------------------------------------------
// Stage kernels
// ---------------------------------------------------------------------------
__global__ __launch_bounds__(256, 2) void k_qkv_mma(const float* __restrict__ x)
{
    int which = blockIdx.z;
    int m0 = blockIdx.y * 128, n0 = blockIdx.x * NT;
    if (which == 0) {
        gemm_f16<0, 1, 2>(x, 0, DM, g_wqth, g_wqtl, DM,
                          g_qf, DM, DM, 0.125f, m0, n0);
    } else if (which == 1) {
        gemm_f16<0, 1, 2>(x, 0, DM, g_wkth, g_wktl, DM,
                          g_kf, DM, DM, 1.0f, m0, n0);
    } else {
        gemm_f16<0, 0, 2>(x, 0, DM, g_wvth, g_wvtl, DM,
                          g_v, DM, DM, 1.0f, m0, n0);
    }
}

__global__ __launch_bounds__(256, 2) void k_scores_mma()
{
    int z = blockIdx.z, b = z >> 3, h = z & 7;
    size_t off = (size_t)b * PLEN * DM + h * DH;
    __half* C = g_S + (size_t)z * PLEN * PLEN;
    gemm_f16<1, 1, 1>(g_qf + off, 0, DM, g_kf + off, nullptr, DM,
                      C, PLEN, DH, 1.0f,
                      blockIdx.y * 128, blockIdx.x * NT);
}

__global__ __launch_bounds__(256, 2) void k_pv_mma()
{
    int kidx = blockIdx.x;
    int z = blockIdx.z, b = z >> 3, g = z & 7;
    const __half* A = g_Sh + (size_t)z * PLEN * PLEN + kidx * (PLEN / KSPLIT);
    size_t boff = (size_t)b * DM * PLEN + (size_t)g * DH * PLEN
                + kidx * (PLEN / KSPLIT);
    float* C = g_ohp + (size_t)kidx * PSTRIDE + (size_t)b * PLEN * DM + g * DH;
    gemm_f16<1, 0, 1>(A, 0, PLEN, g_vt + boff, nullptr, PLEN,
                      C, DM, PLEN / KSPLIT, 1.0f,
                      blockIdx.y * 128, 0);
}

__global__ __launch_bounds__(256, 2) void k_proj_mma(float* __restrict__ out)
{
    gemm_f16<2, 0, 2>(g_ohp, PSTRIDE, DM, g_wpth, g_wptl, DM,
                      out, DM, DM, 1.0f,
                      blockIdx.y * 128, blockIdx.x * NT);
}

// ---------------------------------------------------------------------------
// Stage 3: head-mix (W1) -> softmax -> head-mix (W2, /l folded).
// Register-resident. Reads fp16 g_S, writes fp16 g_Sh. 512 thr.
// ---------------------------------------------------------------------------
__device__ __forceinline__ float4 ld4h(const __half* p) {
    uint2 u = *(const uint2*)p;
    __half2 a = *(__half2*)&u.x;
    __half2 b = *(__half2*)&u.y;
    float4 r;
    r.x = __half2float(a.x); r.y = __half2float(a.y);
    r.z = __half2float(b.x); r.w = __half2float(b.y);
    return r;
}
__device__ __forceinline__ void st4h(__half* p, float4 v) {
    __half2 a, b;
    a.x = __float2half_rn(v.x); a.y = __float2half_rn(v.y);
    b.x = __float2half_rn(v.z); b.y = __float2half_rn(v.w);
    uint2 u;
    u.x = *(uint32_t*)&a; u.y = *(uint32_t*)&b;
    *(uint2*)p = u;
}

__global__ __launch_bounds__(512) void k_mix_softmax(
    const float* __restrict__ W1, const float* __restrict__ W2)
{
    __shared__ float w1s[64], w2l[64];
    __shared__ float red[16][8];
    __shared__ float finm[8], finl[8];

    const int tid = threadIdx.x;
    const int wid = tid >> 5, lane = tid & 31;
    const int i = blockIdx.x, b = blockIdx.y;

    if (tid < 64) w1s[tid] = W1[tid];
    __syncthreads();

    const __half* Srow = g_S + (size_t)b * NH * PLEN * PLEN + (size_t)i * PLEN;
    __half* Orow = g_Sh + (size_t)b * NH * PLEN * PLEN + (size_t)i * PLEN;
    const int j4 = tid << 2;

    float4 v[8];
    {
        float4 r[8];
#pragma unroll
        for (int h = 0; h < 8; h++)
            r[h] = ld4h(Srow + (size_t)h * PLEN * PLEN + j4);
#pragma unroll
        for (int g = 0; g < 8; g++) {
            float4 a = {0.f, 0.f, 0.f, 0.f};
#pragma unroll
            for (int h = 0; h < 8; h++) {
                float w = w1s[h * 8 + g];
                a.x += w * r[h].x; a.y += w * r[h].y;
                a.z += w * r[h].z; a.w += w * r[h].w;
            }
            v[g] = a;
        }
    }

#pragma unroll
    for (int g = 0; g < 8; g++) {
        float m = fmaxf(fmaxf(v[g].x, v[g].y), fmaxf(v[g].z, v[g].w));
#pragma unroll
        for (int o = 16; o; o >>= 1) m = fmaxf(m, __shfl_xor_sync(0xffffffffu, m, o));
        if (lane == 0) red[wid][g] = m;
    }
    __syncthreads();
    if (tid < 8) {
        float m = -1e30f;
#pragma unroll
        for (int w = 0; w < 16; w++) m = fmaxf(m, red[w][tid]);
        finm[tid] = m;
    }
    __syncthreads();

#pragma unroll
    for (int g = 0; g < 8; g++) {
        float m = finm[g];
        v[g].x = __expf(v[g].x - m);
        v[g].y = __expf(v[g].y - m);
        v[g].z = __expf(v[g].z - m);
        v[g].w = __expf(v[g].w - m);
        float s = (v[g].x + v[g].y) + (v[g].z + v[g].w);
#pragma unroll
        for (int o = 16; o; o >>= 1) s += __shfl_xor_sync(0xffffffffu, s, o);
        if (lane == 0) red[wid][g] = s;
    }
    __syncthreads();
    if (tid < 8) {
        float s = 0.f;
#pragma unroll
        for (int w = 0; w < 16; w++) s += red[w][tid];
        finl[tid] = s;
    }
    __syncthreads();

    if (tid < 64) w2l[tid] = W2[tid] / finl[tid >> 3];
    __syncthreads();

#pragma unroll
    for (int gp = 0; gp < 8; gp++) {
        float4 a = {0.f, 0.f, 0.f, 0.f};
#pragma unroll
        for (int h = 0; h < 8; h++) {
            float w = w2l[h * 8 + gp];
            a.x += w * v[h].x; a.y += w * v[h].y;
            a.z += w * v[h].z; a.w += w * v[h].w;
        }
        st4h(Orow + (size_t)gp * PLEN * PLEN + j4, a);
    }
}

// ---------------------------------------------------------------------------
extern "C" void kernel_launch(void* const* d_in, const int* in_sizes, int n_in,
                              void* d_out, int out_size)
{
    const float* x     = (const float*)d_in[0];
    const float* Wq    = (const float*)d_in[1];
    const float* Wk    = (const float*)d_in[2];
    const float* Wv    = (const float*)d_in[3];
    const float* W1    = (const float*)d_in[4];
    const float* W2    = (const float*)d_in[5];
    const float* Wproj = (const float*)d_in[6];
    float* out = (float*)d_out;

    cudaFuncSetAttribute(k_qkv_mma,    cudaFuncAttributeMaxDynamicSharedMemorySize, SMEM_BT2);
    cudaFuncSetAttribute(k_scores_mma, cudaFuncAttributeMaxDynamicSharedMemorySize, SMEM_BT1);
    cudaFuncSetAttribute(k_pv_mma,     cudaFuncAttributeMaxDynamicSharedMemorySize, SMEM_BT1);
    cudaFuncSetAttribute(k_proj_mma,   cudaFuncAttributeMaxDynamicSharedMemorySize, SMEM_BT2);

    __half *wqth, *wqtl, *wkth, *wktl, *wvth, *wvtl, *wpth, *wptl;
    cudaGetSymbolAddress((void**)&wqth, g_wqth); cudaGetSymbolAddress((void**)&wqtl, g_wqtl);
    cudaGetSymbolAddress((void**)&wkth, g_wkth); cudaGetSymbolAddress((void**)&wktl, g_wktl);
    cudaGetSymbolAddress((void**)&wvth, g_wvth); cudaGetSymbolAddress((void**)&wvtl, g_wvtl);
    cudaGetSymbolAddress((void**)&wpth, g_wpth); cudaGetSymbolAddress((void**)&wptl, g_wptl);
    float* vp = nullptr;  cudaGetSymbolAddress((void**)&vp,  g_v);
    __half* vtp = nullptr; cudaGetSymbolAddress((void**)&vtp, g_vt);

    k_wtrans4<<<dim3(16, 16, 4), dim3(32, 8)>>>(Wq, Wk, Wv, Wproj,
                                                wqth, wqtl, wkth, wktl,
                                                wvth, wvtl, wpth, wptl);
    k_qkv_mma<<<dim3(8, 32, 3), 256, SMEM_BT2>>>(x);
    k_transpose_h<<<dim3(16, 64, 2), dim3(32, 8)>>>(vp, vtp, PLEN, DM);
    k_scores_mma<<<dim3(32, 16, 16), 256, SMEM_BT1>>>();
    k_mix_softmax<<<dim3(2048, 2, 1), 512>>>(W1, W2);
    k_pv_mma<<<dim3(KSPLIT, 16, 16), 256, SMEM_BT1>>>();
    k_proj_mma<<<dim3(8, 32, 1), 256, SMEM_BT2>>>(out);
}

// round 15
// speedup vs baseline: 1.3473x; 1.0606x over previous
#include <cuda_runtime.h>
#include <cuda_fp16.h>
#include <cstdint>

#define PLEN 2048
#define BATCH 2
#define NH 8
#define DH 64
#define DM 512
#define KSPLIT 4

static const size_t PSTRIDE = (size_t)BATCH * PLEN * DM;  // one pv partial buffer

// ---------------------------------------------------------------------------
// Scratch (allocation-free: __device__ globals)
// ---------------------------------------------------------------------------
__device__ __half g_qf[BATCH * PLEN * DM];                 // Q fp16 (pre-scaled)
__device__ __half g_kf[BATCH * PLEN * DM];                 // K fp16 (single)
__device__ float  g_v[BATCH * PLEN * DM];
__device__ float  g_ohp[KSPLIT * BATCH * PLEN * DM];       // pv split-K partials
__device__ __half g_vt[BATCH * DM * PLEN];                 // V^T fp16 (single)
__device__ __half g_wqth[DM * DM], g_wqtl[DM * DM];
__device__ __half g_wkth[DM * DM], g_wktl[DM * DM];
__device__ __half g_wvth[DM * DM], g_wvtl[DM * DM];
__device__ __half g_wpth[DM * DM], g_wptl[DM * DM];
__device__ __half g_S[(size_t)BATCH * NH * PLEN * PLEN];   // fp16 raw logits
__device__ __half g_Sh[(size_t)BATCH * NH * PLEN * PLEN];  // fp16 post-mix attn

// ---------------------------------------------------------------------------
// Warp MMA helpers (plain sm_80+ PTX)
// ---------------------------------------------------------------------------
__device__ __forceinline__ uint32_t smem_u32(const void* p) {
    uint32_t a;
    asm("{ .reg .u64 t; cvta.to.shared.u64 t, %1; cvt.u32.u64 %0, t; }" : "=r"(a) : "l"(p));
    return a;
}

#define LDSM4(r, addr)                                                         \
    asm volatile("ldmatrix.sync.aligned.m8n8.x4.shared.b16 {%0,%1,%2,%3}, [%4];" \
                 : "=r"((r)[0]), "=r"((r)[1]), "=r"((r)[2]), "=r"((r)[3])      \
                 : "r"(addr))

#define MMA16816H(d, a, b)                                                     \
    asm volatile("mma.sync.aligned.m16n8k16.row.col.f32.f16.f16.f32 "          \
                 "{%0,%1,%2,%3}, {%4,%5,%6,%7}, {%8,%9}, {%0,%1,%2,%3};"       \
                 : "+f"((d)[0]), "+f"((d)[1]), "+f"((d)[2]), "+f"((d)[3])      \
                 : "r"((a)[0]), "r"((a)[1]), "r"((a)[2]), "r"((a)[3]),         \
                   "r"((b)[0]), "r"((b)[1]))

__device__ __forceinline__ uint2 f4_to_h4(float4 v) {
    __half2 a, b;
    a.x = __float2half_rn(v.x); a.y = __float2half_rn(v.y);
    b.x = __float2half_rn(v.z); b.y = __float2half_rn(v.w);
    uint2 u;
    u.x = *(uint32_t*)&a; u.y = *(uint32_t*)&b;
    return u;
}

// ---------------------------------------------------------------------------
// Generic double-buffered fp16 NT GEMM, CTA tile 128 x 64 (qkv / pv / proj)
// ---------------------------------------------------------------------------
#define KC 32
#define SRS 40  // smem row stride in halves (80 B)
#define NT 64

template <int ASRC, int COUT, int BT>
__device__ void gemm_f16(const void* __restrict__ Asrc, size_t apstride, int lda,
                         const __half* __restrict__ Bh_g,
                         const __half* __restrict__ Bl_g, int ldb,
                         void* __restrict__ Cv, int ldc,
                         int K, float alpha, int m0, int n0)
{
    constexpr int WN = 2, MT = 32, MF = 2;
    constexpr int PB = NT / 32;
    constexpr int AEL = 128 * SRS;
    constexpr int BEL = NT * SRS;
    constexpr int BUFEL = AEL + BT * BEL;

    extern __shared__ __half sm[];

    const int tid = threadIdx.x;
    const int wid = tid >> 5, lane = tid & 31;
    const int wm = wid / WN, wn = wid % WN;
    const uint32_t ubase = smem_u32(sm);

    const uint32_t aOff = (uint32_t)(wm * MT + (lane & 15)) * (SRS * 2)
                        + (uint32_t)(lane >> 4) * 16;
    const uint32_t bOff = (uint32_t)(wn * 32 + ((lane >> 4) << 3) + (lane & 7)) * (SRS * 2)
                        + (uint32_t)((lane >> 3) & 1) * 16;

    float acc[MF][4][4];
#pragma unroll
    for (int i = 0; i < MF; i++)
#pragma unroll
        for (int j = 0; j < 4; j++)
#pragma unroll
            for (int t = 0; t < 4; t++) acc[i][j][t] = 0.f;

    const float* Af = (const float*)Asrc;
    const __half* Ah16 = (const __half*)Asrc;

    uint2 pa[4], pbh[PB], pbl[PB];

#define LOAD_AB(k0_)                                                            \
    {                                                                           \
        _Pragma("unroll")                                                       \
        for (int u = 0; u < 4; u++) {                                           \
            int i_ = tid + u * 256;                                             \
            int r_ = i_ >> 3, c4_ = (i_ & 7) << 2;                              \
            size_t idx_ = (size_t)(m0 + r_) * lda + (k0_) + c4_;                \
            if (ASRC == 1) {                                                    \
                pa[u] = *(const uint2*)(Ah16 + idx_);                           \
            } else {                                                            \
                float4 v_ = *(const float4*)(Af + idx_);                        \
                if (ASRC == 2) {                                                \
                    float4 v1_ = *(const float4*)(Af + idx_ + apstride);        \
                    float4 v2_ = *(const float4*)(Af + idx_ + 2 * apstride);    \
                    float4 v3_ = *(const float4*)(Af + idx_ + 3 * apstride);    \
                    v_.x += v1_.x + v2_.x + v3_.x;                              \
                    v_.y += v1_.y + v2_.y + v3_.y;                              \
                    v_.z += v1_.z + v2_.z + v3_.z;                              \
                    v_.w += v1_.w + v2_.w + v3_.w;                              \
                }                                                               \
                pa[u] = f4_to_h4(v_);                                           \
            }                                                                   \
        }                                                                       \
        _Pragma("unroll")                                                       \
        for (int u = 0; u < PB; u++) {                                          \
            int i_ = tid + u * 256;                                             \
            int r_ = i_ >> 3, c4_ = (i_ & 7) << 2;                              \
            size_t idx_ = (size_t)(n0 + r_) * ldb + (k0_) + c4_;                \
            pbh[u] = *(const uint2*)(Bh_g + idx_);                              \
            if (BT == 2) pbl[u] = *(const uint2*)(Bl_g + idx_);                 \
        }                                                                       \
    }

#define STORE_BUF(bi_)                                                          \
    {                                                                           \
        __half* Af_ = sm + (bi_) * BUFEL;                                       \
        __half* Bh_ = Af_ + AEL;                                                \
        __half* Bl_ = Bh_ + BEL;                                                \
        _Pragma("unroll")                                                       \
        for (int u = 0; u < 4; u++) {                                           \
            int i_ = tid + u * 256;                                             \
            int r_ = i_ >> 3, c4_ = (i_ & 7) << 2;                              \
            *(uint2*)(Af_ + r_ * SRS + c4_) = pa[u];                            \
        }                                                                       \
        _Pragma("unroll")                                                       \
        for (int u = 0; u < PB; u++) {                                          \
            int i_ = tid + u * 256;                                             \
            int r_ = i_ >> 3, c4_ = (i_ & 7) << 2;                              \
            *(uint2*)(Bh_ + r_ * SRS + c4_) = pbh[u];                           \
            if (BT == 2) *(uint2*)(Bl_ + r_ * SRS + c4_) = pbl[u];              \
        }                                                                       \
    }

    LOAD_AB(0);
    STORE_BUF(0);
    __syncthreads();

    const int nch = K / KC;
    for (int ch = 0; ch < nch; ch++) {
        if (ch + 1 < nch) LOAD_AB((ch + 1) * KC);

        const uint32_t bb = (uint32_t)((ch & 1) * BUFEL * 2);
        const uint32_t uAf = ubase + bb;
        const uint32_t uBh = uAf + AEL * 2;
        const uint32_t uBl = uBh + BEL * 2;

#pragma unroll
        for (int ks = 0; ks < 2; ks++) {
            const uint32_t kb = (uint32_t)(ks * 32);
            uint32_t ah[MF][4], bh[4][2], bl[4][2];
#pragma unroll
            for (int mf = 0; mf < MF; mf++) {
                uint32_t off = aOff + (uint32_t)(mf * 16) * (SRS * 2) + kb;
                LDSM4(ah[mf], uAf + off);
            }
#pragma unroll
            for (int g = 0; g < 2; g++) {
                uint32_t off = bOff + (uint32_t)(g * 16) * (SRS * 2) + kb;
                uint32_t th[4], tl[4];
                LDSM4(th, uBh + off);
                bh[2 * g][0] = th[0]; bh[2 * g][1] = th[1];
                bh[2 * g + 1][0] = th[2]; bh[2 * g + 1][1] = th[3];
                if (BT == 2) {
                    LDSM4(tl, uBl + off);
                    bl[2 * g][0] = tl[0]; bl[2 * g][1] = tl[1];
                    bl[2 * g + 1][0] = tl[2]; bl[2 * g + 1][1] = tl[3];
                }
            }
#pragma unroll
            for (int mf = 0; mf < MF; mf++)
#pragma unroll
                for (int nf = 0; nf < 4; nf++) {
                    MMA16816H(acc[mf][nf], ah[mf], bh[nf]);
                    if (BT == 2) MMA16816H(acc[mf][nf], ah[mf], bl[nf]);
                }
        }

        if (ch + 1 < nch) {
            STORE_BUF((ch + 1) & 1);
            __syncthreads();
        }
    }

    const int rbase = m0 + wm * MT + (lane >> 2);
    const int cbase = n0 + wn * 32 + ((lane & 3) << 1);
#pragma unroll
    for (int mf = 0; mf < MF; mf++)
#pragma unroll
        for (int nf = 0; nf < 4; nf++) {
            int r0 = rbase + mf * 16;
            int c = cbase + nf * 8;
            float v0x = acc[mf][nf][0] * alpha, v0y = acc[mf][nf][1] * alpha;
            float v1x = acc[mf][nf][2] * alpha, v1y = acc[mf][nf][3] * alpha;
            if (COUT == 1) {
                __half* Ch = (__half*)Cv;
                __half2 p0, p1;
                p0.x = __float2half_rn(v0x); p0.y = __float2half_rn(v0y);
                p1.x = __float2half_rn(v1x); p1.y = __float2half_rn(v1y);
                *(__half2*)(Ch + (size_t)r0 * ldc + c) = p0;
                *(__half2*)(Ch + (size_t)(r0 + 8) * ldc + c) = p1;
            } else {
                float* C = (float*)Cv;
                float2 w0 = {v0x, v0y};
                float2 w1 = {v1x, v1y};
                *(float2*)(C + (size_t)r0 * ldc + c) = w0;
                *(float2*)(C + (size_t)(r0 + 8) * ldc + c) = w1;
            }
        }
#undef LOAD_AB
#undef STORE_BUF
}

#define SMEM_BT2 (2 * (128 * SRS + 2 * 64 * SRS) * 2)   // 40960 B
#define SMEM_BT1 (2 * (128 * SRS + 1 * 64 * SRS) * 2)   // 30720 B

// ---------------------------------------------------------------------------
// Persistent-Q flash-style scores kernel.
// One CTA per (m-tile, z). Q tile (128x64) -> smem -> registers ONCE,
// then loop over 32 j-tiles of K (64x64), double-buffered, C streamed out.
// K-accumulation order (kf 0..3) identical to the generic kernel.
// ---------------------------------------------------------------------------
#define SRS2 72  // row stride (halves) for 64-wide tiles, bank-conflict-free

#define SMEM_SC ((128 * SRS2 + 2 * 64 * SRS2) * 2)  // 36864 B

__global__ __launch_bounds__(256, 2) void k_scores_flash()
{
    extern __shared__ __half sm[];
    __half* sQ = sm;                       // 128 x SRS2
    __half* sB0 = sQ + 128 * SRS2;         // 64 x SRS2, double buffered
    constexpr int BEL2 = 64 * SRS2;

    const int tid = threadIdx.x;
    const int wid = tid >> 5, lane = tid & 31;
    const int wm = wid >> 1, wn = wid & 1;

    const int z = blockIdx.y, m0 = blockIdx.x * 128;
    const size_t off = (size_t)(z >> 3) * PLEN * DM + (z & 7) * DH;
    const __half* Q = g_qf + off;
    const __half* Kp = g_kf + off;
    __half* C = g_S + (size_t)z * PLEN * PLEN;

    const uint32_t uQ = smem_u32(sQ);
    const uint32_t uB = smem_u32(sB0);

    // ---- load Q tile 128 x 64 into smem ----
#pragma unroll
    for (int u = 0; u < 8; u++) {
        int i = tid + u * 256;
        int r = i >> 4, c4 = (i & 15) << 2;
        *(uint2*)(sQ + r * SRS2 + c4) =
            *(const uint2*)(Q + (size_t)(m0 + r) * DM + c4);
    }
    __syncthreads();

    // ---- ldmatrix Q into persistent registers: ah[mf][kf][4] ----
    const uint32_t aOff = (uint32_t)(wm * 32 + (lane & 15)) * (SRS2 * 2)
                        + (uint32_t)(lane >> 4) * 16;
    uint32_t ah[2][4][4];
#pragma unroll
    for (int mf = 0; mf < 2; mf++)
#pragma unroll
        for (int kf = 0; kf < 4; kf++) {
            uint32_t o = aOff + (uint32_t)(mf * 16) * (SRS2 * 2) + (uint32_t)(kf * 32);
            LDSM4(ah[mf][kf], uQ + o);
        }
    __syncthreads();  // sQ no longer needed as data (regs hold it)

    const uint32_t bOff = (uint32_t)(wn * 32 + ((lane >> 4) << 3) + (lane & 7)) * (SRS2 * 2)
                        + (uint32_t)((lane >> 3) & 1) * 16;

    // ---- prologue: load j-tile 0 ----
    uint2 pb[4];
#pragma unroll
    for (int u = 0; u < 4; u++) {
        int i = tid + u * 256;
        int r = i >> 4, c4 = (i & 15) << 2;
        pb[u] = *(const uint2*)(Kp + (size_t)r * DM + c4);
    }
#pragma unroll
    for (int u = 0; u < 4; u++) {
        int i = tid + u * 256;
        int r = i >> 4, c4 = (i & 15) << 2;
        *(uint2*)(sB0 + r * SRS2 + c4) = pb[u];
    }
    __syncthreads();

    const int rbase = m0 + wm * 32 + (lane >> 2);
    const int cwarp = wn * 32 + ((lane & 3) << 1);

    for (int jt = 0; jt < 32; jt++) {
        // prefetch next j-tile
        if (jt + 1 < 32) {
            const __half* Kn = Kp + (size_t)(jt + 1) * 64 * DM;
#pragma unroll
            for (int u = 0; u < 4; u++) {
                int i = tid + u * 256;
                int r = i >> 4, c4 = (i & 15) << 2;
                pb[u] = *(const uint2*)(Kn + (size_t)r * DM + c4);
            }
        }

        const uint32_t uBc = uB + (uint32_t)((jt & 1) * BEL2 * 2);

        float acc[2][4][4];
#pragma unroll
        for (int i = 0; i < 2; i++)
#pragma unroll
            for (int j = 0; j < 4; j++)
#pragma unroll
                for (int t = 0; t < 4; t++) acc[i][j][t] = 0.f;

#pragma unroll
        for (int kf = 0; kf < 4; kf++) {
            uint32_t bh[4][2];
#pragma unroll
            for (int g = 0; g < 2; g++) {
                uint32_t o = bOff + (uint32_t)(g * 16) * (SRS2 * 2) + (uint32_t)(kf * 32);
                uint32_t th[4];
                LDSM4(th, uBc + o);
                bh[2 * g][0] = th[0]; bh[2 * g][1] = th[1];
                bh[2 * g + 1][0] = th[2]; bh[2 * g + 1][1] = th[3];
            }
#pragma unroll
            for (int mf = 0; mf < 2; mf++)
#pragma unroll
                for (int nf = 0; nf < 4; nf++)
                    MMA16816H(acc[mf][nf], ah[mf][kf], bh[nf]);
        }

        // ---- store C tile ----
        __half* Cj = C + jt * 64;
#pragma unroll
        for (int mf = 0; mf < 2; mf++)
#pragma unroll
            for (int nf = 0; nf < 4; nf++) {
                int r0 = rbase + mf * 16;
                int c = cwarp + nf * 8;
                __half2 p0, p1;
                p0.x = __float2half_rn(acc[mf][nf][0]);
                p0.y = __float2half_rn(acc[mf][nf][1]);
                p1.x = __float2half_rn(acc[mf][nf][2]);
                p1.y = __float2half_rn(acc[mf][nf][3]);
                *(__half2*)(Cj + (size_t)r0 * PLEN + c) = p0;
                *(__half2*)(Cj + (size_t)(r0 + 8) * PLEN + c) = p1;
            }

        if (jt + 1 < 32) {
            __syncthreads();  // all LDSM of current buffer done before overwrite
            __half* sBn = sB0 + ((jt + 1) & 1) * BEL2;
#pragma unroll
            for (int u = 0; u < 4; u++) {
                int i = tid + u * 256;
                int r = i >> 4, c4 = (i & 15) << 2;
                *(uint2*)(sBn + r * SRS2 + c4) = pb[u];
            }
            __syncthreads();
        }
    }
}

// ---------------------------------------------------------------------------
// Merged weight transpose + fp16 split: 4 x (512x512)
// ---------------------------------------------------------------------------
__global__ __launch_bounds__(256) void k_wtrans4(
    const float* __restrict__ Wq, const float* __restrict__ Wk,
    const float* __restrict__ Wv, const float* __restrict__ Wp,
    __half* qh, __half* ql, __half* kh, __half* kl,
    __half* vh, __half* vl, __half* ph, __half* pl)
{
    __shared__ float t[32][33];
    int z = blockIdx.z;
    const float* s = (z == 0) ? Wq : (z == 1) ? Wk : (z == 2) ? Wv : Wp;
    __half* dh = (z == 0) ? qh : (z == 1) ? kh : (z == 2) ? vh : ph;
    __half* dl = (z == 0) ? ql : (z == 1) ? kl : (z == 2) ? vl : pl;
    int c0 = blockIdx.x * 32, r0 = blockIdx.y * 32;
    for (int dy = threadIdx.y; dy < 32; dy += 8)
        t[dy][threadIdx.x] = s[(size_t)(r0 + dy) * DM + c0 + threadIdx.x];
    __syncthreads();
    for (int dy = threadIdx.y; dy < 32; dy += 8) {
        float v = t[threadIdx.x][dy];
        __half h = __float2half_rn(v);
        size_t o = (size_t)(c0 + dy) * DM + r0 + threadIdx.x;
        dh[o] = h;
        dl[o] = __float2half_rn(v - __half2float(h));
    }
}

// V transpose (single fp16): [b, p, d] -> [b, d, p]
__global__ __launch_bounds__(256) void k_transpose_h(
    const float* __restrict__ src, __half* __restrict__ dst, int R, int C)
{
    __shared__ float t[32][33];
    const float* s = src + (size_t)blockIdx.z * R * C;
    __half* d = dst + (size_t)blockIdx.z * R * C;
    int c0 = blockIdx.x * 32, r0 = blockIdx.y * 32;
    for (int dy = threadIdx.y; dy < 32; dy += 8)
        t[dy][threadIdx.x] = s[(size_t)(r0 + dy) * C + c0 + threadIdx.x];
    __syncthreads();
    for (int dy = threadIdx.y; dy < 32; dy += 8)
        d[(size_t)(c0 + dy) * R + r0 + threadIdx.x] =
            __float2half_rn(t[threadIdx.x][dy]);
}

// ---------------------------------------------------------------------------
// Stage kernels
// ---------------------------------------------------------------------------
__global__ __launch_bounds__(256, 2) void k_qkv_mma(const float* __restrict__ x)
{
    int which = blockIdx.z;
    int m0 = blockIdx.y * 128, n0 = blockIdx.x * NT;
    if (which == 0) {
        gemm_f16<0, 1, 2>(x, 0, DM, g_wqth, g_wqtl, DM,
                          g_qf, DM, DM, 0.125f, m0, n0);
    } else if (which == 1) {
        gemm_f16<0, 1, 2>(x, 0, DM, g_wkth, g_wktl, DM,
                          g_kf, DM, DM, 1.0f, m0, n0);
    } else {
        gemm_f16<0, 0, 2>(x, 0, DM, g_wvth, g_wvtl, DM,
                          g_v, DM, DM, 1.0f, m0, n0);
    }
}

__global__ __launch_bounds__(256, 2) void k_pv_mma()
{
    int kidx = blockIdx.x;
    int z = blockIdx.z, b = z >> 3, g = z & 7;
    const __half* A = g_Sh + (size_t)z * PLEN * PLEN + kidx * (PLEN / KSPLIT);
    size_t boff = (size_t)b * DM * PLEN + (size_t)g * DH * PLEN
                + kidx * (PLEN / KSPLIT);
    float* C = g_ohp + (size_t)kidx * PSTRIDE + (size_t)b * PLEN * DM + g * DH;
    gemm_f16<1, 0, 1>(A, 0, PLEN, g_vt + boff, nullptr, PLEN,
                      C, DM, PLEN / KSPLIT, 1.0f,
                      blockIdx.y * 128, 0);
}

__global__ __launch_bounds__(256, 2) void k_proj_mma(float* __restrict__ out)
{
    gemm_f16<2, 0, 2>(g_ohp, PSTRIDE, DM, g_wpth, g_wptl, DM,
                      out, DM, DM, 1.0f,
                      blockIdx.y * 128, blockIdx.x * NT);
}

// ---------------------------------------------------------------------------
// Stage 3: head-mix (W1) -> softmax -> head-mix (W2, /l folded).
// Register-resident. Reads fp16 g_S, writes fp16 g_Sh. 512 thr.
// ---------------------------------------------------------------------------
__device__ __forceinline__ float4 ld4h(const __half* p) {
    uint2 u = *(const uint2*)p;
    __half2 a = *(__half2*)&u.x;
    __half2 b = *(__half2*)&u.y;
    float4 r;
    r.x = __half2float(a.x); r.y = __half2float(a.y);
    r.z = __half2float(b.x); r.w = __half2float(b.y);
    return r;
}
__device__ __forceinline__ void st4h(__half* p, float4 v) {
    __half2 a, b;
    a.x = __float2half_rn(v.x); a.y = __float2half_rn(v.y);
    b.x = __float2half_rn(v.z); b.y = __float2half_rn(v.w);
    uint2 u;
    u.x = *(uint32_t*)&a; u.y = *(uint32_t*)&b;
    *(uint2*)p = u;
}

__global__ __launch_bounds__(512) void k_mix_softmax(
    const float* __restrict__ W1, const float* __restrict__ W2)
{
    __shared__ float w1s[64], w2l[64];
    __shared__ float red[16][8];
    __shared__ float finm[8], finl[8];

    const int tid = threadIdx.x;
    const int wid = tid >> 5, lane = tid & 31;
    const int i = blockIdx.x, b = blockIdx.y;

    if (tid < 64) w1s[tid] = W1[tid];
    __syncthreads();

    const __half* Srow = g_S + (size_t)b * NH * PLEN * PLEN + (size_t)i * PLEN;
    __half* Orow = g_Sh + (size_t)b * NH * PLEN * PLEN + (size_t)i * PLEN;
    const int j4 = tid << 2;

    float4 v[8];
    {
        float4 r[8];
#pragma unroll
        for (int h = 0; h < 8; h++)
            r[h] = ld4h(Srow + (size_t)h * PLEN * PLEN + j4);
#pragma unroll
        for (int g = 0; g < 8; g++) {
            float4 a = {0.f, 0.f, 0.f, 0.f};
#pragma unroll
            for (int h = 0; h < 8; h++) {
                float w = w1s[h * 8 + g];
                a.x += w * r[h].x; a.y += w * r[h].y;
                a.z += w * r[h].z; a.w += w * r[h].w;
            }
            v[g] = a;
        }
    }

#pragma unroll
    for (int g = 0; g < 8; g++) {
        float m = fmaxf(fmaxf(v[g].x, v[g].y), fmaxf(v[g].z, v[g].w));
#pragma unroll
        for (int o = 16; o; o >>= 1) m = fmaxf(m, __shfl_xor_sync(0xffffffffu, m, o));
        if (lane == 0) red[wid][g] = m;
    }
    __syncthreads();
    if (tid < 8) {
        float m = -1e30f;
#pragma unroll
        for (int w = 0; w < 16; w++) m = fmaxf(m, red[w][tid]);
        finm[tid] = m;
    }
    __syncthreads();

#pragma unroll
    for (int g = 0; g < 8; g++) {
        float m = finm[g];
        v[g].x = __expf(v[g].x - m);
        v[g].y = __expf(v[g].y - m);
        v[g].z = __expf(v[g].z - m);
        v[g].w = __expf(v[g].w - m);
        float s = (v[g].x + v[g].y) + (v[g].z + v[g].w);
#pragma unroll
        for (int o = 16; o; o >>= 1) s += __shfl_xor_sync(0xffffffffu, s, o);
        if (lane == 0) red[wid][g] = s;
    }
    __syncthreads();
    if (tid < 8) {
        float s = 0.f;
#pragma unroll
        for (int w = 0; w < 16; w++) s += red[w][tid];
        finl[tid] = s;
    }
    __syncthreads();

    if (tid < 64) w2l[tid] = W2[tid] / finl[tid >> 3];
    __syncthreads();

#pragma unroll
    for (int gp = 0; gp < 8; gp++) {
        float4 a = {0.f, 0.f, 0.f, 0.f};
#pragma unroll
        for (int h = 0; h < 8; h++) {
            float w = w2l[h * 8 + gp];
            a.x += w * v[h].x; a.y += w * v[h].y;
            a.z += w * v[h].z; a.w += w * v[h].w;
        }
        st4h(Orow + (size_t)gp * PLEN * PLEN + j4, a);
    }
}

// ---------------------------------------------------------------------------
extern "C" void kernel_launch(void* const* d_in, const int* in_sizes, int n_in,
                              void* d_out, int out_size)
{
    const float* x     = (const float*)d_in[0];
    const float* Wq    = (const float*)d_in[1];
    const float* Wk    = (const float*)d_in[2];
    const float* Wv    = (const float*)d_in[3];
    const float* W1    = (const float*)d_in[4];
    const float* W2    = (const float*)d_in[5];
    const float* Wproj = (const float*)d_in[6];
    float* out = (float*)d_out;

    cudaFuncSetAttribute(k_qkv_mma,      cudaFuncAttributeMaxDynamicSharedMemorySize, SMEM_BT2);
    cudaFuncSetAttribute(k_scores_flash, cudaFuncAttributeMaxDynamicSharedMemorySize, SMEM_SC);
    cudaFuncSetAttribute(k_pv_mma,       cudaFuncAttributeMaxDynamicSharedMemorySize, SMEM_BT1);
    cudaFuncSetAttribute(k_proj_mma,     cudaFuncAttributeMaxDynamicSharedMemorySize, SMEM_BT2);

    __half *wqth, *wqtl, *wkth, *wktl, *wvth, *wvtl, *wpth, *wptl;
    cudaGetSymbolAddress((void**)&wqth, g_wqth); cudaGetSymbolAddress((void**)&wqtl, g_wqtl);
    cudaGetSymbolAddress((void**)&wkth, g_wkth); cudaGetSymbolAddress((void**)&wktl, g_wktl);
    cudaGetSymbolAddress((void**)&wvth, g_wvth); cudaGetSymbolAddress((void**)&wvtl, g_wvtl);
    cudaGetSymbolAddress((void**)&wpth, g_wpth); cudaGetSymbolAddress((void**)&wptl, g_wptl);
    float* vp = nullptr;  cudaGetSymbolAddress((void**)&vp,  g_v);
    __half* vtp = nullptr; cudaGetSymbolAddress((void**)&vtp, g_vt);

    k_wtrans4<<<dim3(16, 16, 4), dim3(32, 8)>>>(Wq, Wk, Wv, Wproj,
                                                wqth, wqtl, wkth, wktl,
                                                wvth, wvtl, wpth, wptl);
    k_qkv_mma<<<dim3(8, 32, 3), 256, SMEM_BT2>>>(x);
    k_transpose_h<<<dim3(16, 64, 2), dim3(32, 8)>>>(vp, vtp, PLEN, DM);
    k_scores_flash<<<dim3(16, 16), 256, SMEM_SC>>>();
    k_mix_softmax<<<dim3(2048, 2, 1), 512>>>(W1, W2);
    k_pv_mma<<<dim3(KSPLIT, 16, 16), 256, SMEM_BT1>>>();
    k_proj_mma<<<dim3(8, 32, 1), 256, SMEM_BT2>>>(out);
}

// round 17
// speedup vs baseline: 1.4072x; 1.0444x over previous
#include <cuda_runtime.h>
#include <cuda_fp16.h>
#include <cstdint>

#define PLEN 2048
#define BATCH 2
#define NH 8
#define DH 64
#define DM 512
#define KSPLIT 4

static const size_t PSTRIDE = (size_t)BATCH * PLEN * DM;  // one pv partial buffer

// ---------------------------------------------------------------------------
// Scratch (allocation-free: __device__ globals)
// ---------------------------------------------------------------------------
__device__ __half g_qf[BATCH * PLEN * DM];                 // Q fp16 (pre-scaled)
__device__ __half g_kf[BATCH * PLEN * DM];                 // K fp16 (single)
__device__ float  g_v[BATCH * PLEN * DM];
__device__ float  g_ohp[KSPLIT * BATCH * PLEN * DM];       // pv split-K partials
__device__ __half g_vt[BATCH * DM * PLEN];                 // V^T fp16 (single)
__device__ __half g_wqth[DM * DM], g_wqtl[DM * DM];
__device__ __half g_wkth[DM * DM], g_wktl[DM * DM];
__device__ __half g_wvth[DM * DM], g_wvtl[DM * DM];
__device__ __half g_wpth[DM * DM], g_wptl[DM * DM];
__device__ __half g_S[(size_t)BATCH * NH * PLEN * PLEN];   // fp16 raw logits
__device__ __half g_Sh[(size_t)BATCH * NH * PLEN * PLEN];  // fp16 post-mix attn

// ---------------------------------------------------------------------------
// Warp MMA helpers (plain sm_80+ PTX)
// ---------------------------------------------------------------------------
__device__ __forceinline__ uint32_t smem_u32(const void* p) {
    uint32_t a;
    asm("{ .reg .u64 t; cvta.to.shared.u64 t, %1; cvt.u32.u64 %0, t; }" : "=r"(a) : "l"(p));
    return a;
}

#define LDSM4(r, addr)                                                         \
    asm volatile("ldmatrix.sync.aligned.m8n8.x4.shared.b16 {%0,%1,%2,%3}, [%4];" \
                 : "=r"((r)[0]), "=r"((r)[1]), "=r"((r)[2]), "=r"((r)[3])      \
                 : "r"(addr))

#define MMA16816H(d, a, b)                                                     \
    asm volatile("mma.sync.aligned.m16n8k16.row.col.f32.f16.f16.f32 "          \
                 "{%0,%1,%2,%3}, {%4,%5,%6,%7}, {%8,%9}, {%0,%1,%2,%3};"       \
                 : "+f"((d)[0]), "+f"((d)[1]), "+f"((d)[2]), "+f"((d)[3])      \
                 : "r"((a)[0]), "r"((a)[1]), "r"((a)[2]), "r"((a)[3]),         \
                   "r"((b)[0]), "r"((b)[1]))

__device__ __forceinline__ uint2 f4_to_h4(float4 v) {
    __half2 a, b;
    a.x = __float2half_rn(v.x); a.y = __float2half_rn(v.y);
    b.x = __float2half_rn(v.z); b.y = __float2half_rn(v.w);
    uint2 u;
    u.x = *(uint32_t*)&a; u.y = *(uint32_t*)&b;
    return u;
}

// 4x4 transpose across a lane quad. Two xor-shuffle stages (bit0, bit1);
// each stage buffers ALL exchanges before committing writes (no in-place hazard).
__device__ __forceinline__ void quad_transpose(uint32_t v[4], int lane) {
    uint32_t t[4];
#pragma unroll
    for (int j = 0; j < 4; j++)
        t[j] = __shfl_xor_sync(0xffffffffu, v[j ^ 1], 1);
#pragma unroll
    for (int j = 0; j < 4; j++)
        if ((lane ^ j) & 1) v[j] = t[j];
#pragma unroll
    for (int j = 0; j < 4; j++)
        t[j] = __shfl_xor_sync(0xffffffffu, v[j ^ 2], 2);
#pragma unroll
    for (int j = 0; j < 4; j++)
        if ((lane ^ j) & 2) v[j] = t[j];
}

// ---------------------------------------------------------------------------
// Generic double-buffered fp16 NT GEMM, CTA tile 128 x 64 (qkv / pv / proj)
// ---------------------------------------------------------------------------
#define KC 32
#define SRS 40  // smem row stride in halves (80 B)
#define NT 64

template <int ASRC, int COUT, int BT>
__device__ void gemm_f16(const void* __restrict__ Asrc, size_t apstride, int lda,
                         const __half* __restrict__ Bh_g,
                         const __half* __restrict__ Bl_g, int ldb,
                         void* __restrict__ Cv, int ldc,
                         int K, float alpha, int m0, int n0)
{
    constexpr int WN = 2, MT = 32, MF = 2;
    constexpr int PB = NT / 32;
    constexpr int AEL = 128 * SRS;
    constexpr int BEL = NT * SRS;
    constexpr int BUFEL = AEL + BT * BEL;

    extern __shared__ __half sm[];

    const int tid = threadIdx.x;
    const int wid = tid >> 5, lane = tid & 31;
    const int wm = wid / WN, wn = wid % WN;
    const uint32_t ubase = smem_u32(sm);

    const uint32_t aOff = (uint32_t)(wm * MT + (lane & 15)) * (SRS * 2)
                        + (uint32_t)(lane >> 4) * 16;
    const uint32_t bOff = (uint32_t)(wn * 32 + ((lane >> 4) << 3) + (lane & 7)) * (SRS * 2)
                        + (uint32_t)((lane >> 3) & 1) * 16;

    float acc[MF][4][4];
#pragma unroll
    for (int i = 0; i < MF; i++)
#pragma unroll
        for (int j = 0; j < 4; j++)
#pragma unroll
            for (int t = 0; t < 4; t++) acc[i][j][t] = 0.f;

    const float* Af = (const float*)Asrc;
    const __half* Ah16 = (const __half*)Asrc;

    uint2 pa[4], pbh[PB], pbl[PB];

#define LOAD_AB(k0_)                                                            \
    {                                                                           \
        _Pragma("unroll")                                                       \
        for (int u = 0; u < 4; u++) {                                           \
            int i_ = tid + u * 256;                                             \
            int r_ = i_ >> 3, c4_ = (i_ & 7) << 2;                              \
            size_t idx_ = (size_t)(m0 + r_) * lda + (k0_) + c4_;                \
            if (ASRC == 1) {                                                    \
                pa[u] = *(const uint2*)(Ah16 + idx_);                           \
            } else {                                                            \
                float4 v_ = *(const float4*)(Af + idx_);                        \
                if (ASRC == 2) {                                                \
                    float4 v1_ = *(const float4*)(Af + idx_ + apstride);        \
                    float4 v2_ = *(const float4*)(Af + idx_ + 2 * apstride);    \
                    float4 v3_ = *(const float4*)(Af + idx_ + 3 * apstride);    \
                    v_.x += v1_.x + v2_.x + v3_.x;                              \
                    v_.y += v1_.y + v2_.y + v3_.y;                              \
                    v_.z += v1_.z + v2_.z + v3_.z;                              \
                    v_.w += v1_.w + v2_.w + v3_.w;                              \
                }                                                               \
                pa[u] = f4_to_h4(v_);                                           \
            }                                                                   \
        }                                                                       \
        _Pragma("unroll")                                                       \
        for (int u = 0; u < PB; u++) {                                          \
            int i_ = tid + u * 256;                                             \
            int r_ = i_ >> 3, c4_ = (i_ & 7) << 2;                              \
            size_t idx_ = (size_t)(n0 + r_) * ldb + (k0_) + c4_;                \
            pbh[u] = *(const uint2*)(Bh_g + idx_);                              \
            if (BT == 2) pbl[u] = *(const uint2*)(Bl_g + idx_);                 \
        }                                                                       \
    }

#define STORE_BUF(bi_)                                                          \
    {                                                                           \
        __half* Af_ = sm + (bi_) * BUFEL;                                       \
        __half* Bh_ = Af_ + AEL;                                                \
        __half* Bl_ = Bh_ + BEL;                                                \
        _Pragma("unroll")                                                       \
        for (int u = 0; u < 4; u++) {                                           \
            int i_ = tid + u * 256;                                             \
            int r_ = i_ >> 3, c4_ = (i_ & 7) << 2;                              \
            *(uint2*)(Af_ + r_ * SRS + c4_) = pa[u];                            \
        }                                                                       \
        _Pragma("unroll")                                                       \
        for (int u = 0; u < PB; u++) {                                          \
            int i_ = tid + u * 256;                                             \
            int r_ = i_ >> 3, c4_ = (i_ & 7) << 2;                              \
            *(uint2*)(Bh_ + r_ * SRS + c4_) = pbh[u];                           \
            if (BT == 2) *(uint2*)(Bl_ + r_ * SRS + c4_) = pbl[u];              \
        }                                                                       \
    }

    LOAD_AB(0);
    STORE_BUF(0);
    __syncthreads();

    const int nch = K / KC;
    for (int ch = 0; ch < nch; ch++) {
        if (ch + 1 < nch) LOAD_AB((ch + 1) * KC);

        const uint32_t bb = (uint32_t)((ch & 1) * BUFEL * 2);
        const uint32_t uAf = ubase + bb;
        const uint32_t uBh = uAf + AEL * 2;
        const uint32_t uBl = uBh + BEL * 2;

#pragma unroll
        for (int ks = 0; ks < 2; ks++) {
            const uint32_t kb = (uint32_t)(ks * 32);
            uint32_t ah[MF][4], bh[4][2], bl[4][2];
#pragma unroll
            for (int mf = 0; mf < MF; mf++) {
                uint32_t off = aOff + (uint32_t)(mf * 16) * (SRS * 2) + kb;
                LDSM4(ah[mf], uAf + off);
            }
#pragma unroll
            for (int g = 0; g < 2; g++) {
                uint32_t off = bOff + (uint32_t)(g * 16) * (SRS * 2) + kb;
                uint32_t th[4], tl[4];
                LDSM4(th, uBh + off);
                bh[2 * g][0] = th[0]; bh[2 * g][1] = th[1];
                bh[2 * g + 1][0] = th[2]; bh[2 * g + 1][1] = th[3];
                if (BT == 2) {
                    LDSM4(tl, uBl + off);
                    bl[2 * g][0] = tl[0]; bl[2 * g][1] = tl[1];
                    bl[2 * g + 1][0] = tl[2]; bl[2 * g + 1][1] = tl[3];
                }
            }
#pragma unroll
            for (int mf = 0; mf < MF; mf++)
#pragma unroll
                for (int nf = 0; nf < 4; nf++) {
                    MMA16816H(acc[mf][nf], ah[mf], bh[nf]);
                    if (BT == 2) MMA16816H(acc[mf][nf], ah[mf], bl[nf]);
                }
        }

        if (ch + 1 < nch) {
            STORE_BUF((ch + 1) & 1);
            __syncthreads();
        }
    }

    const int rbase = m0 + wm * MT + (lane >> 2);
    const int cbase = n0 + wn * 32 + ((lane & 3) << 1);
#pragma unroll
    for (int mf = 0; mf < MF; mf++)
#pragma unroll
        for (int nf = 0; nf < 4; nf++) {
            int r0 = rbase + mf * 16;
            int c = cbase + nf * 8;
            float v0x = acc[mf][nf][0] * alpha, v0y = acc[mf][nf][1] * alpha;
            float v1x = acc[mf][nf][2] * alpha, v1y = acc[mf][nf][3] * alpha;
            if (COUT == 1) {
                __half* Ch = (__half*)Cv;
                __half2 p0, p1;
                p0.x = __float2half_rn(v0x); p0.y = __float2half_rn(v0y);
                p1.x = __float2half_rn(v1x); p1.y = __float2half_rn(v1y);
                *(__half2*)(Ch + (size_t)r0 * ldc + c) = p0;
                *(__half2*)(Ch + (size_t)(r0 + 8) * ldc + c) = p1;
            } else {
                float* C = (float*)Cv;
                float2 w0 = {v0x, v0y};
                float2 w1 = {v1x, v1y};
                *(float2*)(C + (size_t)r0 * ldc + c) = w0;
                *(float2*)(C + (size_t)(r0 + 8) * ldc + c) = w1;
            }
        }
#undef LOAD_AB
#undef STORE_BUF
}

#define SMEM_BT2 (2 * (128 * SRS + 2 * 64 * SRS) * 2)   // 40960 B
#define SMEM_BT1 (2 * (128 * SRS + 1 * 64 * SRS) * 2)   // 30720 B

// ---------------------------------------------------------------------------
// Persistent-Q flash-style scores kernel, j-range split 4 ways.
// grid (4, 16, 16): x = j-quarter (8 j-tiles), y = m-tile, z = (b,h).
// C stores via quad-transpose -> STG.128.
// ---------------------------------------------------------------------------
#define SRS2 72  // row stride (halves) for 64-wide tiles

#define SMEM_SC ((128 * SRS2 + 2 * 64 * SRS2) * 2)  // 36864 B

__global__ __launch_bounds__(256, 2) void k_scores_flash()
{
    extern __shared__ __half sm[];
    __half* sQ = sm;                       // 128 x SRS2
    __half* sB0 = sQ + 128 * SRS2;         // 64 x SRS2, double buffered
    constexpr int BEL2 = 64 * SRS2;

    const int tid = threadIdx.x;
    const int wid = tid >> 5, lane = tid & 31;
    const int wm = wid >> 1, wn = wid & 1;
    const int qid = lane & 3;

    const int z = blockIdx.z, m0 = blockIdx.y * 128;
    const int jt0 = blockIdx.x * 8;
    const size_t off = (size_t)(z >> 3) * PLEN * DM + (z & 7) * DH;
    const __half* Q = g_qf + off;
    const __half* Kp = g_kf + off;
    __half* C = g_S + (size_t)z * PLEN * PLEN;

    const uint32_t uQ = smem_u32(sQ);
    const uint32_t uB = smem_u32(sB0);

    // ---- load Q tile 128 x 64 into smem ----
#pragma unroll
    for (int u = 0; u < 8; u++) {
        int i = tid + u * 256;
        int r = i >> 4, c4 = (i & 15) << 2;
        *(uint2*)(sQ + r * SRS2 + c4) =
            *(const uint2*)(Q + (size_t)(m0 + r) * DM + c4);
    }
    __syncthreads();

    // ---- ldmatrix Q into persistent registers ----
    const uint32_t aOff = (uint32_t)(wm * 32 + (lane & 15)) * (SRS2 * 2)
                        + (uint32_t)(lane >> 4) * 16;
    uint32_t ah[2][4][4];
#pragma unroll
    for (int mf = 0; mf < 2; mf++)
#pragma unroll
        for (int kf = 0; kf < 4; kf++) {
            uint32_t o = aOff + (uint32_t)(mf * 16) * (SRS2 * 2) + (uint32_t)(kf * 32);
            LDSM4(ah[mf][kf], uQ + o);
        }
    __syncthreads();

    const uint32_t bOff = (uint32_t)(wn * 32 + ((lane >> 4) << 3) + (lane & 7)) * (SRS2 * 2)
                        + (uint32_t)((lane >> 3) & 1) * 16;

    // ---- prologue: load first j-tile ----
    uint2 pb[4];
    {
        const __half* K0 = Kp + (size_t)jt0 * 64 * DM;
#pragma unroll
        for (int u = 0; u < 4; u++) {
            int i = tid + u * 256;
            int r = i >> 4, c4 = (i & 15) << 2;
            pb[u] = *(const uint2*)(K0 + (size_t)r * DM + c4);
        }
#pragma unroll
        for (int u = 0; u < 4; u++) {
            int i = tid + u * 256;
            int r = i >> 4, c4 = (i & 15) << 2;
            *(uint2*)(sB0 + r * SRS2 + c4) = pb[u];
        }
    }
    __syncthreads();

    const int rbase = m0 + wm * 32 + (lane >> 2);
    const int colbase = wn * 32 + qid * 8;

    for (int j = 0; j < 8; j++) {
        const int jt = jt0 + j;
        if (j + 1 < 8) {
            const __half* Kn = Kp + (size_t)(jt + 1) * 64 * DM;
#pragma unroll
            for (int u = 0; u < 4; u++) {
                int i = tid + u * 256;
                int r = i >> 4, c4 = (i & 15) << 2;
                pb[u] = *(const uint2*)(Kn + (size_t)r * DM + c4);
            }
        }

        const uint32_t uBc = uB + (uint32_t)((j & 1) * BEL2 * 2);

        float acc[2][4][4];
#pragma unroll
        for (int i = 0; i < 2; i++)
#pragma unroll
            for (int jj = 0; jj < 4; jj++)
#pragma unroll
                for (int t = 0; t < 4; t++) acc[i][jj][t] = 0.f;

#pragma unroll
        for (int kf = 0; kf < 4; kf++) {
            uint32_t bh[4][2];
#pragma unroll
            for (int g = 0; g < 2; g++) {
                uint32_t o = bOff + (uint32_t)(g * 16) * (SRS2 * 2) + (uint32_t)(kf * 32);
                uint32_t th[4];
                LDSM4(th, uBc + o);
                bh[2 * g][0] = th[0]; bh[2 * g][1] = th[1];
                bh[2 * g + 1][0] = th[2]; bh[2 * g + 1][1] = th[3];
            }
#pragma unroll
            for (int mf = 0; mf < 2; mf++)
#pragma unroll
                for (int nf = 0; nf < 4; nf++)
                    MMA16816H(acc[mf][nf], ah[mf][kf], bh[nf]);
        }

        // ---- store C tile via quad transpose -> STG.128 ----
        __half* Cj = C + jt * 64;
#pragma unroll
        for (int mf = 0; mf < 2; mf++)
#pragma unroll
            for (int half = 0; half < 2; half++) {
                uint32_t h[4];
#pragma unroll
                for (int nf = 0; nf < 4; nf++) {
                    __half2 p;
                    p.x = __float2half_rn(acc[mf][nf][half * 2 + 0]);
                    p.y = __float2half_rn(acc[mf][nf][half * 2 + 1]);
                    h[nf] = *(uint32_t*)&p;
                }
                quad_transpose(h, lane);
                int r = rbase + mf * 16 + half * 8;
                uint4 o;
                o.x = h[0]; o.y = h[1]; o.z = h[2]; o.w = h[3];
                *(uint4*)(Cj + (size_t)r * PLEN + colbase) = o;
            }

        if (j + 1 < 8) {
            __syncthreads();
            __half* sBn = sB0 + ((j + 1) & 1) * BEL2;
#pragma unroll
            for (int u = 0; u < 4; u++) {
                int i = tid + u * 256;
                int r = i >> 4, c4 = (i & 15) << 2;
                *(uint2*)(sBn + r * SRS2 + c4) = pb[u];
            }
            __syncthreads();
        }
    }
}

// ---------------------------------------------------------------------------
// Merged weight transpose + fp16 split: 4 x (512x512)
// ---------------------------------------------------------------------------
__global__ __launch_bounds__(256) void k_wtrans4(
    const float* __restrict__ Wq, const float* __restrict__ Wk,
    const float* __restrict__ Wv, const float* __restrict__ Wp,
    __half* qh, __half* ql, __half* kh, __half* kl,
    __half* vh, __half* vl, __half* ph, __half* pl)
{
    __shared__ float t[32][33];
    int z = blockIdx.z;
    const float* s = (z == 0) ? Wq : (z == 1) ? Wk : (z == 2) ? Wv : Wp;
    __half* dh = (z == 0) ? qh : (z == 1) ? kh : (z == 2) ? vh : ph;
    __half* dl = (z == 0) ? ql : (z == 1) ? kl : (z == 2) ? vl : pl;
    int c0 = blockIdx.x * 32, r0 = blockIdx.y * 32;
    for (int dy = threadIdx.y; dy < 32; dy += 8)
        t[dy][threadIdx.x] = s[(size_t)(r0 + dy) * DM + c0 + threadIdx.x];
    __syncthreads();
    for (int dy = threadIdx.y; dy < 32; dy += 8) {
        float v = t[threadIdx.x][dy];
        __half h = __float2half_rn(v);
        size_t o = (size_t)(c0 + dy) * DM + r0 + threadIdx.x;
        dh[o] = h;
        dl[o] = __float2half_rn(v - __half2float(h));
    }
}

// V transpose (single fp16): [b, p, d] -> [b, d, p]
__global__ __launch_bounds__(256) void k_transpose_h(
    const float* __restrict__ src, __half* __restrict__ dst, int R, int C)
{
    __shared__ float t[32][33];
    const float* s = src + (size_t)blockIdx.z * R * C;
    __half* d = dst + (size_t)blockIdx.z * R * C;
    int c0 = blockIdx.x * 32, r0 = blockIdx.y * 32;
    for (int dy = threadIdx.y; dy < 32; dy += 8)
        t[dy][threadIdx.x] = s[(size_t)(r0 + dy) * C + c0 + threadIdx.x];
    __syncthreads();
    for (int dy = threadIdx.y; dy < 32; dy += 8)
        d[(size_t)(c0 + dy) * R + r0 + threadIdx.x] =
            __float2half_rn(t[threadIdx.x][dy]);
}

// ---------------------------------------------------------------------------
// Stage kernels
// ---------------------------------------------------------------------------
__global__ __launch_bounds__(256, 2) void k_qkv_mma(const float* __restrict__ x)
{
    int which = blockIdx.z;
    int m0 = blockIdx.y * 128, n0 = blockIdx.x * NT;
    if (which == 0) {
        gemm_f16<0, 1, 2>(x, 0, DM, g_wqth, g_wqtl, DM,
                          g_qf, DM, DM, 0.125f, m0, n0);
    } else if (which == 1) {
        gemm_f16<0, 1, 2>(x, 0, DM, g_wkth, g_wktl, DM,
                          g_kf, DM, DM, 1.0f, m0, n0);
    } else {
        gemm_f16<0, 0, 2>(x, 0, DM, g_wvth, g_wvtl, DM,
                          g_v, DM, DM, 1.0f, m0, n0);
    }
}

__global__ __launch_bounds__(256, 2) void k_pv_mma()
{
    int kidx = blockIdx.x;
    int z = blockIdx.z, b = z >> 3, g = z & 7;
    const __half* A = g_Sh + (size_t)z * PLEN * PLEN + kidx * (PLEN / KSPLIT);
    size_t boff = (size_t)b * DM * PLEN + (size_t)g * DH * PLEN
                + kidx * (PLEN / KSPLIT);
    float* C = g_ohp + (size_t)kidx * PSTRIDE + (size_t)b * PLEN * DM + g * DH;
    gemm_f16<1, 0, 1>(A, 0, PLEN, g_vt + boff, nullptr, PLEN,
                      C, DM, PLEN / KSPLIT, 1.0f,
                      blockIdx.y * 128, 0);
}

__global__ __launch_bounds__(256, 2) void k_proj_mma(float* __restrict__ out)
{
    gemm_f16<2, 0, 2>(g_ohp, PSTRIDE, DM, g_wpth, g_wptl, DM,
                      out, DM, DM, 1.0f,
                      blockIdx.y * 128, blockIdx.x * NT);
}

// ---------------------------------------------------------------------------
// Stage 3: head-mix (W1) -> softmax -> head-mix (W2, /l folded).
// Register-resident. Reads fp16 g_S, writes fp16 g_Sh. 512 thr.
// ---------------------------------------------------------------------------
__device__ __forceinline__ float4 ld4h(const __half* p) {
    uint2 u = *(const uint2*)p;
    __half2 a = *(__half2*)&u.x;
    __half2 b = *(__half2*)&u.y;
    float4 r;
    r.x = __half2float(a.x); r.y = __half2float(a.y);
    r.z = __half2float(b.x); r.w = __half2float(b.y);
    return r;
}
__device__ __forceinline__ void st4h(__half* p, float4 v) {
    __half2 a, b;
    a.x = __float2half_rn(v.x); a.y = __float2half_rn(v.y);
    b.x = __float2half_rn(v.z); b.y = __float2half_rn(v.w);
    uint2 u;
    u.x = *(uint32_t*)&a; u.y = *(uint32_t*)&b;
    *(uint2*)p = u;
}

__global__ __launch_bounds__(512) void k_mix_softmax(
    const float* __restrict__ W1, const float* __restrict__ W2)
{
    __shared__ float w1s[64], w2l[64];
    __shared__ float red[16][8];
    __shared__ float finm[8], finl[8];

    const int tid = threadIdx.x;
    const int wid = tid >> 5, lane = tid & 31;
    const int i = blockIdx.x, b = blockIdx.y;

    if (tid < 64) w1s[tid] = W1[tid];
    __syncthreads();

    const __half* Srow = g_S + (size_t)b * NH * PLEN * PLEN + (size_t)i * PLEN;
    __half* Orow = g_Sh + (size_t)b * NH * PLEN * PLEN + (size_t)i * PLEN;
    const int j4 = tid << 2;

    float4 v[8];
    {
        float4 r[8];
#pragma unroll
        for (int h = 0; h < 8; h++)
            r[h] = ld4h(Srow + (size_t)h * PLEN * PLEN + j4);
#pragma unroll
        for (int g = 0; g < 8; g++) {
            float4 a = {0.f, 0.f, 0.f, 0.f};
#pragma unroll
            for (int h = 0; h < 8; h++) {
                float w = w1s[h * 8 + g];
                a.x += w * r[h].x; a.y += w * r[h].y;
                a.z += w * r[h].z; a.w += w * r[h].w;
            }
            v[g] = a;
        }
    }

#pragma unroll
    for (int g = 0; g < 8; g++) {
        float m = fmaxf(fmaxf(v[g].x, v[g].y), fmaxf(v[g].z, v[g].w));
#pragma unroll
        for (int o = 16; o; o >>= 1) m = fmaxf(m, __shfl_xor_sync(0xffffffffu, m, o));
        if (lane == 0) red[wid][g] = m;
    }
    __syncthreads();
    if (tid < 8) {
        float m = -1e30f;
#pragma unroll
        for (int w = 0; w < 16; w++) m = fmaxf(m, red[w][tid]);
        finm[tid] = m;
    }
    __syncthreads();

#pragma unroll
    for (int g = 0; g < 8; g++) {
        float m = finm[g];
        v[g].x = __expf(v[g].x - m);
        v[g].y = __expf(v[g].y - m);
        v[g].z = __expf(v[g].z - m);
        v[g].w = __expf(v[g].w - m);
        float s = (v[g].x + v[g].y) + (v[g].z + v[g].w);
#pragma unroll
        for (int o = 16; o; o >>= 1) s += __shfl_xor_sync(0xffffffffu, s, o);
        if (lane == 0) red[wid][g] = s;
    }
    __syncthreads();
    if (tid < 8) {
        float s = 0.f;
#pragma unroll
        for (int w = 0; w < 16; w++) s += red[w][tid];
        finl[tid] = s;
    }
    __syncthreads();

    if (tid < 64) w2l[tid] = W2[tid] / finl[tid >> 3];
    __syncthreads();

#pragma unroll
    for (int gp = 0; gp < 8; gp++) {
        float4 a = {0.f, 0.f, 0.f, 0.f};
#pragma unroll
        for (int h = 0; h < 8; h++) {
            float w = w2l[h * 8 + gp];
            a.x += w * v[h].x; a.y += w * v[h].y;
            a.z += w * v[h].z; a.w += w * v[h].w;
        }
        st4h(Orow + (size_t)gp * PLEN * PLEN + j4, a);
    }
}

// ---------------------------------------------------------------------------
extern "C" void kernel_launch(void* const* d_in, const int* in_sizes, int n_in,
                              void* d_out, int out_size)
{
    const float* x     = (const float*)d_in[0];
    const float* Wq    = (const float*)d_in[1];
    const float* Wk    = (const float*)d_in[2];
    const float* Wv    = (const float*)d_in[3];
    const float* W1    = (const float*)d_in[4];
    const float* W2    = (const float*)d_in[5];
    const float* Wproj = (const float*)d_in[6];
    float* out = (float*)d_out;

    cudaFuncSetAttribute(k_qkv_mma,      cudaFuncAttributeMaxDynamicSharedMemorySize, SMEM_BT2);
    cudaFuncSetAttribute(k_scores_flash, cudaFuncAttributeMaxDynamicSharedMemorySize, SMEM_SC);
    cudaFuncSetAttribute(k_pv_mma,       cudaFuncAttributeMaxDynamicSharedMemorySize, SMEM_BT1);
    cudaFuncSetAttribute(k_proj_mma,     cudaFuncAttributeMaxDynamicSharedMemorySize, SMEM_BT2);

    __half *wqth, *wqtl, *wkth, *wktl, *wvth, *wvtl, *wpth, *wptl;
    cudaGetSymbolAddress((void**)&wqth, g_wqth); cudaGetSymbolAddress((void**)&wqtl, g_wqtl);
    cudaGetSymbolAddress((void**)&wkth, g_wkth); cudaGetSymbolAddress((void**)&wktl, g_wktl);
    cudaGetSymbolAddress((void**)&wvth, g_wvth); cudaGetSymbolAddress((void**)&wvtl, g_wvtl);
    cudaGetSymbolAddress((void**)&wpth, g_wpth); cudaGetSymbolAddress((void**)&wptl, g_wptl);
    float* vp = nullptr;  cudaGetSymbolAddress((void**)&vp,  g_v);
    __half* vtp = nullptr; cudaGetSymbolAddress((void**)&vtp, g_vt);

    k_wtrans4<<<dim3(16, 16, 4), dim3(32, 8)>>>(Wq, Wk, Wv, Wproj,
                                                wqth, wqtl, wkth, wktl,
                                                wvth, wvtl, wpth, wptl);
    k_qkv_mma<<<dim3(8, 32, 3), 256, SMEM_BT2>>>(x);
    k_transpose_h<<<dim3(16, 64, 2), dim3(32, 8)>>>(vp, vtp, PLEN, DM);
    k_scores_flash<<<dim3(4, 16, 16), 256, SMEM_SC>>>();
    k_mix_softmax<<<dim3(2048, 2, 1), 512>>>(W1, W2);
    k_pv_mma<<<dim3(KSPLIT, 16, 16), 256, SMEM_BT1>>>();
    k_proj_mma<<<dim3(8, 32, 1), 256, SMEM_BT2>>>(out);
}